// round 3
// baseline (speedup 1.0000x reference)
#include <cuda_runtime.h>
#include <cuda_bf16.h>
#include <cstdint>

// Problem constants
#define B_WIN   4096
#define SEQ     49
#define CDIM    384
#define HEADS   12
#define HDIM    32
#define NW      1024
#define MROWS   (B_WIN * SEQ)        // 200704
#define QKV_N   (3 * CDIM)           // 1152
#define SCALE_F 0.17677669529663687f // 32^-0.5

// Scratch (static device globals: allowed; no allocations)
__device__ float g_qkv[(size_t)MROWS * QKV_N];  // (B_*N, 1152)
__device__ float g_att[(size_t)MROWS * CDIM];   // (B_*N, 384)

// ---------------------------------------------------------------------------
// TF32 helpers
// ---------------------------------------------------------------------------
__device__ __forceinline__ uint32_t f2tf32(float f) {
    uint32_t u;
    asm("cvt.rna.tf32.f32 %0, %1;" : "=r"(u) : "f"(f));
    return u;
}

__device__ __forceinline__ void mma_m16n8k8_tf32(float* c, const uint32_t* a, const uint32_t* b) {
    asm volatile(
        "mma.sync.aligned.m16n8k8.row.col.f32.tf32.tf32.f32 "
        "{%0,%1,%2,%3}, {%4,%5,%6,%7}, {%8,%9}, {%0,%1,%2,%3};\n"
        : "+f"(c[0]), "+f"(c[1]), "+f"(c[2]), "+f"(c[3])
        : "r"(a[0]), "r"(a[1]), "r"(a[2]), "r"(a[3]), "r"(b[0]), "r"(b[1]));
}

// ---------------------------------------------------------------------------
// GEMM: C[M,N] = A[M,K] @ W[K,N] + bias[N]   (A,W row-major, fp32 in, tf32 mma)
// MODE 0: A = param (x),  C = g_qkv
// MODE 1: A = g_att,      C = param (d_out)
// BM=128, BN=64, BK=32, 256 threads (8 warps: 4m x 2n, each warp 32x32)
// Requires M%128==0, N%64==0, K%32==0 (true here).
// ---------------------------------------------------------------------------
template <int MODE>
__global__ void __launch_bounds__(256)
gemm_tf32(const float* __restrict__ A_in, const float* __restrict__ W,
          const float* __restrict__ bias, float* __restrict__ C_out,
          int M, int N, int K) {
    const float* A = (MODE == 0) ? A_in : g_att;
    float*       C = (MODE == 0) ? g_qkv : C_out;

    __shared__ __align__(16) uint32_t As[128][36];
    __shared__ __align__(16) uint32_t Bs[32][72];

    const int tid  = threadIdx.x;
    const int warp = tid >> 5;
    const int lane = tid & 31;
    const int wm   = warp >> 1;   // 0..3
    const int wn   = warp & 1;    // 0..1
    const int block_row = blockIdx.y * 128;
    const int block_col = blockIdx.x * 64;

    float acc[8][4];
#pragma unroll
    for (int i = 0; i < 8; ++i)
#pragma unroll
        for (int j = 0; j < 4; ++j) acc[i][j] = 0.f;

    for (int k0 = 0; k0 < K; k0 += 32) {
        // Load A tile: 128x32 floats = 1024 float4 / 256 threads = 4 each
#pragma unroll
        for (int it = 0; it < 4; ++it) {
            int idx = tid + it * 256;           // 0..1023
            int r = idx >> 3;                   // row 0..127
            int c = (idx & 7) << 2;             // 0,4,...,28
            float4 v = *(const float4*)(A + (size_t)(block_row + r) * K + k0 + c);
            uint4 t;
            t.x = f2tf32(v.x); t.y = f2tf32(v.y); t.z = f2tf32(v.z); t.w = f2tf32(v.w);
            *(uint4*)&As[r][c] = t;
        }
        // Load B tile: 32x64 = 512 float4 / 256 threads = 2 each
#pragma unroll
        for (int it = 0; it < 2; ++it) {
            int idx = tid + it * 256;           // 0..511
            int r = idx >> 4;                   // row 0..31
            int c = (idx & 15) << 2;            // 0..60
            float4 v = *(const float4*)(W + (size_t)(k0 + r) * N + block_col + c);
            uint4 t;
            t.x = f2tf32(v.x); t.y = f2tf32(v.y); t.z = f2tf32(v.z); t.w = f2tf32(v.w);
            *(uint4*)&Bs[r][c] = t;
        }
        __syncthreads();

#pragma unroll
        for (int kk = 0; kk < 32; kk += 8) {
            uint32_t afrag[2][4];
#pragma unroll
            for (int mt = 0; mt < 2; ++mt) {
                int ar = wm * 32 + mt * 16 + (lane >> 2);
                int ac = kk + (lane & 3);
                afrag[mt][0] = As[ar][ac];
                afrag[mt][1] = As[ar + 8][ac];
                afrag[mt][2] = As[ar][ac + 4];
                afrag[mt][3] = As[ar + 8][ac + 4];
            }
            uint32_t bfrag[4][2];
#pragma unroll
            for (int nt = 0; nt < 4; ++nt) {
                int bc = wn * 32 + nt * 8 + (lane >> 2);
                int br = kk + (lane & 3);
                bfrag[nt][0] = Bs[br][bc];
                bfrag[nt][1] = Bs[br + 4][bc];
            }
#pragma unroll
            for (int mt = 0; mt < 2; ++mt)
#pragma unroll
                for (int nt = 0; nt < 4; ++nt)
                    mma_m16n8k8_tf32(acc[mt * 4 + nt], afrag[mt], bfrag[nt]);
        }
        __syncthreads();
    }

    // Epilogue: add bias, write out (float2 stores, rows r and r+8 per tile)
#pragma unroll
    for (int mt = 0; mt < 2; ++mt) {
#pragma unroll
        for (int nt = 0; nt < 4; ++nt) {
            int r = block_row + wm * 32 + mt * 16 + (lane >> 2);
            int c = block_col + wn * 32 + nt * 8 + ((lane & 3) << 1);
            float b0 = bias[c], b1 = bias[c + 1];
            const float* a4 = acc[mt * 4 + nt];
            float2 v0 = make_float2(a4[0] + b0, a4[1] + b1);
            float2 v1 = make_float2(a4[2] + b0, a4[3] + b1);
            *(float2*)(C + (size_t)r * N + c)       = v0;
            *(float2*)(C + (size_t)(r + 8) * N + c) = v1;
        }
    }
}

// ---------------------------------------------------------------------------
// Fused window attention per (window b, head h).
// Reads g_qkv, writes g_att. 256 threads.
// ---------------------------------------------------------------------------
__global__ void __launch_bounds__(256)
attn_kernel(const float* __restrict__ mask,
            const float* __restrict__ rpb,       // (169, 12)
            const int*   __restrict__ relidx) {  // (49, 49)
    const int h = blockIdx.x;   // 0..11
    const int b = blockIdx.y;   // 0..4095

    __shared__ __align__(16) float q[52][36];
    __shared__ __align__(16) float k[52][36];
    __shared__ __align__(16) float v[52][36];
    __shared__ float S[52][56];
    __shared__ float rpb_s[176];
    __shared__ int   rel_s[2401];

    const int tid = threadIdx.x;

    // Load q/k/v (zero-padded to 52 rows)
    const float* base = g_qkv + (size_t)b * SEQ * QKV_N + h * HDIM;
    for (int e = tid; e < 52 * 32; e += 256) {
        int n = e >> 5, d = e & 31;
        float qv = 0.f, kv = 0.f, vv = 0.f;
        if (n < SEQ) {
            const float* p = base + (size_t)n * QKV_N;
            qv = p[d] * SCALE_F;
            kv = p[CDIM + d];
            vv = p[2 * CDIM + d];
        }
        q[n][d] = qv; k[n][d] = kv; v[n][d] = vv;
    }
    for (int e = tid; e < 169; e += 256) rpb_s[e] = rpb[e * HEADS + h];
    for (int e = tid; e < 2401; e += 256) rel_s[e] = relidx[e];
    __syncthreads();

    // Phase A: S = q k^T (+bias +mask), 4x4 register tiles, 13x13 tile grid
    const float* mptr = mask + (size_t)(b & (NW - 1)) * (SEQ * SEQ);
    if (tid < 169) {
        int ty = tid / 13, tx = tid % 13;
        int i0 = ty * 4, j0 = tx * 4;
        float accs[4][4];
#pragma unroll
        for (int a = 0; a < 4; ++a)
#pragma unroll
            for (int c = 0; c < 4; ++c) accs[a][c] = 0.f;
#pragma unroll
        for (int d = 0; d < 32; d += 4) {
            float4 qa[4], kb[4];
#pragma unroll
            for (int a = 0; a < 4; ++a) qa[a] = *(const float4*)&q[i0 + a][d];
#pragma unroll
            for (int c = 0; c < 4; ++c) kb[c] = *(const float4*)&k[j0 + c][d];
#pragma unroll
            for (int a = 0; a < 4; ++a)
#pragma unroll
                for (int c = 0; c < 4; ++c)
                    accs[a][c] += qa[a].x * kb[c].x + qa[a].y * kb[c].y +
                                  qa[a].z * kb[c].z + qa[a].w * kb[c].w;
        }
#pragma unroll
        for (int a = 0; a < 4; ++a)
#pragma unroll
            for (int c = 0; c < 4; ++c) {
                int i = i0 + a, j = j0 + c;
                float s = accs[a][c];
                if (i < SEQ && j < SEQ)
                    s += rpb_s[rel_s[i * SEQ + j]] + mptr[i * SEQ + j];
                S[i][j] = s;
            }
    }
    __syncthreads();

    // Phase B: row softmax (8 warps, row-cyclic)
    const int warp = tid >> 5, lane = tid & 31;
    for (int i = warp; i < SEQ; i += 8) {
        float v0 = (lane < SEQ) ? S[i][lane] : -1e30f;
        float v1 = (lane + 32 < SEQ) ? S[i][lane + 32] : -1e30f;
        float m = fmaxf(v0, v1);
#pragma unroll
        for (int off = 16; off; off >>= 1)
            m = fmaxf(m, __shfl_xor_sync(0xffffffffu, m, off));
        float e0 = (lane < SEQ) ? __expf(v0 - m) : 0.f;
        float e1 = (lane + 32 < SEQ) ? __expf(v1 - m) : 0.f;
        float s = e0 + e1;
#pragma unroll
        for (int off = 16; off; off >>= 1)
            s += __shfl_xor_sync(0xffffffffu, s, off);
        float inv = 1.f / s;
        if (lane < SEQ)      S[i][lane]      = e0 * inv;
        if (lane + 32 < SEQ) S[i][lane + 32] = e1 * inv;
    }
    __syncthreads();

    // Phase C: out = P @ v, 4x4 register tiles (13 i-tiles x 8 d-tiles = 104 threads)
    if (tid < 104) {
        int ty = tid >> 3, tx = tid & 7;
        int i0 = ty * 4, d0 = tx * 4;
        float4 a0 = {0, 0, 0, 0}, a1 = {0, 0, 0, 0}, a2 = {0, 0, 0, 0}, a3 = {0, 0, 0, 0};
        for (int j = 0; j < SEQ; ++j) {
            float4 vv = *(const float4*)&v[j][d0];
            float p0 = S[i0 + 0][j], p1 = S[i0 + 1][j];
            float p2 = S[i0 + 2][j], p3 = S[i0 + 3][j];
            a0.x += p0 * vv.x; a0.y += p0 * vv.y; a0.z += p0 * vv.z; a0.w += p0 * vv.w;
            a1.x += p1 * vv.x; a1.y += p1 * vv.y; a1.z += p1 * vv.z; a1.w += p1 * vv.w;
            a2.x += p2 * vv.x; a2.y += p2 * vv.y; a2.z += p2 * vv.z; a2.w += p2 * vv.w;
            a3.x += p3 * vv.x; a3.y += p3 * vv.y; a3.z += p3 * vv.z; a3.w += p3 * vv.w;
        }
        float* op = g_att + ((size_t)b * SEQ + i0) * CDIM + h * HDIM + d0;
        if (i0 + 0 < SEQ) *(float4*)(op)            = a0;
        if (i0 + 1 < SEQ) *(float4*)(op + CDIM)     = a1;
        if (i0 + 2 < SEQ) *(float4*)(op + 2 * CDIM) = a2;
        if (i0 + 3 < SEQ) *(float4*)(op + 3 * CDIM) = a3;
    }
}

// ---------------------------------------------------------------------------
// Launch
// ---------------------------------------------------------------------------
extern "C" void kernel_launch(void* const* d_in, const int* in_sizes, int n_in,
                              void* d_out, int out_size) {
    const float* x      = (const float*)d_in[0];
    const float* mask   = (const float*)d_in[1];
    const float* qkv_w  = (const float*)d_in[2];
    const float* qkv_b  = (const float*)d_in[3];
    const float* proj_w = (const float*)d_in[4];
    const float* proj_b = (const float*)d_in[5];
    const float* rpb    = (const float*)d_in[6];
    const int*   rel    = (const int*)d_in[7];
    float*       out    = (float*)d_out;

    // 1) QKV GEMM: g_qkv = x @ qkv_w + qkv_b
    gemm_tf32<0><<<dim3(QKV_N / 64, MROWS / 128), 256>>>(x, qkv_w, qkv_b, nullptr,
                                                         MROWS, QKV_N, CDIM);
    // 2) Fused per-(window, head) attention: g_att
    attn_kernel<<<dim3(HEADS, B_WIN), 256>>>(mask, rpb, rel);
    // 3) Proj GEMM: out = g_att @ proj_w + proj_b
    gemm_tf32<1><<<dim3(CDIM / 64, MROWS / 128), 256>>>(nullptr, proj_w, proj_b, out,
                                                        MROWS, CDIM, CDIM);
}

// round 4
// speedup vs baseline: 1.2586x; 1.2586x over previous
#include <cuda_runtime.h>
#include <cuda_bf16.h>
#include <cstdint>

// Problem constants
#define B_WIN   4096
#define SEQ     49
#define CDIM    384
#define HEADS   12
#define HDIM    32
#define NW      1024
#define MROWS   (B_WIN * SEQ)        // 200704
#define QKV_N   (3 * CDIM)           // 1152
#define SCALE_F 0.17677669529663687f // 32^-0.5

// Scratch (static device globals: allowed; no allocations)
__device__ float g_qkv[(size_t)MROWS * QKV_N];   // (B_*N, 1152)
__device__ float g_att[(size_t)MROWS * CDIM];    // (B_*N, 384)
__device__ float g_bias[HEADS * SEQ * SEQ];      // combined rpb gather (12,49,49)

// ---------------------------------------------------------------------------
// Helpers
// ---------------------------------------------------------------------------
__device__ __forceinline__ uint32_t f2tf32(float f) {
    uint32_t u;
    asm("cvt.rna.tf32.f32 %0, %1;" : "=r"(u) : "f"(f));
    return u;
}

__device__ __forceinline__ void mma_m16n8k8_tf32(float* c, const uint32_t* a, const uint32_t* b) {
    asm volatile(
        "mma.sync.aligned.m16n8k8.row.col.f32.tf32.tf32.f32 "
        "{%0,%1,%2,%3}, {%4,%5,%6,%7}, {%8,%9}, {%0,%1,%2,%3};\n"
        : "+f"(c[0]), "+f"(c[1]), "+f"(c[2]), "+f"(c[3])
        : "r"(a[0]), "r"(a[1]), "r"(a[2]), "r"(a[3]), "r"(b[0]), "r"(b[1]));
}

__device__ __forceinline__ void cp_async16(void* smem_dst, const void* gmem_src) {
    uint32_t s = (uint32_t)__cvta_generic_to_shared(smem_dst);
    asm volatile("cp.async.cg.shared.global [%0], [%1], 16;\n" :: "r"(s), "l"(gmem_src));
}
__device__ __forceinline__ void cp_async_commit() {
    asm volatile("cp.async.commit_group;\n" ::: "memory");
}
template <int N>
__device__ __forceinline__ void cp_async_wait() {
    asm volatile("cp.async.wait_group %0;\n" :: "n"(N) : "memory");
}

// ---------------------------------------------------------------------------
// GEMM: C[M,N] = A[M,K] @ W[K,N] + bias[N]   (fp32 in, tf32 mma, fp32 out)
// MODE 0: A = param (x),  C = g_qkv, q-columns (c<384) scaled by SCALE_F
// MODE 1: A = g_att,      C = param (d_out)
// BM=128, BN=64, BK=32, 256 threads, double-buffered cp.async pipeline.
// ---------------------------------------------------------------------------
template <int MODE>
__global__ void __launch_bounds__(256)
gemm_tf32(const float* __restrict__ A_in, const float* __restrict__ W,
          const float* __restrict__ bias, float* __restrict__ C_out,
          int M, int N, int K) {
    const float* A = (MODE == 0) ? A_in : g_att;
    float*       C = (MODE == 0) ? g_qkv : C_out;

    __shared__ __align__(16) float As[2][128][36];
    __shared__ __align__(16) float Bs[2][32][72];

    const int tid  = threadIdx.x;
    const int warp = tid >> 5;
    const int lane = tid & 31;
    const int wm   = warp >> 1;   // 0..3
    const int wn   = warp & 1;    // 0..1
    const int block_row = blockIdx.y * 128;
    const int block_col = blockIdx.x * 64;

    // Per-thread load coordinates (A: 4 chunks, B: 2 chunks of 16B)
    const int ar_ld = tid >> 3;             // 0..31 (then +32*it)
    const int ac_ld = (tid & 7) << 2;       // 0,4,...,28
    const int br_ld = tid >> 4;             // 0..15 (then +16*it)
    const int bc_ld = (tid & 15) << 2;      // 0..60

    const int NK = K >> 5;

    auto load_tile = [&](int stage, int k0) {
#pragma unroll
        for (int it = 0; it < 4; ++it) {
            int r = ar_ld + it * 32;
            cp_async16(&As[stage][r][ac_ld],
                       A + (size_t)(block_row + r) * K + k0 + ac_ld);
        }
#pragma unroll
        for (int it = 0; it < 2; ++it) {
            int r = br_ld + it * 16;
            cp_async16(&Bs[stage][r][bc_ld],
                       W + (size_t)(k0 + r) * N + block_col + bc_ld);
        }
        cp_async_commit();
    };

    float acc[8][4];
#pragma unroll
    for (int i = 0; i < 8; ++i)
#pragma unroll
        for (int j = 0; j < 4; ++j) acc[i][j] = 0.f;

    load_tile(0, 0);

    for (int i = 0; i < NK; ++i) {
        if (i + 1 < NK) {
            load_tile((i + 1) & 1, (i + 1) << 5);
            cp_async_wait<1>();
        } else {
            cp_async_wait<0>();
        }
        __syncthreads();

        const int st = i & 1;
#pragma unroll
        for (int kk = 0; kk < 32; kk += 8) {
            uint32_t afrag[2][4];
#pragma unroll
            for (int mt = 0; mt < 2; ++mt) {
                int arr = wm * 32 + mt * 16 + (lane >> 2);
                int acc_ = kk + (lane & 3);
                afrag[mt][0] = f2tf32(As[st][arr][acc_]);
                afrag[mt][1] = f2tf32(As[st][arr + 8][acc_]);
                afrag[mt][2] = f2tf32(As[st][arr][acc_ + 4]);
                afrag[mt][3] = f2tf32(As[st][arr + 8][acc_ + 4]);
            }
            uint32_t bfrag[4][2];
#pragma unroll
            for (int nt = 0; nt < 4; ++nt) {
                int bcc = wn * 32 + nt * 8 + (lane >> 2);
                int brr = kk + (lane & 3);
                bfrag[nt][0] = f2tf32(Bs[st][brr][bcc]);
                bfrag[nt][1] = f2tf32(Bs[st][brr + 4][bcc]);
            }
#pragma unroll
            for (int mt = 0; mt < 2; ++mt)
#pragma unroll
                for (int nt = 0; nt < 4; ++nt)
                    mma_m16n8k8_tf32(acc[mt * 4 + nt], afrag[mt], bfrag[nt]);
        }
        __syncthreads();
    }

    // Epilogue: add bias; for QKV, scale q-columns by SCALE_F
    const float qscale = (MODE == 0 && block_col < CDIM) ? SCALE_F : 1.f;
#pragma unroll
    for (int mt = 0; mt < 2; ++mt) {
#pragma unroll
        for (int nt = 0; nt < 4; ++nt) {
            int r = block_row + wm * 32 + mt * 16 + (lane >> 2);
            int c = block_col + wn * 32 + nt * 8 + ((lane & 3) << 1);
            float b0 = bias[c], b1 = bias[c + 1];
            const float* a4 = acc[mt * 4 + nt];
            float2 v0 = make_float2((a4[0] + b0) * qscale, (a4[1] + b1) * qscale);
            float2 v1 = make_float2((a4[2] + b0) * qscale, (a4[3] + b1) * qscale);
            *(float2*)(C + (size_t)r * N + c)       = v0;
            *(float2*)(C + (size_t)(r + 8) * N + c) = v1;
        }
    }
}

// ---------------------------------------------------------------------------
// Precompute combined relative-position bias: g_bias[h][i*49+j]
// ---------------------------------------------------------------------------
__global__ void bias_kernel(const float* __restrict__ rpb, const int* __restrict__ rel) {
    int t = blockIdx.x * 256 + threadIdx.x;
    if (t < HEADS * SEQ * SEQ) {
        int h = t / (SEQ * SEQ);
        int ij = t - h * (SEQ * SEQ);
        g_bias[t] = rpb[rel[ij] * HEADS + h];
    }
}

// ---------------------------------------------------------------------------
// Fused window attention per (window b, head h). Reads g_qkv, writes g_att.
// ---------------------------------------------------------------------------
__global__ void __launch_bounds__(256)
attn_kernel(const float* __restrict__ mask) {
    const int h = blockIdx.x;   // 0..11
    const int b = blockIdx.y;   // 0..4095

    __shared__ __align__(16) float q[52][36];
    __shared__ __align__(16) float k[52][36];
    __shared__ __align__(16) float v[52][36];
    __shared__ float S[52][56];

    const int tid = threadIdx.x;

    // Load q/k/v (zero-padded to 52 rows); q is pre-scaled by the QKV GEMM
    const float* base = g_qkv + (size_t)b * SEQ * QKV_N + h * HDIM;
    for (int e = tid; e < 52 * 32; e += 256) {
        int n = e >> 5, d = e & 31;
        float qv = 0.f, kv = 0.f, vv = 0.f;
        if (n < SEQ) {
            const float* p = base + (size_t)n * QKV_N;
            qv = p[d];
            kv = p[CDIM + d];
            vv = p[2 * CDIM + d];
        }
        q[n][d] = qv; k[n][d] = kv; v[n][d] = vv;
    }
    __syncthreads();

    // Phase A: S = q k^T (+bias +mask), 4x4 register tiles, 13x13 tile grid
    const float* mptr = mask + (size_t)(b & (NW - 1)) * (SEQ * SEQ);
    const float* bptr = g_bias + (size_t)h * (SEQ * SEQ);
    if (tid < 169) {
        int ty = tid / 13, tx = tid % 13;
        int i0 = ty * 4, j0 = tx * 4;
        float accs[4][4];
#pragma unroll
        for (int a = 0; a < 4; ++a)
#pragma unroll
            for (int c = 0; c < 4; ++c) accs[a][c] = 0.f;
#pragma unroll
        for (int d = 0; d < 32; d += 4) {
            float4 qa[4], kb[4];
#pragma unroll
            for (int a = 0; a < 4; ++a) qa[a] = *(const float4*)&q[i0 + a][d];
#pragma unroll
            for (int c = 0; c < 4; ++c) kb[c] = *(const float4*)&k[j0 + c][d];
#pragma unroll
            for (int a = 0; a < 4; ++a)
#pragma unroll
                for (int c = 0; c < 4; ++c)
                    accs[a][c] += qa[a].x * kb[c].x + qa[a].y * kb[c].y +
                                  qa[a].z * kb[c].z + qa[a].w * kb[c].w;
        }
#pragma unroll
        for (int a = 0; a < 4; ++a)
#pragma unroll
            for (int c = 0; c < 4; ++c) {
                int i = i0 + a, j = j0 + c;
                float s = accs[a][c];
                if (i < SEQ && j < SEQ)
                    s += bptr[i * SEQ + j] + mptr[i * SEQ + j];
                S[i][j] = s;
            }
    }
    __syncthreads();

    // Phase B: row softmax (8 warps, row-cyclic)
    const int warp = tid >> 5, lane = tid & 31;
    for (int i = warp; i < SEQ; i += 8) {
        float v0 = (lane < SEQ) ? S[i][lane] : -1e30f;
        float v1 = (lane + 32 < SEQ) ? S[i][lane + 32] : -1e30f;
        float m = fmaxf(v0, v1);
#pragma unroll
        for (int off = 16; off; off >>= 1)
            m = fmaxf(m, __shfl_xor_sync(0xffffffffu, m, off));
        float e0 = (lane < SEQ) ? __expf(v0 - m) : 0.f;
        float e1 = (lane + 32 < SEQ) ? __expf(v1 - m) : 0.f;
        float s = e0 + e1;
#pragma unroll
        for (int off = 16; off; off >>= 1)
            s += __shfl_xor_sync(0xffffffffu, s, off);
        float inv = 1.f / s;
        if (lane < SEQ)      S[i][lane]      = e0 * inv;
        if (lane + 32 < SEQ) S[i][lane + 32] = e1 * inv;
    }
    __syncthreads();

    // Phase C: out = P @ v, 4x4 register tiles (13 i-tiles x 8 d-tiles)
    if (tid < 104) {
        int ty = tid >> 3, tx = tid & 7;
        int i0 = ty * 4, d0 = tx * 4;
        float4 a0 = {0, 0, 0, 0}, a1 = {0, 0, 0, 0}, a2 = {0, 0, 0, 0}, a3 = {0, 0, 0, 0};
        for (int j = 0; j < SEQ; ++j) {
            float4 vv = *(const float4*)&v[j][d0];
            float p0 = S[i0 + 0][j], p1 = S[i0 + 1][j];
            float p2 = S[i0 + 2][j], p3 = S[i0 + 3][j];
            a0.x += p0 * vv.x; a0.y += p0 * vv.y; a0.z += p0 * vv.z; a0.w += p0 * vv.w;
            a1.x += p1 * vv.x; a1.y += p1 * vv.y; a1.z += p1 * vv.z; a1.w += p1 * vv.w;
            a2.x += p2 * vv.x; a2.y += p2 * vv.y; a2.z += p2 * vv.z; a2.w += p2 * vv.w;
            a3.x += p3 * vv.x; a3.y += p3 * vv.y; a3.z += p3 * vv.z; a3.w += p3 * vv.w;
        }
        float* op = g_att + ((size_t)b * SEQ + i0) * CDIM + h * HDIM + d0;
        if (i0 + 0 < SEQ) *(float4*)(op)            = a0;
        if (i0 + 1 < SEQ) *(float4*)(op + CDIM)     = a1;
        if (i0 + 2 < SEQ) *(float4*)(op + 2 * CDIM) = a2;
        if (i0 + 3 < SEQ) *(float4*)(op + 3 * CDIM) = a3;
    }
}

// ---------------------------------------------------------------------------
// Launch
// ---------------------------------------------------------------------------
extern "C" void kernel_launch(void* const* d_in, const int* in_sizes, int n_in,
                              void* d_out, int out_size) {
    const float* x      = (const float*)d_in[0];
    const float* mask   = (const float*)d_in[1];
    const float* qkv_w  = (const float*)d_in[2];
    const float* qkv_b  = (const float*)d_in[3];
    const float* proj_w = (const float*)d_in[4];
    const float* proj_b = (const float*)d_in[5];
    const float* rpb    = (const float*)d_in[6];
    const int*   rel    = (const int*)d_in[7];
    float*       out    = (float*)d_out;

    // 0) Combined relative-position bias table
    bias_kernel<<<(HEADS * SEQ * SEQ + 255) / 256, 256>>>(rpb, rel);
    // 1) QKV GEMM: g_qkv = x @ qkv_w + qkv_b (q-cols pre-scaled)
    gemm_tf32<0><<<dim3(QKV_N / 64, MROWS / 128), 256>>>(x, qkv_w, qkv_b, nullptr,
                                                         MROWS, QKV_N, CDIM);
    // 2) Fused per-(window, head) attention: g_att
    attn_kernel<<<dim3(HEADS, B_WIN), 256>>>(mask);
    // 3) Proj GEMM: out = g_att @ proj_w + proj_b
    gemm_tf32<1><<<dim3(CDIM / 64, MROWS / 128), 256>>>(nullptr, proj_w, proj_b, out,
                                                        MROWS, CDIM, CDIM);
}

// round 5
// speedup vs baseline: 1.3138x; 1.0439x over previous
#include <cuda_runtime.h>
#include <cuda_bf16.h>
#include <cstdint>

// Problem constants
#define B_WIN   4096
#define SEQ     49
#define NPAD    64
#define CDIM    384
#define HEADS   12
#define HDIM    32
#define NW      1024
#define MROWS   (B_WIN * SEQ)        // 200704
#define QKV_N   (3 * CDIM)           // 1152
#define SCALE_F 0.17677669529663687f // 32^-0.5

// Scratch (static device globals: allowed; no allocations)
__device__ float    g_qkv[(size_t)MROWS * QKV_N];   // tf32 bits (B_*N, 1152)
__device__ float    g_att[(size_t)MROWS * CDIM];    // tf32 bits (dual use: x-cvt, attn out)
__device__ float    g_bias[HEADS * SEQ * SEQ];      // combined rpb gather (12,49,49)
__device__ uint32_t g_wqkv[CDIM * QKV_N];           // tf32 bits of qkv_w
__device__ uint32_t g_wproj[CDIM * CDIM];           // tf32 bits of proj_w

// ---------------------------------------------------------------------------
// Helpers
// ---------------------------------------------------------------------------
__device__ __forceinline__ uint32_t f2tf32(float f) {
    uint32_t u;
    asm("cvt.rna.tf32.f32 %0, %1;" : "=r"(u) : "f"(f));
    return u;
}

__device__ __forceinline__ void mma_m16n8k8_tf32(float* c, const uint32_t* a, const uint32_t* b) {
    asm volatile(
        "mma.sync.aligned.m16n8k8.row.col.f32.tf32.tf32.f32 "
        "{%0,%1,%2,%3}, {%4,%5,%6,%7}, {%8,%9}, {%0,%1,%2,%3};\n"
        : "+f"(c[0]), "+f"(c[1]), "+f"(c[2]), "+f"(c[3])
        : "r"(a[0]), "r"(a[1]), "r"(a[2]), "r"(a[3]), "r"(b[0]), "r"(b[1]));
}

__device__ __forceinline__ void cp_async16(void* smem_dst, const void* gmem_src) {
    uint32_t s = (uint32_t)__cvta_generic_to_shared(smem_dst);
    asm volatile("cp.async.cg.shared.global [%0], [%1], 16;\n" :: "r"(s), "l"(gmem_src));
}
__device__ __forceinline__ void cp_async_commit() {
    asm volatile("cp.async.commit_group;\n" ::: "memory");
}
template <int N>
__device__ __forceinline__ void cp_async_wait() {
    asm volatile("cp.async.wait_group %0;\n" :: "n"(N) : "memory");
}

// ---------------------------------------------------------------------------
// Pre-conversion kernels
// ---------------------------------------------------------------------------
__global__ void cvt_x_kernel(const float* __restrict__ x) {
    size_t t = (size_t)blockIdx.x * 256 + threadIdx.x;            // float4 index
    const size_t n4 = (size_t)MROWS * CDIM / 4;
    if (t < n4) {
        float4 v = ((const float4*)x)[t];
        uint4 u;
        u.x = f2tf32(v.x); u.y = f2tf32(v.y); u.z = f2tf32(v.z); u.w = f2tf32(v.w);
        ((uint4*)g_att)[t] = u;
    }
}

__global__ void cvt_w_kernel(const float* __restrict__ qkv_w, const float* __restrict__ proj_w) {
    int t = blockIdx.x * 256 + threadIdx.x;
    if (t < CDIM * QKV_N) g_wqkv[t] = f2tf32(qkv_w[t]);
    if (t < CDIM * CDIM)  g_wproj[t] = f2tf32(proj_w[t]);
}

__global__ void bias_kernel(const float* __restrict__ rpb, const int* __restrict__ rel) {
    int t = blockIdx.x * 256 + threadIdx.x;
    if (t < HEADS * SEQ * SEQ) {
        int h = t / (SEQ * SEQ);
        int ij = t - h * (SEQ * SEQ);
        g_bias[t] = rpb[rel[ij] * HEADS + h];
    }
}

// ---------------------------------------------------------------------------
// GEMM: C[M,N] = A[M,K] @ W[K,N] + bias[N]   (tf32-bit operands, fp32 accum)
// MODE 0: A = g_att (x as tf32), W = g_wqkv, C = g_qkv (tf32 bits, q-scaled)
// MODE 1: A = g_att (attn out),  W = g_wproj, C = d_out (fp32)
// BM=128, BN=64, BK=32, 256 threads, 3-stage cp.async pipeline, dyn smem.
// ---------------------------------------------------------------------------
#define AS(s, r, c) sm[(s) * (128 * 36) + (r) * 36 + (c)]
#define BS(s, r, c) sm[3 * (128 * 36) + (s) * (32 * 72) + (r) * 72 + (c)]
#define GEMM_SMEM_BYTES ((3 * 128 * 36 + 3 * 32 * 72) * 4)

template <int MODE>
__global__ void __launch_bounds__(256)
gemm_tf32(const float* __restrict__ bias, float* __restrict__ C_out,
          int M, int N, int K) {
    const uint32_t* A = (const uint32_t*)g_att;
    const uint32_t* W = (MODE == 0) ? g_wqkv : g_wproj;
    float*          C = (MODE == 0) ? g_qkv : C_out;

    extern __shared__ uint32_t sm[];

    const int tid  = threadIdx.x;
    const int warp = tid >> 5;
    const int lane = tid & 31;
    const int wm   = warp >> 1;   // 0..3
    const int wn   = warp & 1;    // 0..1
    const int block_row = blockIdx.y * 128;
    const int block_col = blockIdx.x * 64;

    const int ar_ld = tid >> 3;             // 0..31 (then +32*it)
    const int ac_ld = (tid & 7) << 2;       // 0,4,...,28
    const int br_ld = tid >> 4;             // 0..15 (then +16*it)
    const int bc_ld = (tid & 15) << 2;      // 0..60

    const int NK = K >> 5;

    auto load_tile = [&](int stage, int k0) {
#pragma unroll
        for (int it = 0; it < 4; ++it) {
            int r = ar_ld + it * 32;
            cp_async16(&AS(stage, r, ac_ld),
                       A + (size_t)(block_row + r) * K + k0 + ac_ld);
        }
#pragma unroll
        for (int it = 0; it < 2; ++it) {
            int r = br_ld + it * 16;
            cp_async16(&BS(stage, r, bc_ld),
                       W + (size_t)(k0 + r) * N + block_col + bc_ld);
        }
        cp_async_commit();
    };

    float acc[8][4];
#pragma unroll
    for (int i = 0; i < 8; ++i)
#pragma unroll
        for (int j = 0; j < 4; ++j) acc[i][j] = 0.f;

    load_tile(0, 0);
    load_tile(1, 32);

    for (int i = 0; i < NK; ++i) {
        if (i + 2 < NK) load_tile((i + 2) % 3, (i + 2) << 5);
        else            cp_async_commit();
        cp_async_wait<2>();
        __syncthreads();

        const int st = i % 3;
#pragma unroll
        for (int kk = 0; kk < 32; kk += 8) {
            uint32_t afrag[2][4];
#pragma unroll
            for (int mt = 0; mt < 2; ++mt) {
                int arr = wm * 32 + mt * 16 + (lane >> 2);
                int acd = kk + (lane & 3);
                afrag[mt][0] = AS(st, arr, acd);
                afrag[mt][1] = AS(st, arr + 8, acd);
                afrag[mt][2] = AS(st, arr, acd + 4);
                afrag[mt][3] = AS(st, arr + 8, acd + 4);
            }
            uint32_t bfrag[4][2];
#pragma unroll
            for (int nt = 0; nt < 4; ++nt) {
                int bcc = wn * 32 + nt * 8 + (lane >> 2);
                int brr = kk + (lane & 3);
                bfrag[nt][0] = BS(st, brr, bcc);
                bfrag[nt][1] = BS(st, brr + 4, bcc);
            }
#pragma unroll
            for (int mt = 0; mt < 2; ++mt)
#pragma unroll
                for (int nt = 0; nt < 4; ++nt)
                    mma_m16n8k8_tf32(acc[mt * 4 + nt], afrag[mt], bfrag[nt]);
        }
        __syncthreads();
    }

    // Epilogue
    const float qscale = (MODE == 0 && block_col < CDIM) ? SCALE_F : 1.f;
#pragma unroll
    for (int mt = 0; mt < 2; ++mt) {
#pragma unroll
        for (int nt = 0; nt < 4; ++nt) {
            int r = block_row + wm * 32 + mt * 16 + (lane >> 2);
            int c = block_col + wn * 32 + nt * 8 + ((lane & 3) << 1);
            float b0 = bias[c], b1 = bias[c + 1];
            const float* a4 = acc[mt * 4 + nt];
            if (MODE == 0) {
                // store tf32 bits (consumed by attention mma)
                uint2 u0 = make_uint2(f2tf32((a4[0] + b0) * qscale), f2tf32((a4[1] + b1) * qscale));
                uint2 u1 = make_uint2(f2tf32((a4[2] + b0) * qscale), f2tf32((a4[3] + b1) * qscale));
                *(uint2*)(C + (size_t)r * N + c)       = u0;
                *(uint2*)(C + (size_t)(r + 8) * N + c) = u1;
            } else {
                float2 v0 = make_float2(a4[0] + b0, a4[1] + b1);
                float2 v1 = make_float2(a4[2] + b0, a4[3] + b1);
                *(float2*)(C + (size_t)r * N + c)       = v0;
                *(float2*)(C + (size_t)(r + 8) * N + c) = v1;
            }
        }
    }
}

// ---------------------------------------------------------------------------
// Fused window attention per (window b, head h), tensor-core version.
// 128 threads (4 warps). N padded 49->64. Reads g_qkv (tf32 bits),
// writes g_att (tf32 bits). Bias+mask+softmax fused.
// ---------------------------------------------------------------------------
__global__ void __launch_bounds__(128)
attn_kernel(const float* __restrict__ mask) {
    const int h = blockIdx.x;   // 0..11
    const int b = blockIdx.y;   // 0..4095

    __shared__ uint32_t q[NPAD][36];   // tf32 bits, zero-padded
    __shared__ uint32_t k[NPAD][36];
    __shared__ uint32_t v[NPAD][40];
    __shared__ uint32_t Su[NPAD][68];  // scores (f32 bits) then P (tf32 bits)

    const int tid  = threadIdx.x;
    const int warp = tid >> 5;
    const int lane = tid & 31;

    // ---- Load q/k/v tiles (vectorized, zero-padded) ----
    const float* base = g_qkv + (size_t)b * SEQ * QKV_N + h * HDIM;
    for (int e = tid; e < NPAD * 8; e += 128) {
        int n = e >> 3, d = (e & 7) << 2;
        uint4 qv = {0, 0, 0, 0}, kv = {0, 0, 0, 0}, vv = {0, 0, 0, 0};
        if (n < SEQ) {
            const float* p = base + (size_t)n * QKV_N + d;
            qv = *(const uint4*)(p);
            kv = *(const uint4*)(p + CDIM);
            vv = *(const uint4*)(p + 2 * CDIM);
        }
        *(uint4*)&q[n][d] = qv;
        *(uint4*)&k[n][d] = kv;
        *(uint4*)&v[n][d] = vv;
    }
    __syncthreads();

    // ---- Phase A: S = Q K^T via mma. Warp w -> rows 16w..16w+15, cols 0..63
    {
        float acc[8][4];
#pragma unroll
        for (int i = 0; i < 8; ++i)
#pragma unroll
            for (int j = 0; j < 4; ++j) acc[i][j] = 0.f;
#pragma unroll
        for (int kk = 0; kk < 32; kk += 8) {
            uint32_t a[4];
            int arr = warp * 16 + (lane >> 2);
            int acd = kk + (lane & 3);
            a[0] = q[arr][acd];
            a[1] = q[arr + 8][acd];
            a[2] = q[arr][acd + 4];
            a[3] = q[arr + 8][acd + 4];
#pragma unroll
            for (int nt = 0; nt < 8; ++nt) {
                uint32_t bfr[2];
                int bn = nt * 8 + (lane >> 2);
                bfr[0] = k[bn][kk + (lane & 3)];
                bfr[1] = k[bn][kk + 4 + (lane & 3)];
                mma_m16n8k8_tf32(acc[nt], a, bfr);
            }
        }
        // write S (raw fp32 bits)
        int r0 = warp * 16 + (lane >> 2);
#pragma unroll
        for (int nt = 0; nt < 8; ++nt) {
            int c0 = nt * 8 + ((lane & 3) << 1);
            Su[r0][c0]         = __float_as_uint(acc[nt][0]);
            Su[r0][c0 + 1]     = __float_as_uint(acc[nt][1]);
            Su[r0 + 8][c0]     = __float_as_uint(acc[nt][2]);
            Su[r0 + 8][c0 + 1] = __float_as_uint(acc[nt][3]);
        }
    }
    __syncthreads();

    // ---- Phase B: bias + mask + row softmax; store P as tf32 bits ----
    {
        const float* mptr = mask + (size_t)(b & (NW - 1)) * (SEQ * SEQ);
        const float* bptr = g_bias + (size_t)h * (SEQ * SEQ);
#pragma unroll 1
        for (int t = 0; t < 16; ++t) {
            int i = (warp << 4) + t;
            float s0, s1;
            if (i < SEQ && lane < SEQ)
                s0 = __uint_as_float(Su[i][lane]) + bptr[i * SEQ + lane] + mptr[i * SEQ + lane];
            else s0 = -1e30f;
            if (i < SEQ && lane + 32 < SEQ)
                s1 = __uint_as_float(Su[i][lane + 32]) + bptr[i * SEQ + lane + 32] + mptr[i * SEQ + lane + 32];
            else s1 = -1e30f;
            float m = fmaxf(s0, s1);
#pragma unroll
            for (int off = 16; off; off >>= 1)
                m = fmaxf(m, __shfl_xor_sync(0xffffffffu, m, off));
            float e0 = __expf(s0 - m);
            float e1 = __expf(s1 - m);
            float s = e0 + e1;
#pragma unroll
            for (int off = 16; off; off >>= 1)
                s += __shfl_xor_sync(0xffffffffu, s, off);
            float inv = 1.f / s;
            Su[i][lane]      = f2tf32(e0 * inv);
            Su[i][lane + 32] = f2tf32(e1 * inv);
        }
    }
    __syncthreads();

    // ---- Phase C: O = P V via mma. Warp w -> rows 16w..16w+15, cols 0..31
    {
        float acc[4][4];
#pragma unroll
        for (int i = 0; i < 4; ++i)
#pragma unroll
            for (int j = 0; j < 4; ++j) acc[i][j] = 0.f;
#pragma unroll
        for (int kk = 0; kk < 64; kk += 8) {
            uint32_t a[4];
            int arr = warp * 16 + (lane >> 2);
            int acd = kk + (lane & 3);
            a[0] = Su[arr][acd];
            a[1] = Su[arr + 8][acd];
            a[2] = Su[arr][acd + 4];
            a[3] = Su[arr + 8][acd + 4];
#pragma unroll
            for (int nt = 0; nt < 4; ++nt) {
                uint32_t bfr[2];
                int bc = nt * 8 + (lane >> 2);
                bfr[0] = v[kk + (lane & 3)][bc];
                bfr[1] = v[kk + 4 + (lane & 3)][bc];
                mma_m16n8k8_tf32(acc[nt], a, bfr);
            }
        }
        // store rows < 49 to g_att as tf32 bits
        int r0 = warp * 16 + (lane >> 2);
        float* op = g_att + ((size_t)b * SEQ) * CDIM + h * HDIM;
#pragma unroll
        for (int nt = 0; nt < 4; ++nt) {
            int c0 = nt * 8 + ((lane & 3) << 1);
            if (r0 < SEQ) {
                uint2 u = make_uint2(f2tf32(acc[nt][0]), f2tf32(acc[nt][1]));
                *(uint2*)(op + (size_t)r0 * CDIM + c0) = u;
            }
            if (r0 + 8 < SEQ) {
                uint2 u = make_uint2(f2tf32(acc[nt][2]), f2tf32(acc[nt][3]));
                *(uint2*)(op + (size_t)(r0 + 8) * CDIM + c0) = u;
            }
        }
    }
}

// ---------------------------------------------------------------------------
// Launch
// ---------------------------------------------------------------------------
extern "C" void kernel_launch(void* const* d_in, const int* in_sizes, int n_in,
                              void* d_out, int out_size) {
    const float* x      = (const float*)d_in[0];
    const float* mask   = (const float*)d_in[1];
    const float* qkv_w  = (const float*)d_in[2];
    const float* qkv_b  = (const float*)d_in[3];
    const float* proj_w = (const float*)d_in[4];
    const float* proj_b = (const float*)d_in[5];
    const float* rpb    = (const float*)d_in[6];
    const int*   rel    = (const int*)d_in[7];
    float*       out    = (float*)d_out;

    cudaFuncSetAttribute(gemm_tf32<0>, cudaFuncAttributeMaxDynamicSharedMemorySize, GEMM_SMEM_BYTES);
    cudaFuncSetAttribute(gemm_tf32<1>, cudaFuncAttributeMaxDynamicSharedMemorySize, GEMM_SMEM_BYTES);

    // 0) small precompute: bias table, weight cvt, x cvt (into g_att)
    bias_kernel<<<(HEADS * SEQ * SEQ + 255) / 256, 256>>>(rpb, rel);
    cvt_w_kernel<<<(CDIM * QKV_N + 255) / 256, 256>>>(qkv_w, proj_w);
    cvt_x_kernel<<<(int)(((size_t)MROWS * CDIM / 4 + 255) / 256), 256>>>(x);
    // 1) QKV GEMM: g_qkv = tf32(x) @ tf32(qkv_w) + qkv_b  (q-cols pre-scaled, tf32 out)
    gemm_tf32<0><<<dim3(QKV_N / 64, MROWS / 128), 256, GEMM_SMEM_BYTES>>>(qkv_b, nullptr,
                                                                          MROWS, QKV_N, CDIM);
    // 2) Fused per-(window, head) tensor-core attention: g_att (tf32 bits)
    attn_kernel<<<dim3(HEADS, B_WIN), 128>>>(mask);
    // 3) Proj GEMM: out = g_att @ tf32(proj_w) + proj_b
    gemm_tf32<1><<<dim3(CDIM / 64, MROWS / 128), 256, GEMM_SMEM_BYTES>>>(proj_b, out,
                                                                         MROWS, CDIM, CDIM);
}

// round 6
// speedup vs baseline: 1.7658x; 1.3440x over previous
#include <cuda_runtime.h>
#include <cuda_bf16.h>
#include <cstdint>

// Problem constants
#define B_WIN   4096
#define SEQ     49
#define NPAD    64
#define CDIM    384
#define HEADS   12
#define HDIM    32
#define NW      1024
#define MROWS   (B_WIN * SEQ)        // 200704
#define QKV_N   (3 * CDIM)           // 1152
#define SCALE_F 0.17677669529663687f // 32^-0.5

// Scratch (static device globals: allowed; no allocations)
__device__ float    g_qkv[(size_t)MROWS * QKV_N];   // tf32 bits (B_*N, 1152)
__device__ float    g_att[(size_t)MROWS * CDIM];    // tf32 bits (dual use: x-cvt, attn out)
__device__ uint32_t g_wqkv[CDIM * QKV_N];           // tf32 bits of qkv_w
__device__ uint32_t g_wproj[CDIM * CDIM];           // tf32 bits of proj_w
__device__ float    g_biasp[HEADS * NPAD * NPAD];   // padded bias (12,64,64), pad=-1e30
__device__ float    g_maskp[NW * NPAD * NPAD];      // padded mask (1024,64,64), pad=0

// ---------------------------------------------------------------------------
// Helpers
// ---------------------------------------------------------------------------
__device__ __forceinline__ uint32_t f2tf32(float f) {
    uint32_t u;
    asm("cvt.rna.tf32.f32 %0, %1;" : "=r"(u) : "f"(f));
    return u;
}

__device__ __forceinline__ void mma_m16n8k8_tf32(float* c, const uint32_t* a, const uint32_t* b) {
    asm volatile(
        "mma.sync.aligned.m16n8k8.row.col.f32.tf32.tf32.f32 "
        "{%0,%1,%2,%3}, {%4,%5,%6,%7}, {%8,%9}, {%0,%1,%2,%3};\n"
        : "+f"(c[0]), "+f"(c[1]), "+f"(c[2]), "+f"(c[3])
        : "r"(a[0]), "r"(a[1]), "r"(a[2]), "r"(a[3]), "r"(b[0]), "r"(b[1]));
}

__device__ __forceinline__ void cp_async16(void* smem_dst, const void* gmem_src) {
    uint32_t s = (uint32_t)__cvta_generic_to_shared(smem_dst);
    asm volatile("cp.async.cg.shared.global [%0], [%1], 16;\n" :: "r"(s), "l"(gmem_src));
}
__device__ __forceinline__ void cp_async_commit() {
    asm volatile("cp.async.commit_group;\n" ::: "memory");
}
template <int N>
__device__ __forceinline__ void cp_async_wait() {
    asm volatile("cp.async.wait_group %0;\n" :: "n"(N) : "memory");
}

// ---------------------------------------------------------------------------
// Pre-conversion / padding kernels
// ---------------------------------------------------------------------------
__global__ void cvt_x_kernel(const float* __restrict__ x) {
    size_t t = (size_t)blockIdx.x * 256 + threadIdx.x;            // float4 index
    const size_t n4 = (size_t)MROWS * CDIM / 4;
    if (t < n4) {
        float4 v = ((const float4*)x)[t];
        uint4 u;
        u.x = f2tf32(v.x); u.y = f2tf32(v.y); u.z = f2tf32(v.z); u.w = f2tf32(v.w);
        ((uint4*)g_att)[t] = u;
    }
}

__global__ void cvt_w_kernel(const float* __restrict__ qkv_w, const float* __restrict__ proj_w) {
    int t = blockIdx.x * 256 + threadIdx.x;
    if (t < CDIM * QKV_N) g_wqkv[t] = f2tf32(qkv_w[t]);
    if (t < CDIM * CDIM)  g_wproj[t] = f2tf32(proj_w[t]);
}

// Padded combined-bias table: g_biasp[h][i][j], -1e30 outside 49x49
__global__ void biasp_kernel(const float* __restrict__ rpb, const int* __restrict__ rel) {
    int t = blockIdx.x * 256 + threadIdx.x;           // h*4096 + i*64 + j
    if (t < HEADS * NPAD * NPAD) {
        int h = t >> 12, ij = t & 4095, i = ij >> 6, j = ij & 63;
        float v = -1e30f;
        if (i < SEQ && j < SEQ) v = rpb[rel[i * SEQ + j] * HEADS + h];
        g_biasp[t] = v;
    }
}

// Padded mask: g_maskp[w][i][j], 0 outside 49x49
__global__ void maskp_kernel(const float* __restrict__ mask) {
    int t = blockIdx.x * 256 + threadIdx.x;           // w*4096 + i*64 + j
    if (t < NW * NPAD * NPAD) {
        int w = t >> 12, ij = t & 4095, i = ij >> 6, j = ij & 63;
        float v = 0.f;
        if (i < SEQ && j < SEQ) v = mask[(size_t)w * SEQ * SEQ + i * SEQ + j];
        g_maskp[t] = v;
    }
}

// ---------------------------------------------------------------------------
// GEMM: C[M,N] = A[M,K] @ W[K,N] + bias[N]   (tf32-bit operands, fp32 accum)
// MODE 0: A = g_att (x as tf32), W = g_wqkv, C = g_qkv (tf32 bits, q-scaled)
// MODE 1: A = g_att (attn out),  W = g_wproj, C = d_out (fp32)
// BM=128, BN=64, BK=32, 256 threads, 2-stage cp.async, 4 CTAs/SM.
// ---------------------------------------------------------------------------
#define AS(s, r, c) sm[(s) * (128 * 36) + (r) * 36 + (c)]
#define BS(s, r, c) sm[2 * (128 * 36) + (s) * (32 * 72) + (r) * 72 + (c)]
#define GEMM_SMEM_BYTES ((2 * 128 * 36 + 2 * 32 * 72) * 4)

template <int MODE>
__global__ void __launch_bounds__(256, 4)
gemm_tf32(const float* __restrict__ bias, float* __restrict__ C_out,
          int M, int N, int K) {
    const uint32_t* A = (const uint32_t*)g_att;
    const uint32_t* W = (MODE == 0) ? g_wqkv : g_wproj;
    float*          C = (MODE == 0) ? g_qkv : C_out;

    extern __shared__ uint32_t sm[];

    const int tid  = threadIdx.x;
    const int warp = tid >> 5;
    const int lane = tid & 31;
    const int wm   = warp >> 1;   // 0..3
    const int wn   = warp & 1;    // 0..1
    const int block_row = blockIdx.y * 128;
    const int block_col = blockIdx.x * 64;

    const int ar_ld = tid >> 3;             // 0..31 (then +32*it)
    const int ac_ld = (tid & 7) << 2;       // 0,4,...,28
    const int br_ld = tid >> 4;             // 0..15 (then +16*it)
    const int bc_ld = (tid & 15) << 2;      // 0..60

    const int NK = K >> 5;

    auto load_tile = [&](int stage, int k0) {
#pragma unroll
        for (int it = 0; it < 4; ++it) {
            int r = ar_ld + it * 32;
            cp_async16(&AS(stage, r, ac_ld),
                       A + (size_t)(block_row + r) * K + k0 + ac_ld);
        }
#pragma unroll
        for (int it = 0; it < 2; ++it) {
            int r = br_ld + it * 16;
            cp_async16(&BS(stage, r, bc_ld),
                       W + (size_t)(k0 + r) * N + block_col + bc_ld);
        }
        cp_async_commit();
    };

    float acc[8][4];
#pragma unroll
    for (int i = 0; i < 8; ++i)
#pragma unroll
        for (int j = 0; j < 4; ++j) acc[i][j] = 0.f;

    load_tile(0, 0);

    for (int i = 0; i < NK; ++i) {
        if (i + 1 < NK) {
            load_tile((i + 1) & 1, (i + 1) << 5);
            cp_async_wait<1>();
        } else {
            cp_async_wait<0>();
        }
        __syncthreads();

        const int st = i & 1;
#pragma unroll
        for (int kk = 0; kk < 32; kk += 8) {
            uint32_t afrag[2][4];
#pragma unroll
            for (int mt = 0; mt < 2; ++mt) {
                int arr = wm * 32 + mt * 16 + (lane >> 2);
                int acd = kk + (lane & 3);
                afrag[mt][0] = AS(st, arr, acd);
                afrag[mt][1] = AS(st, arr + 8, acd);
                afrag[mt][2] = AS(st, arr, acd + 4);
                afrag[mt][3] = AS(st, arr + 8, acd + 4);
            }
            uint32_t bfrag[4][2];
#pragma unroll
            for (int nt = 0; nt < 4; ++nt) {
                int bcc = wn * 32 + nt * 8 + (lane >> 2);
                int brr = kk + (lane & 3);
                bfrag[nt][0] = BS(st, brr, bcc);
                bfrag[nt][1] = BS(st, brr + 4, bcc);
            }
#pragma unroll
            for (int mt = 0; mt < 2; ++mt)
#pragma unroll
                for (int nt = 0; nt < 4; ++nt)
                    mma_m16n8k8_tf32(acc[mt * 4 + nt], afrag[mt], bfrag[nt]);
        }
        __syncthreads();
    }

    // Epilogue
    const float qscale = (MODE == 0 && block_col < CDIM) ? SCALE_F : 1.f;
#pragma unroll
    for (int mt = 0; mt < 2; ++mt) {
#pragma unroll
        for (int nt = 0; nt < 4; ++nt) {
            int r = block_row + wm * 32 + mt * 16 + (lane >> 2);
            int c = block_col + wn * 32 + nt * 8 + ((lane & 3) << 1);
            float b0 = bias[c], b1 = bias[c + 1];
            const float* a4 = acc[mt * 4 + nt];
            if (MODE == 0) {
                uint2 u0 = make_uint2(f2tf32((a4[0] + b0) * qscale), f2tf32((a4[1] + b1) * qscale));
                uint2 u1 = make_uint2(f2tf32((a4[2] + b0) * qscale), f2tf32((a4[3] + b1) * qscale));
                *(uint2*)(C + (size_t)r * N + c)       = u0;
                *(uint2*)(C + (size_t)(r + 8) * N + c) = u1;
            } else {
                float2 v0 = make_float2(a4[0] + b0, a4[1] + b1);
                float2 v1 = make_float2(a4[2] + b0, a4[3] + b1);
                *(float2*)(C + (size_t)r * N + c)       = v0;
                *(float2*)(C + (size_t)(r + 8) * N + c) = v1;
            }
        }
    }
}

// ---------------------------------------------------------------------------
// Fused window attention per (window b, head h), tensor cores, S-in-registers.
// 128 threads (4 warps). Smem: q|k (aliased by P after phase A) + v = 28.7KB.
// ---------------------------------------------------------------------------
__global__ void __launch_bounds__(128, 6)
attn_kernel() {
    const int h = blockIdx.x;   // 0..11
    const int b = blockIdx.y;   // 0..4095

    __shared__ uint32_t sQK[2 * NPAD * 36];  // q rows then k rows; P aliases (stride 68)
    __shared__ uint32_t sV[NPAD][40];

    const int tid  = threadIdx.x;
    const int warp = tid >> 5;
    const int lane = tid & 31;

    uint32_t* q = sQK;
    uint32_t* k = sQK + NPAD * 36;
    uint32_t* P = sQK;                       // alias, stride 68 (4352 <= 4608 words)

    // ---- Load q/k/v tiles (tf32 bits, zero-padded rows 49..63) ----
    const float* base = g_qkv + (size_t)b * SEQ * QKV_N + h * HDIM;
    for (int e = tid; e < NPAD * 8; e += 128) {
        int n = e >> 3, d = (e & 7) << 2;
        uint4 qv = {0, 0, 0, 0}, kv = {0, 0, 0, 0}, vv = {0, 0, 0, 0};
        if (n < SEQ) {
            const float* p = base + (size_t)n * QKV_N + d;
            qv = *(const uint4*)(p);
            kv = *(const uint4*)(p + CDIM);
            vv = *(const uint4*)(p + 2 * CDIM);
        }
        *(uint4*)&q[n * 36 + d] = qv;
        *(uint4*)&k[n * 36 + d] = kv;
        *(uint4*)&sV[n][d] = vv;
    }
    __syncthreads();

    const int r0 = warp * 16 + (lane >> 2);      // rows r0, r0+8
    const int cq = (lane & 3);                   // quad lane

    // ---- Phase A: S = Q K^T in registers ----
    float acc[8][4];
#pragma unroll
    for (int i = 0; i < 8; ++i)
#pragma unroll
        for (int j = 0; j < 4; ++j) acc[i][j] = 0.f;
#pragma unroll
    for (int kk = 0; kk < 32; kk += 8) {
        uint32_t a[4];
        a[0] = q[r0 * 36 + kk + cq];
        a[1] = q[(r0 + 8) * 36 + kk + cq];
        a[2] = q[r0 * 36 + kk + 4 + cq];
        a[3] = q[(r0 + 8) * 36 + kk + 4 + cq];
#pragma unroll
        for (int nt = 0; nt < 8; ++nt) {
            uint32_t bfr[2];
            int bn = nt * 8 + (lane >> 2);
            bfr[0] = k[bn * 36 + kk + cq];
            bfr[1] = k[bn * 36 + kk + 4 + cq];
            mma_m16n8k8_tf32(acc[nt], a, bfr);
        }
    }

    // ---- Add padded bias + mask (branch-free; pad cols/rows get -1e30) ----
    {
        const float* bp = g_biasp + (size_t)h * (NPAD * NPAD);
        const float* mp = g_maskp + (size_t)(b & (NW - 1)) * (NPAD * NPAD);
        const int c0 = cq << 1;                      // 0,2,4,6
#pragma unroll
        for (int nt = 0; nt < 8; ++nt) {
            int c = nt * 8 + c0;
            float2 b0 = *(const float2*)(bp + r0 * NPAD + c);
            float2 m0 = *(const float2*)(mp + r0 * NPAD + c);
            float2 b1 = *(const float2*)(bp + (r0 + 8) * NPAD + c);
            float2 m1 = *(const float2*)(mp + (r0 + 8) * NPAD + c);
            acc[nt][0] += b0.x + m0.x;
            acc[nt][1] += b0.y + m0.y;
            acc[nt][2] += b1.x + m1.x;
            acc[nt][3] += b1.y + m1.y;
        }
    }

    // ---- Row softmax in registers (quad shuffles only) ----
    {
        float mx0 = -3e38f, mx1 = -3e38f;
#pragma unroll
        for (int nt = 0; nt < 8; ++nt) {
            mx0 = fmaxf(mx0, fmaxf(acc[nt][0], acc[nt][1]));
            mx1 = fmaxf(mx1, fmaxf(acc[nt][2], acc[nt][3]));
        }
        mx0 = fmaxf(mx0, __shfl_xor_sync(0xffffffffu, mx0, 1));
        mx0 = fmaxf(mx0, __shfl_xor_sync(0xffffffffu, mx0, 2));
        mx1 = fmaxf(mx1, __shfl_xor_sync(0xffffffffu, mx1, 1));
        mx1 = fmaxf(mx1, __shfl_xor_sync(0xffffffffu, mx1, 2));
        float s0 = 0.f, s1 = 0.f;
#pragma unroll
        for (int nt = 0; nt < 8; ++nt) {
            acc[nt][0] = __expf(acc[nt][0] - mx0); s0 += acc[nt][0];
            acc[nt][1] = __expf(acc[nt][1] - mx0); s0 += acc[nt][1];
            acc[nt][2] = __expf(acc[nt][2] - mx1); s1 += acc[nt][2];
            acc[nt][3] = __expf(acc[nt][3] - mx1); s1 += acc[nt][3];
        }
        s0 += __shfl_xor_sync(0xffffffffu, s0, 1);
        s0 += __shfl_xor_sync(0xffffffffu, s0, 2);
        s1 += __shfl_xor_sync(0xffffffffu, s1, 1);
        s1 += __shfl_xor_sync(0xffffffffu, s1, 2);
        float inv0 = 1.f / s0, inv1 = 1.f / s1;
#pragma unroll
        for (int nt = 0; nt < 8; ++nt) {
            acc[nt][0] *= inv0; acc[nt][1] *= inv0;
            acc[nt][2] *= inv1; acc[nt][3] *= inv1;
        }
    }

    // All warps must finish reading q/k before P (alias) is written
    __syncthreads();

    // ---- Write P (tf32 bits) to aliased smem, stride 68 ----
    {
        const int c0 = cq << 1;
#pragma unroll
        for (int nt = 0; nt < 8; ++nt) {
            int c = nt * 8 + c0;
            uint2 u0 = make_uint2(f2tf32(acc[nt][0]), f2tf32(acc[nt][1]));
            uint2 u1 = make_uint2(f2tf32(acc[nt][2]), f2tf32(acc[nt][3]));
            *(uint2*)&P[r0 * 68 + c]       = u0;
            *(uint2*)&P[(r0 + 8) * 68 + c] = u1;
        }
    }
    __syncwarp();   // each warp reads only its own P rows

    // ---- Phase C: O = P V ----
    {
        float oacc[4][4];
#pragma unroll
        for (int i = 0; i < 4; ++i)
#pragma unroll
            for (int j = 0; j < 4; ++j) oacc[i][j] = 0.f;
#pragma unroll
        for (int kk = 0; kk < 64; kk += 8) {
            uint32_t a[4];
            a[0] = P[r0 * 68 + kk + cq];
            a[1] = P[(r0 + 8) * 68 + kk + cq];
            a[2] = P[r0 * 68 + kk + 4 + cq];
            a[3] = P[(r0 + 8) * 68 + kk + 4 + cq];
#pragma unroll
            for (int nt = 0; nt < 4; ++nt) {
                uint32_t bfr[2];
                int bc = nt * 8 + (lane >> 2);
                bfr[0] = sV[kk + cq][bc];
                bfr[1] = sV[kk + 4 + cq][bc];
                mma_m16n8k8_tf32(oacc[nt], a, bfr);
            }
        }
        // store rows < 49 to g_att as tf32 bits
        float* op = g_att + ((size_t)b * SEQ) * CDIM + h * HDIM;
        const int c0 = cq << 1;
#pragma unroll
        for (int nt = 0; nt < 4; ++nt) {
            int c = nt * 8 + c0;
            if (r0 < SEQ) {
                uint2 u = make_uint2(f2tf32(oacc[nt][0]), f2tf32(oacc[nt][1]));
                *(uint2*)(op + (size_t)r0 * CDIM + c) = u;
            }
            if (r0 + 8 < SEQ) {
                uint2 u = make_uint2(f2tf32(oacc[nt][2]), f2tf32(oacc[nt][3]));
                *(uint2*)(op + (size_t)(r0 + 8) * CDIM + c) = u;
            }
        }
    }
}

// ---------------------------------------------------------------------------
// Launch
// ---------------------------------------------------------------------------
extern "C" void kernel_launch(void* const* d_in, const int* in_sizes, int n_in,
                              void* d_out, int out_size) {
    const float* x      = (const float*)d_in[0];
    const float* mask   = (const float*)d_in[1];
    const float* qkv_w  = (const float*)d_in[2];
    const float* qkv_b  = (const float*)d_in[3];
    const float* proj_w = (const float*)d_in[4];
    const float* proj_b = (const float*)d_in[5];
    const float* rpb    = (const float*)d_in[6];
    const int*   rel    = (const int*)d_in[7];
    float*       out    = (float*)d_out;

    cudaFuncSetAttribute(gemm_tf32<0>, cudaFuncAttributeMaxDynamicSharedMemorySize, GEMM_SMEM_BYTES);
    cudaFuncSetAttribute(gemm_tf32<1>, cudaFuncAttributeMaxDynamicSharedMemorySize, GEMM_SMEM_BYTES);

    // 0) precompute: padded bias/mask tables, weight cvt, x cvt (into g_att)
    biasp_kernel<<<(HEADS * NPAD * NPAD + 255) / 256, 256>>>(rpb, rel);
    maskp_kernel<<<(NW * NPAD * NPAD + 255) / 256, 256>>>(mask);
    cvt_w_kernel<<<(CDIM * QKV_N + 255) / 256, 256>>>(qkv_w, proj_w);
    cvt_x_kernel<<<(int)(((size_t)MROWS * CDIM / 4 + 255) / 256), 256>>>(x);
    // 1) QKV GEMM: g_qkv = tf32(x) @ tf32(qkv_w) + qkv_b  (q-cols pre-scaled, tf32 out)
    gemm_tf32<0><<<dim3(QKV_N / 64, MROWS / 128), 256, GEMM_SMEM_BYTES>>>(qkv_b, nullptr,
                                                                          MROWS, QKV_N, CDIM);
    // 2) Fused per-(window, head) tensor-core attention: g_att (tf32 bits)
    attn_kernel<<<dim3(HEADS, B_WIN), 128>>>();
    // 3) Proj GEMM: out = g_att @ tf32(proj_w) + proj_b
    gemm_tf32<1><<<dim3(CDIM / 64, MROWS / 128), 256, GEMM_SMEM_BYTES>>>(proj_b, out,
                                                                         MROWS, CDIM, CDIM);
}

// round 8
// speedup vs baseline: 2.1645x; 1.2258x over previous
#include <cuda_runtime.h>
#include <cuda_bf16.h>
#include <cstdint>

// Problem constants
#define B_WIN   4096
#define SEQ     49
#define NPAD    64
#define CDIM    384
#define HEADS   12
#define HDIM    32
#define NW      1024
#define MROWS   (B_WIN * SEQ)        // 200704
#define QKV_N   (3 * CDIM)           // 1152
#define K8S     (CDIM / 8)           // 48 k-subtiles
#define SCALE_F 0.17677669529663687f // 32^-0.5

// Scratch (static device globals)
// g_att: A-operand in fragment-tiled layout [m16][k8][lane][4] (tf32 bits)
// g_qkv: row-major (B_*N, 1152) tf32 bits (consumed by attention row-wise)
__device__ float    g_qkv[(size_t)MROWS * QKV_N];
__device__ float    g_att[(size_t)MROWS * CDIM];
__device__ uint32_t g_wqkv_t[QKV_N / 8 * K8S * 64];   // B-tiled [n8][k8][lane][2]
__device__ uint32_t g_wproj_t[CDIM / 8 * K8S * 64];
__device__ float    g_biasp[HEADS * NPAD * NPAD];     // padded bias, pad=-1e30
__device__ float    g_maskp[NW * NPAD * NPAD];        // padded mask, pad=0

// ---------------------------------------------------------------------------
// Helpers
// ---------------------------------------------------------------------------
__device__ __forceinline__ uint32_t f2tf32(float f) {
    uint32_t u;
    asm("cvt.rna.tf32.f32 %0, %1;" : "=r"(u) : "f"(f));
    return u;
}

__device__ __forceinline__ void mma_m16n8k8_tf32(float* c, const uint32_t* a, const uint32_t* b) {
    asm volatile(
        "mma.sync.aligned.m16n8k8.row.col.f32.tf32.tf32.f32 "
        "{%0,%1,%2,%3}, {%4,%5,%6,%7}, {%8,%9}, {%0,%1,%2,%3};\n"
        : "+f"(c[0]), "+f"(c[1]), "+f"(c[2]), "+f"(c[3])
        : "r"(a[0]), "r"(a[1]), "r"(a[2]), "r"(a[3]), "r"(b[0]), "r"(b[1]));
}

__device__ __forceinline__ void cp_async16(void* smem_dst, const void* gmem_src) {
    uint32_t s = (uint32_t)__cvta_generic_to_shared(smem_dst);
    asm volatile("cp.async.cg.shared.global [%0], [%1], 16;\n" :: "r"(s), "l"(gmem_src));
}
__device__ __forceinline__ void cp_async_commit() {
    asm volatile("cp.async.commit_group;\n" ::: "memory");
}
template <int N>
__device__ __forceinline__ void cp_async_wait() {
    asm volatile("cp.async.wait_group %0;\n" :: "n"(N) : "memory");
}

// A-tiled element address (in floats) for logical (m, k), K=384
__device__ __forceinline__ size_t a_tiled_off(int m, int kcol) {
    int m16 = m >> 4, r = m & 15, k8 = kcol >> 3, c = kcol & 7;
    int lane = ((r & 7) << 2) | (c & 3);
    int w = (r >> 3) | ((c >> 2) << 1);
    return (((size_t)m16 * K8S + k8) * 32 + lane) * 4 + w;
}

// ---------------------------------------------------------------------------
// Pre-conversion / padding kernels
// ---------------------------------------------------------------------------
// x (row-major f32) -> g_att (A-tiled tf32 bits). One thread per (m16,k8,lane).
__global__ void cvt_x_kernel(const float* __restrict__ x) {
    size_t t = (size_t)blockIdx.x * 256 + threadIdx.x;
    const size_t total = (size_t)(MROWS / 16) * K8S * 32;
    if (t >= total) return;
    int lane = (int)(t & 31);
    size_t u = t >> 5;
    int k8 = (int)(u % K8S);
    int m16 = (int)(u / K8S);
    int r0 = lane >> 2, c0 = lane & 3;
    const float* xp = x + (size_t)(m16 * 16) * CDIM + k8 * 8;
    uint4 o;
    o.x = f2tf32(xp[(size_t)r0 * CDIM + c0]);
    o.y = f2tf32(xp[(size_t)(r0 + 8) * CDIM + c0]);
    o.z = f2tf32(xp[(size_t)r0 * CDIM + c0 + 4]);
    o.w = f2tf32(xp[(size_t)(r0 + 8) * CDIM + c0 + 4]);
    *(uint4*)(g_att + t * 4) = o;
}

// Weights -> B-tiled tf32 bits. One thread per (n8,k8,lane), writes 2 words.
__global__ void cvt_w_kernel(const float* __restrict__ qkv_w, const float* __restrict__ proj_w) {
    int t = blockIdx.x * 256 + threadIdx.x;
    int lane = t & 31;
    int u = t >> 5;
    int k8 = u % K8S;
    int n8 = u / K8S;
    int kk = k8 * 8 + (lane & 3);
    int nn = n8 * 8 + (lane >> 2);
    if (n8 < QKV_N / 8) {
        uint2 o;
        o.x = f2tf32(qkv_w[(size_t)kk * QKV_N + nn]);
        o.y = f2tf32(qkv_w[(size_t)(kk + 4) * QKV_N + nn]);
        *(uint2*)(g_wqkv_t + (size_t)t * 2) = o;
    }
    if (n8 < CDIM / 8) {
        uint2 o;
        o.x = f2tf32(proj_w[(size_t)kk * CDIM + nn]);
        o.y = f2tf32(proj_w[(size_t)(kk + 4) * CDIM + nn]);
        *(uint2*)(g_wproj_t + (size_t)t * 2) = o;
    }
}

__global__ void biasp_kernel(const float* __restrict__ rpb, const int* __restrict__ rel) {
    int t = blockIdx.x * 256 + threadIdx.x;
    if (t < HEADS * NPAD * NPAD) {
        int h = t >> 12, ij = t & 4095, i = ij >> 6, j = ij & 63;
        float v = -1e30f;
        if (i < SEQ && j < SEQ) v = rpb[rel[i * SEQ + j] * HEADS + h];
        g_biasp[t] = v;
    }
}

__global__ void maskp_kernel(const float* __restrict__ mask) {
    int t = blockIdx.x * 256 + threadIdx.x;
    if (t < NW * NPAD * NPAD) {
        int w = t >> 12, ij = t & 4095, i = ij >> 6, j = ij & 63;
        float v = 0.f;
        if (i < SEQ && j < SEQ) v = mask[(size_t)w * SEQ * SEQ + i * SEQ + j];
        g_maskp[t] = v;
    }
}

// ---------------------------------------------------------------------------
// GEMM: C[M,N] = A @ W + bias. A in A-tiled layout, W in B-tiled layout.
// BM=128, BN=128, BK=32, 128 threads (4 warps, 2x2), warp tile 64x64.
// 3-stage cp.async pipeline; fragments load as LDS.128 / LDS.64.
// MODE 0: A = g_att (x), W = g_wqkv_t, C = g_qkv (row-major tf32, q-scaled)
// MODE 1: A = g_att (attn), W = g_wproj_t, C = d_out (f32)
// ---------------------------------------------------------------------------
#define GSTAGE (32768)
#define GSM_A(s) ((s) * GSTAGE)
#define GSM_B(s) ((s) * GSTAGE + 16384)
#define GEMM_DSMEM (3 * GSTAGE)

template <int MODE>
__global__ void __launch_bounds__(128)
gemm_frag(const float* __restrict__ bias, float* __restrict__ C_out) {
    const uint32_t* A = (const uint32_t*)g_att;
    const uint32_t* W = (MODE == 0) ? g_wqkv_t : g_wproj_t;
    float*          C = (MODE == 0) ? g_qkv : C_out;
    const int    Ntot = (MODE == 0) ? QKV_N : CDIM;

    extern __shared__ __align__(16) uint8_t sm[];

    const int tid  = threadIdx.x;
    const int warp = tid >> 5;
    const int lane = tid & 31;
    const int wm   = warp >> 1;          // 0..1
    const int wn   = warp & 1;           // 0..1
    const int m16base = blockIdx.y * 8;  // 128 rows
    const int n8base  = blockIdx.x * 16; // 128 cols
    const int n0 = n8base * 8;

    auto load_chunk = [&](int s, int c) {
#pragma unroll
        for (int it = 0; it < 8; ++it) {
            int idx = tid + it * 128;            // 0..1023
            int u = idx >> 5, in16 = idx & 31;   // A unit=512B (32x16B)
            cp_async16(sm + GSM_A(s) + idx * 16,
                       A + (((size_t)(m16base + (u >> 2)) * K8S + c * 4 + (u & 3)) * 32 + in16) * 4);
        }
#pragma unroll
        for (int it = 0; it < 8; ++it) {
            int idx = tid + it * 128;
            int u = idx >> 4, in16 = idx & 15;   // B unit=256B (16x16B)
            cp_async16(sm + GSM_B(s) + idx * 16,
                       W + (((size_t)(n8base + (u >> 2)) * K8S + c * 4 + (u & 3)) * 16 + in16) * 4);
        }
        cp_async_commit();
    };

    float acc[4][8][4];
#pragma unroll
    for (int i = 0; i < 4; ++i)
#pragma unroll
        for (int j = 0; j < 8; ++j)
#pragma unroll
            for (int q = 0; q < 4; ++q) acc[i][j][q] = 0.f;

    load_chunk(0, 0);
    load_chunk(1, 1);

    const int NCH = CDIM / 32;   // 12
    for (int c = 0; c < NCH; ++c) {
        if (c + 2 < NCH) load_chunk((c + 2) % 3, c + 2);
        else             cp_async_commit();
        cp_async_wait<2>();
        __syncthreads();

        const uint32_t* smA = (const uint32_t*)(sm + GSM_A(c % 3));
        const uint32_t* smB = (const uint32_t*)(sm + GSM_B(c % 3));
#pragma unroll
        for (int k8l = 0; k8l < 4; ++k8l) {
            uint4 a[4];
#pragma unroll
            for (int mt = 0; mt < 4; ++mt)
                a[mt] = *(const uint4*)&smA[(((wm * 4 + mt) * 4 + k8l) * 32 + lane) * 4];
            uint2 b[8];
#pragma unroll
            for (int nt = 0; nt < 8; ++nt)
                b[nt] = *(const uint2*)&smB[(((wn * 8 + nt) * 4 + k8l) * 32 + lane) * 2];
#pragma unroll
            for (int mt = 0; mt < 4; ++mt)
#pragma unroll
                for (int nt = 0; nt < 8; ++nt)
                    mma_m16n8k8_tf32(acc[mt][nt], (const uint32_t*)&a[mt], (const uint32_t*)&b[nt]);
        }
        __syncthreads();
    }

    // Epilogue: row-major C + bias (MODE 0 also tf32-rounds and scales q cols)
    const float qs = (MODE == 0 && n0 < CDIM) ? SCALE_F : 1.f;
    const int rbase = m16base * 16 + wm * 64 + (lane >> 2);
    const int cbase = n0 + wn * 64 + ((lane & 3) << 1);
#pragma unroll
    for (int mt = 0; mt < 4; ++mt) {
        int r = rbase + mt * 16;
#pragma unroll
        for (int nt = 0; nt < 8; ++nt) {
            int cc = cbase + nt * 8;
            float b0 = bias[cc], b1 = bias[cc + 1];
            const float* a4 = acc[mt][nt];
            if (MODE == 0) {
                uint2 u0 = make_uint2(f2tf32((a4[0] + b0) * qs), f2tf32((a4[1] + b1) * qs));
                uint2 u1 = make_uint2(f2tf32((a4[2] + b0) * qs), f2tf32((a4[3] + b1) * qs));
                *(uint2*)(C + (size_t)r * Ntot + cc)       = u0;
                *(uint2*)(C + (size_t)(r + 8) * Ntot + cc) = u1;
            } else {
                *(float2*)(C + (size_t)r * Ntot + cc)       = make_float2(a4[0] + b0, a4[1] + b1);
                *(float2*)(C + (size_t)(r + 8) * Ntot + cc) = make_float2(a4[2] + b0, a4[3] + b1);
            }
        }
    }
}

// ---------------------------------------------------------------------------
// Fused window attention per (window b, head h). S-in-registers (R6 design).
// Output written to g_att in A-tiled layout (tf32 bits).
// ---------------------------------------------------------------------------
__global__ void __launch_bounds__(128, 6)
attn_kernel() {
    const int h = blockIdx.x;
    const int b = blockIdx.y;

    __shared__ uint32_t sQK[2 * NPAD * 36];
    __shared__ uint32_t sV[NPAD][40];

    const int tid  = threadIdx.x;
    const int warp = tid >> 5;
    const int lane = tid & 31;

    uint32_t* q = sQK;
    uint32_t* k = sQK + NPAD * 36;
    uint32_t* P = sQK;                       // alias, stride 68

    const float* base = g_qkv + (size_t)b * SEQ * QKV_N + h * HDIM;
    for (int e = tid; e < NPAD * 8; e += 128) {
        int n = e >> 3, d = (e & 7) << 2;
        uint4 qv = {0, 0, 0, 0}, kv = {0, 0, 0, 0}, vv = {0, 0, 0, 0};
        if (n < SEQ) {
            const float* p = base + (size_t)n * QKV_N + d;
            qv = *(const uint4*)(p);
            kv = *(const uint4*)(p + CDIM);
            vv = *(const uint4*)(p + 2 * CDIM);
        }
        *(uint4*)&q[n * 36 + d] = qv;
        *(uint4*)&k[n * 36 + d] = kv;
        *(uint4*)&sV[n][d] = vv;
    }
    __syncthreads();

    const int r0 = warp * 16 + (lane >> 2);
    const int cq = (lane & 3);

    float acc[8][4];
#pragma unroll
    for (int i = 0; i < 8; ++i)
#pragma unroll
        for (int j = 0; j < 4; ++j) acc[i][j] = 0.f;
#pragma unroll
    for (int kk = 0; kk < 32; kk += 8) {
        uint32_t a[4];
        a[0] = q[r0 * 36 + kk + cq];
        a[1] = q[(r0 + 8) * 36 + kk + cq];
        a[2] = q[r0 * 36 + kk + 4 + cq];
        a[3] = q[(r0 + 8) * 36 + kk + 4 + cq];
#pragma unroll
        for (int nt = 0; nt < 8; ++nt) {
            uint32_t bfr[2];
            int bn = nt * 8 + (lane >> 2);
            bfr[0] = k[bn * 36 + kk + cq];
            bfr[1] = k[bn * 36 + kk + 4 + cq];
            mma_m16n8k8_tf32(acc[nt], a, bfr);
        }
    }

    {
        const float* bp = g_biasp + (size_t)h * (NPAD * NPAD);
        const float* mp = g_maskp + (size_t)(b & (NW - 1)) * (NPAD * NPAD);
        const int c0 = cq << 1;
#pragma unroll
        for (int nt = 0; nt < 8; ++nt) {
            int c = nt * 8 + c0;
            float2 b0 = *(const float2*)(bp + r0 * NPAD + c);
            float2 m0 = *(const float2*)(mp + r0 * NPAD + c);
            float2 b1 = *(const float2*)(bp + (r0 + 8) * NPAD + c);
            float2 m1 = *(const float2*)(mp + (r0 + 8) * NPAD + c);
            acc[nt][0] += b0.x + m0.x;
            acc[nt][1] += b0.y + m0.y;
            acc[nt][2] += b1.x + m1.x;
            acc[nt][3] += b1.y + m1.y;
        }
    }

    {
        float mx0 = -3e38f, mx1 = -3e38f;
#pragma unroll
        for (int nt = 0; nt < 8; ++nt) {
            mx0 = fmaxf(mx0, fmaxf(acc[nt][0], acc[nt][1]));
            mx1 = fmaxf(mx1, fmaxf(acc[nt][2], acc[nt][3]));
        }
        mx0 = fmaxf(mx0, __shfl_xor_sync(0xffffffffu, mx0, 1));
        mx0 = fmaxf(mx0, __shfl_xor_sync(0xffffffffu, mx0, 2));
        mx1 = fmaxf(mx1, __shfl_xor_sync(0xffffffffu, mx1, 1));
        mx1 = fmaxf(mx1, __shfl_xor_sync(0xffffffffu, mx1, 2));
        float s0 = 0.f, s1 = 0.f;
#pragma unroll
        for (int nt = 0; nt < 8; ++nt) {
            acc[nt][0] = __expf(acc[nt][0] - mx0); s0 += acc[nt][0];
            acc[nt][1] = __expf(acc[nt][1] - mx0); s0 += acc[nt][1];
            acc[nt][2] = __expf(acc[nt][2] - mx1); s1 += acc[nt][2];
            acc[nt][3] = __expf(acc[nt][3] - mx1); s1 += acc[nt][3];
        }
        s0 += __shfl_xor_sync(0xffffffffu, s0, 1);
        s0 += __shfl_xor_sync(0xffffffffu, s0, 2);
        s1 += __shfl_xor_sync(0xffffffffu, s1, 1);
        s1 += __shfl_xor_sync(0xffffffffu, s1, 2);
        float inv0 = 1.f / s0, inv1 = 1.f / s1;
#pragma unroll
        for (int nt = 0; nt < 8; ++nt) {
            acc[nt][0] *= inv0; acc[nt][1] *= inv0;
            acc[nt][2] *= inv1; acc[nt][3] *= inv1;
        }
    }

    __syncthreads();

    {
        const int c0 = cq << 1;
#pragma unroll
        for (int nt = 0; nt < 8; ++nt) {
            int c = nt * 8 + c0;
            uint2 u0 = make_uint2(f2tf32(acc[nt][0]), f2tf32(acc[nt][1]));
            uint2 u1 = make_uint2(f2tf32(acc[nt][2]), f2tf32(acc[nt][3]));
            *(uint2*)&P[r0 * 68 + c]       = u0;
            *(uint2*)&P[(r0 + 8) * 68 + c] = u1;
        }
    }
    __syncwarp();

    {
        float oacc[4][4];
#pragma unroll
        for (int i = 0; i < 4; ++i)
#pragma unroll
            for (int j = 0; j < 4; ++j) oacc[i][j] = 0.f;
#pragma unroll
        for (int kk = 0; kk < 64; kk += 8) {
            uint32_t a[4];
            a[0] = P[r0 * 68 + kk + cq];
            a[1] = P[(r0 + 8) * 68 + kk + cq];
            a[2] = P[r0 * 68 + kk + 4 + cq];
            a[3] = P[(r0 + 8) * 68 + kk + 4 + cq];
#pragma unroll
            for (int nt = 0; nt < 4; ++nt) {
                uint32_t bfr[2];
                int bc = nt * 8 + (lane >> 2);
                bfr[0] = sV[kk + cq][bc];
                bfr[1] = sV[kk + 4 + cq][bc];
                mma_m16n8k8_tf32(oacc[nt], a, bfr);
            }
        }
        // Store to g_att in A-tiled layout (tf32 bits), rows < 49
        const int c0 = (cq << 1);
#pragma unroll
        for (int nt = 0; nt < 4; ++nt) {
            int cl = h * HDIM + nt * 8 + c0;
            if (r0 < SEQ) {
                int m = b * SEQ + r0;
                g_att[a_tiled_off(m, cl)]     = __uint_as_float(f2tf32(oacc[nt][0]));
                g_att[a_tiled_off(m, cl + 1)] = __uint_as_float(f2tf32(oacc[nt][1]));
            }
            if (r0 + 8 < SEQ) {
                int m = b * SEQ + r0 + 8;
                g_att[a_tiled_off(m, cl)]     = __uint_as_float(f2tf32(oacc[nt][2]));
                g_att[a_tiled_off(m, cl + 1)] = __uint_as_float(f2tf32(oacc[nt][3]));
            }
        }
    }
}

// ---------------------------------------------------------------------------
// Launch
// ---------------------------------------------------------------------------
extern "C" void kernel_launch(void* const* d_in, const int* in_sizes, int n_in,
                              void* d_out, int out_size) {
    const float* x      = (const float*)d_in[0];
    const float* mask   = (const float*)d_in[1];
    const float* qkv_w  = (const float*)d_in[2];
    const float* qkv_b  = (const float*)d_in[3];
    const float* proj_w = (const float*)d_in[4];
    const float* proj_b = (const float*)d_in[5];
    const float* rpb    = (const float*)d_in[6];
    const int*   rel    = (const int*)d_in[7];
    float*       out    = (float*)d_out;

    cudaFuncSetAttribute(gemm_frag<0>, cudaFuncAttributeMaxDynamicSharedMemorySize, GEMM_DSMEM);
    cudaFuncSetAttribute(gemm_frag<1>, cudaFuncAttributeMaxDynamicSharedMemorySize, GEMM_DSMEM);

    // 0) precompute: padded bias/mask, tiled tf32 weights, tiled tf32 x
    biasp_kernel<<<(HEADS * NPAD * NPAD + 255) / 256, 256>>>(rpb, rel);
    maskp_kernel<<<(NW * NPAD * NPAD + 255) / 256, 256>>>(mask);
    cvt_w_kernel<<<(QKV_N / 8 * K8S * 32 + 255) / 256, 256>>>(qkv_w, proj_w);
    cvt_x_kernel<<<(int)(((size_t)(MROWS / 16) * K8S * 32 + 255) / 256), 256>>>(x);
    // 1) QKV GEMM: g_qkv = tf32(x) @ qkv_w + qkv_b (row-major tf32, q-scaled)
    gemm_frag<0><<<dim3(QKV_N / 128, MROWS / 128), 128, GEMM_DSMEM>>>(qkv_b, nullptr);
    // 2) Fused per-(window, head) attention -> g_att (A-tiled tf32)
    attn_kernel<<<dim3(HEADS, B_WIN), 128>>>();
    // 3) Proj GEMM: out = g_att @ proj_w + proj_b
    gemm_frag<1><<<dim3(CDIM / 128, MROWS / 128), 128, GEMM_DSMEM>>>(proj_b, out);
}

// round 9
// speedup vs baseline: 3.3521x; 1.5486x over previous
#include <cuda_runtime.h>
#include <cuda_fp16.h>
#include <cstdint>

// Problem constants
#define B_WIN   4096
#define SEQ     49
#define NPAD    64
#define CDIM    384
#define HEADS   12
#define HDIM    32
#define NW      1024
#define MROWS   (B_WIN * SEQ)        // 200704
#define QKV_N   (3 * CDIM)           // 1152
#define K16S    (CDIM / 16)          // 24 k16-subtiles
#define SCALE_F 0.17677669529663687f // 32^-0.5

// Scratch (static device globals)
__device__ uint32_t g_qkv[(size_t)MROWS * (QKV_N / 2)];        // half2 rows (B_*N, 576)
__device__ uint32_t g_xa[(size_t)(MROWS / 16) * K16S * 128];   // x, A-tiled fp16
__device__ uint32_t g_att_t[(size_t)(MROWS / 16) * K16S * 128];// attn out, A-tiled fp16
__device__ uint32_t g_wqkv_t[(QKV_N / 8) * K16S * 64];         // B-tiled fp16
__device__ uint32_t g_wproj_t[(CDIM / 8) * K16S * 64];
__device__ float    g_biasp[HEADS * NPAD * NPAD];              // padded bias, pad=-1e30
__device__ float    g_maskp[NW * NPAD * NPAD];                 // padded mask, pad=0

// ---------------------------------------------------------------------------
// Helpers
// ---------------------------------------------------------------------------
__device__ __forceinline__ uint32_t h2u(float a, float b) {
    __half2 h = __floats2half2_rn(a, b);
    return *(uint32_t*)&h;
}

__device__ __forceinline__ void mma_f16(float* c, const uint32_t* a, const uint32_t* b) {
    asm volatile(
        "mma.sync.aligned.m16n8k16.row.col.f32.f16.f16.f32 "
        "{%0,%1,%2,%3}, {%4,%5,%6,%7}, {%8,%9}, {%0,%1,%2,%3};\n"
        : "+f"(c[0]), "+f"(c[1]), "+f"(c[2]), "+f"(c[3])
        : "r"(a[0]), "r"(a[1]), "r"(a[2]), "r"(a[3]), "r"(b[0]), "r"(b[1]));
}

__device__ __forceinline__ void cp_async16(void* smem_dst, const void* gmem_src) {
    uint32_t s = (uint32_t)__cvta_generic_to_shared(smem_dst);
    asm volatile("cp.async.cg.shared.global [%0], [%1], 16;\n" :: "r"(s), "l"(gmem_src));
}
__device__ __forceinline__ void cp_async_commit() {
    asm volatile("cp.async.commit_group;\n" ::: "memory");
}
template <int N>
__device__ __forceinline__ void cp_async_wait() {
    asm volatile("cp.async.wait_group %0;\n" :: "n"(N) : "memory");
}

// A-tiled fp16 u32 index for element pair (m, c..c+1), c even, K=384
__device__ __forceinline__ size_t a16_off(int m, int c) {
    int m16 = m >> 4, rr = m & 15, k16 = c >> 4, kc = c & 15;
    int lane = ((rr & 7) << 2) | ((kc & 7) >> 1);
    int w = (rr >> 3) | ((kc >> 3) << 1);
    return (((size_t)m16 * K16S + k16) * 32 + lane) * 4 + w;
}

// ---------------------------------------------------------------------------
// Pre-conversion / padding kernels
// ---------------------------------------------------------------------------
// x (row-major f32) -> g_xa (A-tiled fp16). One thread per (m16,k16,lane).
__global__ void cvt_x_kernel(const float* __restrict__ x) {
    size_t t = (size_t)blockIdx.x * 256 + threadIdx.x;
    const size_t total = (size_t)(MROWS / 16) * K16S * 32;
    if (t >= total) return;
    int lane = (int)(t & 31);
    size_t u = t >> 5;
    int k16 = (int)(u % K16S);
    int m16 = (int)(u / K16S);
    int r = lane >> 2, c = (lane & 3) << 1;
    const float* xp = x + (size_t)(m16 * 16) * CDIM + k16 * 16;
    float2 v00 = *(const float2*)(xp + (size_t)r * CDIM + c);
    float2 v10 = *(const float2*)(xp + (size_t)(r + 8) * CDIM + c);
    float2 v01 = *(const float2*)(xp + (size_t)r * CDIM + c + 8);
    float2 v11 = *(const float2*)(xp + (size_t)(r + 8) * CDIM + c + 8);
    uint4 o;
    o.x = h2u(v00.x, v00.y);
    o.y = h2u(v10.x, v10.y);
    o.z = h2u(v01.x, v01.y);
    o.w = h2u(v11.x, v11.y);
    *(uint4*)(g_xa + t * 4) = o;
}

// Weights -> B-tiled fp16. One thread per (n8,k16,lane), writes 2 u32.
__global__ void cvt_w_kernel(const float* __restrict__ qkv_w, const float* __restrict__ proj_w) {
    int t = blockIdx.x * 256 + threadIdx.x;
    if (t >= (QKV_N / 8) * K16S * 32) return;
    int lane = t & 31;
    int u = t >> 5;
    int k16 = u % K16S;
    int n8 = u / K16S;
    int kk = k16 * 16 + ((lane & 3) << 1);
    int nn = n8 * 8 + (lane >> 2);
    {
        uint2 o;
        o.x = h2u(qkv_w[(size_t)kk * QKV_N + nn],       qkv_w[(size_t)(kk + 1) * QKV_N + nn]);
        o.y = h2u(qkv_w[(size_t)(kk + 8) * QKV_N + nn], qkv_w[(size_t)(kk + 9) * QKV_N + nn]);
        *(uint2*)(g_wqkv_t + (size_t)t * 2) = o;
    }
    if (n8 < CDIM / 8) {
        uint2 o;
        o.x = h2u(proj_w[(size_t)kk * CDIM + nn],       proj_w[(size_t)(kk + 1) * CDIM + nn]);
        o.y = h2u(proj_w[(size_t)(kk + 8) * CDIM + nn], proj_w[(size_t)(kk + 9) * CDIM + nn]);
        *(uint2*)(g_wproj_t + (size_t)((n8 * K16S + k16) * 32 + lane) * 2) = o;
    }
}

__global__ void biasp_kernel(const float* __restrict__ rpb, const int* __restrict__ rel) {
    int t = blockIdx.x * 256 + threadIdx.x;
    if (t < HEADS * NPAD * NPAD) {
        int h = t >> 12, ij = t & 4095, i = ij >> 6, j = ij & 63;
        float v = -1e30f;
        if (i < SEQ && j < SEQ) v = rpb[rel[i * SEQ + j] * HEADS + h];
        g_biasp[t] = v;
    }
}

__global__ void maskp_kernel(const float* __restrict__ mask) {
    int t = blockIdx.x * 256 + threadIdx.x;
    if (t < NW * NPAD * NPAD) {
        int w = t >> 12, ij = t & 4095, i = ij >> 6, j = ij & 63;
        float v = 0.f;
        if (i < SEQ && j < SEQ) v = mask[(size_t)w * SEQ * SEQ + i * SEQ + j];
        g_maskp[t] = v;
    }
}

// ---------------------------------------------------------------------------
// GEMM fp16: C[M,N] = A @ W + bias. BM=128, BN=128, BK=32 (2 k16-steps/chunk),
// 128 threads (2x2 warps, 64x64 each), 3-stage cp.async.
// MODE 0: A = g_xa, W = g_wqkv_t, C = g_qkv (half2, q-scaled)
// MODE 1: A = g_att_t, W = g_wproj_t, C = d_out (f32)
// ---------------------------------------------------------------------------
#define GSTAGE 16384
#define GSM_A(s) ((s) * GSTAGE)
#define GSM_B(s) ((s) * GSTAGE + 8192)
#define GEMM_DSMEM (3 * GSTAGE)

template <int MODE>
__global__ void __launch_bounds__(128)
gemm_f16(const float* __restrict__ bias, float* __restrict__ C_out) {
    const uint32_t* A = (MODE == 0) ? g_xa : g_att_t;
    const uint32_t* W = (MODE == 0) ? g_wqkv_t : g_wproj_t;
    const int    Ntot = (MODE == 0) ? QKV_N : CDIM;

    extern __shared__ __align__(16) uint8_t sm[];

    const int tid  = threadIdx.x;
    const int warp = tid >> 5;
    const int lane = tid & 31;
    const int wm   = warp >> 1;
    const int wn   = warp & 1;
    const int m16base = blockIdx.y * 8;
    const int n8base  = blockIdx.x * 16;
    const int n0 = n8base * 8;

    auto load_chunk = [&](int s, int ch) {
#pragma unroll
        for (int it = 0; it < 4; ++it) {
            int idx = tid + it * 128;            // 0..511
            int u = idx >> 5, i = idx & 31;      // A unit 128 u32
            cp_async16(sm + GSM_A(s) + idx * 16,
                       A + (((size_t)(m16base + (u >> 1)) * K16S + ch * 2 + (u & 1)) * 32 + i) * 4);
        }
#pragma unroll
        for (int it = 0; it < 4; ++it) {
            int idx = tid + it * 128;
            int u = idx >> 4, i16 = idx & 15;    // B unit 64 u32
            cp_async16(sm + GSM_B(s) + idx * 16,
                       W + ((size_t)(n8base + (u >> 1)) * K16S + ch * 2 + (u & 1)) * 64 + i16 * 4);
        }
        cp_async_commit();
    };

    float acc[4][8][4];
#pragma unroll
    for (int i = 0; i < 4; ++i)
#pragma unroll
        for (int j = 0; j < 8; ++j)
#pragma unroll
            for (int q = 0; q < 4; ++q) acc[i][j][q] = 0.f;

    load_chunk(0, 0);
    load_chunk(1, 1);

    const int NCH = K16S / 2;    // 12
    for (int ch = 0; ch < NCH; ++ch) {
        if (ch + 2 < NCH) load_chunk((ch + 2) % 3, ch + 2);
        else              cp_async_commit();
        cp_async_wait<2>();
        __syncthreads();

        const uint32_t* smA = (const uint32_t*)(sm + GSM_A(ch % 3));
        const uint32_t* smB = (const uint32_t*)(sm + GSM_B(ch % 3));
#pragma unroll
        for (int kl = 0; kl < 2; ++kl) {
            uint4 a[4];
#pragma unroll
            for (int mt = 0; mt < 4; ++mt)
                a[mt] = *(const uint4*)&smA[(((wm * 4 + mt) * 2 + kl) * 32 + lane) * 4];
            uint2 b[8];
#pragma unroll
            for (int nt = 0; nt < 8; ++nt)
                b[nt] = *(const uint2*)&smB[(((wn * 8 + nt) * 2 + kl) * 32 + lane) * 2];
#pragma unroll
            for (int mt = 0; mt < 4; ++mt)
#pragma unroll
                for (int nt = 0; nt < 8; ++nt)
                    mma_f16(acc[mt][nt], (const uint32_t*)&a[mt], (const uint32_t*)&b[nt]);
        }
        __syncthreads();
    }

    // Epilogue
    const float qs = (MODE == 0 && n0 < CDIM) ? SCALE_F : 1.f;
    const int rbase = m16base * 16 + wm * 64 + (lane >> 2);
    const int cbase = n0 + wn * 64 + ((lane & 3) << 1);
#pragma unroll
    for (int mt = 0; mt < 4; ++mt) {
        int r = rbase + mt * 16;
#pragma unroll
        for (int nt = 0; nt < 8; ++nt) {
            int cc = cbase + nt * 8;
            float b0 = bias[cc], b1 = bias[cc + 1];
            const float* a4 = acc[mt][nt];
            if (MODE == 0) {
                g_qkv[(size_t)r * (QKV_N / 2) + (cc >> 1)]       = h2u((a4[0] + b0) * qs, (a4[1] + b1) * qs);
                g_qkv[(size_t)(r + 8) * (QKV_N / 2) + (cc >> 1)] = h2u((a4[2] + b0) * qs, (a4[3] + b1) * qs);
            } else {
                *(float2*)(C_out + (size_t)r * Ntot + cc)       = make_float2(a4[0] + b0, a4[1] + b1);
                *(float2*)(C_out + (size_t)(r + 8) * Ntot + cc) = make_float2(a4[2] + b0, a4[3] + b1);
            }
        }
    }
}

// ---------------------------------------------------------------------------
// Fused window attention per (window b, head h), fp16 mma, S-in-registers.
// ---------------------------------------------------------------------------
__global__ void __launch_bounds__(128, 6)
attn_kernel() {
    const int h = blockIdx.x;
    const int b = blockIdx.y;

    __shared__ uint32_t sQK[2560];        // q [64][20], k [64][20]; P aliases [64][36]
    __shared__ uint32_t sVt[32 * 36];     // V^T as half2 (cols j,j+1), stride 36

    const int tid  = threadIdx.x;
    const int warp = tid >> 5;
    const int lane = tid & 31;

    uint32_t* q = sQK;
    uint32_t* k = sQK + 1280;
    uint32_t* P = sQK;                    // alias (2304 <= 2560)

    // zero Vt (pad cols must be finite: P=0 x garbage=NaN otherwise)
    for (int i = tid; i < 32 * 36; i += 128) sVt[i] = 0;

    const __half* base = (const __half*)g_qkv + (size_t)b * SEQ * QKV_N + h * HDIM;
    // q/k rows (zero-padded)
    for (int e = tid; e < 64 * 4; e += 128) {
        int n = e >> 2, part = e & 3;
        uint4 qv = {0, 0, 0, 0}, kv = {0, 0, 0, 0};
        if (n < SEQ) {
            const __half* p = base + (size_t)n * QKV_N + part * 8;
            qv = *(const uint4*)(p);
            kv = *(const uint4*)(p + CDIM);
        }
        *(uint4*)&q[n * 20 + part * 4] = qv;
        *(uint4*)&k[n * 20 + part * 4] = kv;
    }
    // V transposed: Vt_u32[d][jp] = half2{v[2jp][d], v[2jp+1][d]}
    if (tid < 100) {
        int jp = tid >> 2, part = tid & 3;
        const __half* p0 = base + (size_t)(2 * jp) * QKV_N + 2 * CDIM + part * 8;
        uint4 va = *(const uint4*)(p0);
        uint4 vb = {0, 0, 0, 0};
        if (2 * jp + 1 < SEQ) vb = *(const uint4*)(p0 + QKV_N);
        const __half* ha = (const __half*)&va;
        const __half* hb = (const __half*)&vb;
#pragma unroll
        for (int i = 0; i < 8; ++i) {
            __half2 o = __halves2half2(ha[i], hb[i]);
            sVt[(part * 8 + i) * 36 + jp] = *(uint32_t*)&o;
        }
    }
    __syncthreads();

    const int r0 = warp * 16 + (lane >> 2);
    const int cq = lane & 3;

    // ---- QK^T ----
    float acc[8][4];
#pragma unroll
    for (int i = 0; i < 8; ++i)
#pragma unroll
        for (int j = 0; j < 4; ++j) acc[i][j] = 0.f;
#pragma unroll
    for (int s = 0; s < 2; ++s) {
        uint32_t a[4];
        a[0] = q[r0 * 20 + s * 8 + cq];
        a[1] = q[(r0 + 8) * 20 + s * 8 + cq];
        a[2] = q[r0 * 20 + s * 8 + cq + 4];
        a[3] = q[(r0 + 8) * 20 + s * 8 + cq + 4];
#pragma unroll
        for (int nt = 0; nt < 8; ++nt) {
            int bn = nt * 8 + (lane >> 2);
            uint32_t bb[2];
            bb[0] = k[bn * 20 + s * 8 + cq];
            bb[1] = k[bn * 20 + s * 8 + cq + 4];
            mma_f16(acc[nt], a, bb);
        }
    }

    // ---- bias + mask ----
    {
        const float* bp = g_biasp + (size_t)h * (NPAD * NPAD);
        const float* mp = g_maskp + (size_t)(b & (NW - 1)) * (NPAD * NPAD);
        const int c0 = cq << 1;
#pragma unroll
        for (int nt = 0; nt < 8; ++nt) {
            int c = nt * 8 + c0;
            float2 b0 = *(const float2*)(bp + r0 * NPAD + c);
            float2 m0 = *(const float2*)(mp + r0 * NPAD + c);
            float2 b1 = *(const float2*)(bp + (r0 + 8) * NPAD + c);
            float2 m1 = *(const float2*)(mp + (r0 + 8) * NPAD + c);
            acc[nt][0] += b0.x + m0.x;
            acc[nt][1] += b0.y + m0.y;
            acc[nt][2] += b1.x + m1.x;
            acc[nt][3] += b1.y + m1.y;
        }
    }

    // ---- row softmax (quad shuffles) ----
    {
        float mx0 = -3e38f, mx1 = -3e38f;
#pragma unroll
        for (int nt = 0; nt < 8; ++nt) {
            mx0 = fmaxf(mx0, fmaxf(acc[nt][0], acc[nt][1]));
            mx1 = fmaxf(mx1, fmaxf(acc[nt][2], acc[nt][3]));
        }
        mx0 = fmaxf(mx0, __shfl_xor_sync(0xffffffffu, mx0, 1));
        mx0 = fmaxf(mx0, __shfl_xor_sync(0xffffffffu, mx0, 2));
        mx1 = fmaxf(mx1, __shfl_xor_sync(0xffffffffu, mx1, 1));
        mx1 = fmaxf(mx1, __shfl_xor_sync(0xffffffffu, mx1, 2));
        float s0 = 0.f, s1 = 0.f;
#pragma unroll
        for (int nt = 0; nt < 8; ++nt) {
            acc[nt][0] = __expf(acc[nt][0] - mx0); s0 += acc[nt][0];
            acc[nt][1] = __expf(acc[nt][1] - mx0); s0 += acc[nt][1];
            acc[nt][2] = __expf(acc[nt][2] - mx1); s1 += acc[nt][2];
            acc[nt][3] = __expf(acc[nt][3] - mx1); s1 += acc[nt][3];
        }
        s0 += __shfl_xor_sync(0xffffffffu, s0, 1);
        s0 += __shfl_xor_sync(0xffffffffu, s0, 2);
        s1 += __shfl_xor_sync(0xffffffffu, s1, 1);
        s1 += __shfl_xor_sync(0xffffffffu, s1, 2);
        float inv0 = 1.f / s0, inv1 = 1.f / s1;
#pragma unroll
        for (int nt = 0; nt < 8; ++nt) {
            acc[nt][0] *= inv0; acc[nt][1] *= inv0;
            acc[nt][2] *= inv1; acc[nt][3] *= inv1;
        }
    }

    __syncthreads();   // all warps done reading q/k before P (alias) write

    // ---- write P (fp16 half2) ----
#pragma unroll
    for (int nt = 0; nt < 8; ++nt) {
        P[r0 * 36 + nt * 4 + cq]       = h2u(acc[nt][0], acc[nt][1]);
        P[(r0 + 8) * 36 + nt * 4 + cq] = h2u(acc[nt][2], acc[nt][3]);
    }
    __syncwarp();

    // ---- O = P V ----
    {
        float oacc[4][4];
#pragma unroll
        for (int i = 0; i < 4; ++i)
#pragma unroll
            for (int j = 0; j < 4; ++j) oacc[i][j] = 0.f;
#pragma unroll
        for (int s = 0; s < 4; ++s) {
            uint32_t a[4];
            a[0] = P[r0 * 36 + s * 8 + cq];
            a[1] = P[(r0 + 8) * 36 + s * 8 + cq];
            a[2] = P[r0 * 36 + s * 8 + cq + 4];
            a[3] = P[(r0 + 8) * 36 + s * 8 + cq + 4];
#pragma unroll
            for (int nt = 0; nt < 4; ++nt) {
                int bn = nt * 8 + (lane >> 2);
                uint32_t bb[2];
                bb[0] = sVt[bn * 36 + s * 8 + cq];
                bb[1] = sVt[bn * 36 + s * 8 + cq + 4];
                mma_f16(oacc[nt], a, bb);
            }
        }
        // store O -> g_att_t (A-tiled fp16)
        const int c0 = cq << 1;
#pragma unroll
        for (int nt = 0; nt < 4; ++nt) {
            int c = h * HDIM + nt * 8 + c0;
            if (r0 < SEQ)
                g_att_t[a16_off(b * SEQ + r0, c)]     = h2u(oacc[nt][0], oacc[nt][1]);
            if (r0 + 8 < SEQ)
                g_att_t[a16_off(b * SEQ + r0 + 8, c)] = h2u(oacc[nt][2], oacc[nt][3]);
        }
    }
}

// ---------------------------------------------------------------------------
// Launch
// ---------------------------------------------------------------------------
extern "C" void kernel_launch(void* const* d_in, const int* in_sizes, int n_in,
                              void* d_out, int out_size) {
    const float* x      = (const float*)d_in[0];
    const float* mask   = (const float*)d_in[1];
    const float* qkv_w  = (const float*)d_in[2];
    const float* qkv_b  = (const float*)d_in[3];
    const float* proj_w = (const float*)d_in[4];
    const float* proj_b = (const float*)d_in[5];
    const float* rpb    = (const float*)d_in[6];
    const int*   rel    = (const int*)d_in[7];
    float*       out    = (float*)d_out;

    cudaFuncSetAttribute(gemm_f16<0>, cudaFuncAttributeMaxDynamicSharedMemorySize, GEMM_DSMEM);
    cudaFuncSetAttribute(gemm_f16<1>, cudaFuncAttributeMaxDynamicSharedMemorySize, GEMM_DSMEM);

    // 0) precompute: padded bias/mask, tiled fp16 weights, tiled fp16 x
    biasp_kernel<<<(HEADS * NPAD * NPAD + 255) / 256, 256>>>(rpb, rel);
    maskp_kernel<<<(NW * NPAD * NPAD + 255) / 256, 256>>>(mask);
    cvt_w_kernel<<<((QKV_N / 8) * K16S * 32 + 255) / 256, 256>>>(qkv_w, proj_w);
    cvt_x_kernel<<<(int)(((size_t)(MROWS / 16) * K16S * 32 + 255) / 256), 256>>>(x);
    // 1) QKV GEMM: g_qkv = f16(x) @ f16(qkv_w) + qkv_b (half2 out, q-scaled)
    gemm_f16<0><<<dim3(QKV_N / 128, MROWS / 128), 128, GEMM_DSMEM>>>(qkv_b, nullptr);
    // 2) Fused per-(window, head) attention -> g_att_t (A-tiled fp16)
    attn_kernel<<<dim3(HEADS, B_WIN), 128>>>();
    // 3) Proj GEMM: out = attn @ f16(proj_w) + proj_b
    gemm_f16<1><<<dim3(CDIM / 128, MROWS / 128), 128, GEMM_DSMEM>>>(proj_b, out);
}

// round 10
// speedup vs baseline: 3.7820x; 1.1283x over previous
#include <cuda_runtime.h>
#include <cuda_fp16.h>
#include <cstdint>

// Problem constants
#define B_WIN   4096
#define SEQ     49
#define NPAD    64
#define CDIM    384
#define HEADS   12
#define HDIM    32
#define NW      1024
#define MROWS   (B_WIN * SEQ)        // 200704
#define QKV_N   (3 * CDIM)           // 1152
#define QKV_U   (QKV_N / 2)          // 576 u32 per row
#define K16S    (CDIM / 16)          // 24 k16-subtiles
#define SCALE_F 0.17677669529663687f // 32^-0.5

// Scratch (static device globals)
__device__ uint32_t g_qkv[(size_t)MROWS * QKV_U];              // half2 rows (B_*N, 576)
__device__ uint32_t g_xa[(size_t)(MROWS / 16) * K16S * 128];   // x, A-tiled fp16
__device__ uint32_t g_att_t[(size_t)(MROWS / 16) * K16S * 128];// attn out, A-tiled fp16
__device__ uint32_t g_wqkv_t[(QKV_N / 8) * K16S * 64];         // B-tiled fp16
__device__ uint32_t g_wproj_t[(CDIM / 8) * K16S * 64];
__device__ uint32_t g_biasp_h[HEADS * 2048];                   // fp16 padded bias (12,64,64), pad=-60000
__device__ uint32_t g_maskp_h[NW * 2048];                      // fp16 padded mask (1024,64,64), pad=0

// ---------------------------------------------------------------------------
// Helpers
// ---------------------------------------------------------------------------
__device__ __forceinline__ uint32_t h2u(float a, float b) {
    __half2 h = __floats2half2_rn(a, b);
    return *(uint32_t*)&h;
}

__device__ __forceinline__ void mma_f16(float* c, const uint32_t* a, const uint32_t* b) {
    asm volatile(
        "mma.sync.aligned.m16n8k16.row.col.f32.f16.f16.f32 "
        "{%0,%1,%2,%3}, {%4,%5,%6,%7}, {%8,%9}, {%0,%1,%2,%3};\n"
        : "+f"(c[0]), "+f"(c[1]), "+f"(c[2]), "+f"(c[3])
        : "r"(a[0]), "r"(a[1]), "r"(a[2]), "r"(a[3]), "r"(b[0]), "r"(b[1]));
}

__device__ __forceinline__ void cp_async16(void* smem_dst, const void* gmem_src) {
    uint32_t s = (uint32_t)__cvta_generic_to_shared(smem_dst);
    asm volatile("cp.async.cg.shared.global [%0], [%1], 16;\n" :: "r"(s), "l"(gmem_src));
}
__device__ __forceinline__ void cp_async16z(void* smem_dst, const void* gmem_src, uint32_t src_sz) {
    uint32_t s = (uint32_t)__cvta_generic_to_shared(smem_dst);
    asm volatile("cp.async.cg.shared.global [%0], [%1], 16, %2;\n" :: "r"(s), "l"(gmem_src), "r"(src_sz));
}
__device__ __forceinline__ void cp_async_commit() {
    asm volatile("cp.async.commit_group;\n" ::: "memory");
}
template <int N>
__device__ __forceinline__ void cp_async_wait() {
    asm volatile("cp.async.wait_group %0;\n" :: "n"(N) : "memory");
}

// A-tiled fp16 u32 index for element pair (m, c..c+1), c even, K=384
__device__ __forceinline__ size_t a16_off(int m, int c) {
    int m16 = m >> 4, rr = m & 15, k16 = c >> 4, kc = c & 15;
    int lane = ((rr & 7) << 2) | ((kc & 7) >> 1);
    int w = (rr >> 3) | ((kc >> 3) << 1);
    return (((size_t)m16 * K16S + k16) * 32 + lane) * 4 + w;
}

// ---------------------------------------------------------------------------
// Merged prep: fp16 mask table, fp16 bias table, B-tiled weights
// ---------------------------------------------------------------------------
__global__ void prep_kernel(const float* __restrict__ mask,
                            const float* __restrict__ rpb, const int* __restrict__ rel,
                            const float* __restrict__ qkv_w, const float* __restrict__ proj_w) {
    int t = blockIdx.x * 256 + threadIdx.x;
    // 1) mask fp16 padded: u32 count = NW*2048
    if (t < NW * 2048) {
        int w = t >> 11, ij2 = t & 2047, i = ij2 >> 5, jp = ij2 & 31;
        int j0 = 2 * jp;
        float a = 0.f, b2 = 0.f;
        if (i < SEQ && j0 < SEQ)     a  = mask[(size_t)w * SEQ * SEQ + i * SEQ + j0];
        if (i < SEQ && j0 + 1 < SEQ) b2 = mask[(size_t)w * SEQ * SEQ + i * SEQ + j0 + 1];
        g_maskp_h[t] = h2u(a, b2);
    }
    // 2) bias fp16 padded: u32 count = 12*2048
    if (t < HEADS * 2048) {
        int h = t >> 11, ij2 = t & 2047, i = ij2 >> 5, jp = ij2 & 31;
        int j0 = 2 * jp;
        float a = -60000.f, b2 = -60000.f;
        if (i < SEQ && j0 < SEQ)     a  = rpb[rel[i * SEQ + j0] * HEADS + h];
        if (i < SEQ && j0 + 1 < SEQ) b2 = rpb[rel[i * SEQ + j0 + 1] * HEADS + h];
        g_biasp_h[t] = h2u(a, b2);
    }
    // 3) weights B-tiled fp16
    if (t < (QKV_N / 8) * K16S * 32) {
        int lane = t & 31;
        int u = t >> 5;
        int k16 = u % K16S;
        int n8 = u / K16S;
        int kk = k16 * 16 + ((lane & 3) << 1);
        int nn = n8 * 8 + (lane >> 2);
        {
            uint2 o;
            o.x = h2u(qkv_w[(size_t)kk * QKV_N + nn],       qkv_w[(size_t)(kk + 1) * QKV_N + nn]);
            o.y = h2u(qkv_w[(size_t)(kk + 8) * QKV_N + nn], qkv_w[(size_t)(kk + 9) * QKV_N + nn]);
            *(uint2*)(g_wqkv_t + (size_t)t * 2) = o;
        }
        if (n8 < CDIM / 8) {
            uint2 o;
            o.x = h2u(proj_w[(size_t)kk * CDIM + nn],       proj_w[(size_t)(kk + 1) * CDIM + nn]);
            o.y = h2u(proj_w[(size_t)(kk + 8) * CDIM + nn], proj_w[(size_t)(kk + 9) * CDIM + nn]);
            *(uint2*)(g_wproj_t + (size_t)((n8 * K16S + k16) * 32 + lane) * 2) = o;
        }
    }
}

// x (row-major f32) -> g_xa (A-tiled fp16)
__global__ void cvt_x_kernel(const float* __restrict__ x) {
    size_t t = (size_t)blockIdx.x * 256 + threadIdx.x;
    const size_t total = (size_t)(MROWS / 16) * K16S * 32;
    if (t >= total) return;
    int lane = (int)(t & 31);
    size_t u = t >> 5;
    int k16 = (int)(u % K16S);
    int m16 = (int)(u / K16S);
    int r = lane >> 2, c = (lane & 3) << 1;
    const float* xp = x + (size_t)(m16 * 16) * CDIM + k16 * 16;
    float2 v00 = *(const float2*)(xp + (size_t)r * CDIM + c);
    float2 v10 = *(const float2*)(xp + (size_t)(r + 8) * CDIM + c);
    float2 v01 = *(const float2*)(xp + (size_t)r * CDIM + c + 8);
    float2 v11 = *(const float2*)(xp + (size_t)(r + 8) * CDIM + c + 8);
    uint4 o;
    o.x = h2u(v00.x, v00.y);
    o.y = h2u(v10.x, v10.y);
    o.z = h2u(v01.x, v01.y);
    o.w = h2u(v11.x, v11.y);
    *(uint4*)(g_xa + t * 4) = o;
}

// ---------------------------------------------------------------------------
// GEMM fp16 (unchanged from R9): BM=128, BN=128, BK=32, 128 thr, 3-stage.
// ---------------------------------------------------------------------------
#define GSTAGE 16384
#define GSM_A(s) ((s) * GSTAGE)
#define GSM_B(s) ((s) * GSTAGE + 8192)
#define GEMM_DSMEM (3 * GSTAGE)

template <int MODE>
__global__ void __launch_bounds__(128)
gemm_f16(const float* __restrict__ bias, float* __restrict__ C_out) {
    const uint32_t* A = (MODE == 0) ? g_xa : g_att_t;
    const uint32_t* W = (MODE == 0) ? g_wqkv_t : g_wproj_t;
    const int    Ntot = (MODE == 0) ? QKV_N : CDIM;

    extern __shared__ __align__(16) uint8_t sm[];

    const int tid  = threadIdx.x;
    const int warp = tid >> 5;
    const int lane = tid & 31;
    const int wm   = warp >> 1;
    const int wn   = warp & 1;
    const int m16base = blockIdx.y * 8;
    const int n8base  = blockIdx.x * 16;
    const int n0 = n8base * 8;

    auto load_chunk = [&](int s, int ch) {
#pragma unroll
        for (int it = 0; it < 4; ++it) {
            int idx = tid + it * 128;
            int u = idx >> 5, i = idx & 31;
            cp_async16(sm + GSM_A(s) + idx * 16,
                       A + (((size_t)(m16base + (u >> 1)) * K16S + ch * 2 + (u & 1)) * 32 + i) * 4);
        }
#pragma unroll
        for (int it = 0; it < 4; ++it) {
            int idx = tid + it * 128;
            int u = idx >> 4, i16 = idx & 15;
            cp_async16(sm + GSM_B(s) + idx * 16,
                       W + ((size_t)(n8base + (u >> 1)) * K16S + ch * 2 + (u & 1)) * 64 + i16 * 4);
        }
        cp_async_commit();
    };

    float acc[4][8][4];
#pragma unroll
    for (int i = 0; i < 4; ++i)
#pragma unroll
        for (int j = 0; j < 8; ++j)
#pragma unroll
            for (int q = 0; q < 4; ++q) acc[i][j][q] = 0.f;

    load_chunk(0, 0);
    load_chunk(1, 1);

    const int NCH = K16S / 2;    // 12
    for (int ch = 0; ch < NCH; ++ch) {
        if (ch + 2 < NCH) load_chunk((ch + 2) % 3, ch + 2);
        else              cp_async_commit();
        cp_async_wait<2>();
        __syncthreads();

        const uint32_t* smA = (const uint32_t*)(sm + GSM_A(ch % 3));
        const uint32_t* smB = (const uint32_t*)(sm + GSM_B(ch % 3));
#pragma unroll
        for (int kl = 0; kl < 2; ++kl) {
            uint4 a[4];
#pragma unroll
            for (int mt = 0; mt < 4; ++mt)
                a[mt] = *(const uint4*)&smA[(((wm * 4 + mt) * 2 + kl) * 32 + lane) * 4];
            uint2 b[8];
#pragma unroll
            for (int nt = 0; nt < 8; ++nt)
                b[nt] = *(const uint2*)&smB[(((wn * 8 + nt) * 2 + kl) * 32 + lane) * 2];
#pragma unroll
            for (int mt = 0; mt < 4; ++mt)
#pragma unroll
                for (int nt = 0; nt < 8; ++nt)
                    mma_f16(acc[mt][nt], (const uint32_t*)&a[mt], (const uint32_t*)&b[nt]);
        }
        __syncthreads();
    }

    const float qs = (MODE == 0 && n0 < CDIM) ? SCALE_F : 1.f;
    const int rbase = m16base * 16 + wm * 64 + (lane >> 2);
    const int cbase = n0 + wn * 64 + ((lane & 3) << 1);
#pragma unroll
    for (int mt = 0; mt < 4; ++mt) {
        int r = rbase + mt * 16;
#pragma unroll
        for (int nt = 0; nt < 8; ++nt) {
            int cc = cbase + nt * 8;
            float b0 = bias[cc], b1 = bias[cc + 1];
            const float* a4 = acc[mt][nt];
            if (MODE == 0) {
                g_qkv[(size_t)r * QKV_U + (cc >> 1)]       = h2u((a4[0] + b0) * qs, (a4[1] + b1) * qs);
                g_qkv[(size_t)(r + 8) * QKV_U + (cc >> 1)] = h2u((a4[2] + b0) * qs, (a4[3] + b1) * qs);
            } else {
                *(float2*)(C_out + (size_t)r * Ntot + cc)       = make_float2(a4[0] + b0, a4[1] + b1);
                *(float2*)(C_out + (size_t)(r + 8) * Ntot + cc) = make_float2(a4[2] + b0, a4[3] + b1);
            }
        }
    }
}

// ---------------------------------------------------------------------------
// Window attention: one block per window b, loops 12 heads, double-buffered
// cp.async prefetch of q/k/v, mask in smem (fp16), bias fp16 from L2.
// ---------------------------------------------------------------------------
#define ATT_STAGE 3840   // q 1280 | k 1280 | v 1280 (u32)

__global__ void __launch_bounds__(128)
attn_kernel() {
    const int b = blockIdx.x;

    __shared__ uint32_t sS[2][ATT_STAGE];
    __shared__ uint32_t sVt[32 * 36];
    __shared__ uint32_t sMask[64 * 36];

    const int tid  = threadIdx.x;
    const int warp = tid >> 5;
    const int lane = tid & 31;

    const uint32_t* gq = g_qkv + (size_t)b * SEQ * QKV_U;

    auto load_head = [&](int h, int buf) {
#pragma unroll
        for (int i = 0; i < 6; ++i) {
            int idx = tid + i * 128;                 // 0..767
            int which = idx >> 8;                    // 0=q 1=k 2=v
            int n = (idx >> 2) & 63;
            int part = idx & 3;
            int nc = (n < SEQ) ? n : 0;
            const uint32_t* src = gq + (size_t)nc * QKV_U + h * 16 + which * 192 + part * 4;
            cp_async16z(&sS[buf][which * 1280 + n * 20 + part * 4], src, (n < SEQ) ? 16u : 0u);
        }
        cp_async_commit();
    };

    // mask (8KB fp16) — grouped with head 0's loads
    {
        const uint32_t* mp = g_maskp_h + (size_t)(b & (NW - 1)) * 2048;
#pragma unroll
        for (int i = 0; i < 4; ++i) {
            int idx = tid + i * 128;                 // 0..511 chunks
            int row = idx >> 3, part = idx & 7;
            cp_async16(&sMask[row * 36 + part * 4], mp + row * 32 + part * 4);
        }
    }
    load_head(0, 0);      // commit: group = {mask, head0}
    load_head(1, 1);      // group 2

    const int r0 = warp * 16 + (lane >> 2);
    const int cq = lane & 31 & 3;
    const int c0 = cq << 1;

    for (int h = 0; h < HEADS; ++h) {
        const int cur = h & 1;
        cp_async_wait<1>();
        __syncthreads();

        // transpose v (staging) -> sVt[d][jp]
        {
            const uint32_t* v = &sS[cur][2560];
            int jp = warp * 8 + (lane >> 2);
#pragma unroll
            for (int i = 0; i < 4; ++i) {
                int du = (lane & 3) + i * 4;
                uint32_t a = v[(2 * jp) * 20 + du];
                uint32_t c = v[(2 * jp + 1) * 20 + du];
                sVt[(2 * du) * 36 + jp]     = __byte_perm(a, c, 0x5410);
                sVt[(2 * du + 1) * 36 + jp] = __byte_perm(a, c, 0x7632);
            }
        }
        __syncthreads();

        const uint32_t* q = &sS[cur][0];
        const uint32_t* k = &sS[cur][1280];
        uint32_t* P = &sS[cur][0];          // alias after QK reads complete

        // ---- QK^T ----
        float acc[8][4];
#pragma unroll
        for (int i = 0; i < 8; ++i)
#pragma unroll
            for (int j = 0; j < 4; ++j) acc[i][j] = 0.f;
#pragma unroll
        for (int s = 0; s < 2; ++s) {
            uint32_t a[4];
            a[0] = q[r0 * 20 + s * 8 + cq];
            a[1] = q[(r0 + 8) * 20 + s * 8 + cq];
            a[2] = q[r0 * 20 + s * 8 + cq + 4];
            a[3] = q[(r0 + 8) * 20 + s * 8 + cq + 4];
#pragma unroll
            for (int nt = 0; nt < 8; ++nt) {
                int bn = nt * 8 + (lane >> 2);
                uint32_t bb[2];
                bb[0] = k[bn * 20 + s * 8 + cq];
                bb[1] = k[bn * 20 + s * 8 + cq + 4];
                mma_f16(acc[nt], a, bb);
            }
        }

        // ---- bias (fp16, gmem) + mask (fp16, smem) ----
        {
            const __half* bp = (const __half*)g_biasp_h + h * 4096;
#pragma unroll
            for (int nt = 0; nt < 8; ++nt) {
                int c = nt * 8 + c0;                 // half col
                uint32_t bu0 = *(const uint32_t*)(bp + r0 * 64 + c);
                uint32_t bu1 = *(const uint32_t*)(bp + (r0 + 8) * 64 + c);
                uint32_t mu0 = sMask[r0 * 36 + nt * 4 + cq];
                uint32_t mu1 = sMask[(r0 + 8) * 36 + nt * 4 + cq];
                float2 fb0 = __half22float2(*(__half2*)&bu0);
                float2 fb1 = __half22float2(*(__half2*)&bu1);
                float2 fm0 = __half22float2(*(__half2*)&mu0);
                float2 fm1 = __half22float2(*(__half2*)&mu1);
                acc[nt][0] += fb0.x + fm0.x;
                acc[nt][1] += fb0.y + fm0.y;
                acc[nt][2] += fb1.x + fm1.x;
                acc[nt][3] += fb1.y + fm1.y;
            }
        }

        // ---- row softmax (quad shuffles) ----
        {
            float mx0 = -3e38f, mx1 = -3e38f;
#pragma unroll
            for (int nt = 0; nt < 8; ++nt) {
                mx0 = fmaxf(mx0, fmaxf(acc[nt][0], acc[nt][1]));
                mx1 = fmaxf(mx1, fmaxf(acc[nt][2], acc[nt][3]));
            }
            mx0 = fmaxf(mx0, __shfl_xor_sync(0xffffffffu, mx0, 1));
            mx0 = fmaxf(mx0, __shfl_xor_sync(0xffffffffu, mx0, 2));
            mx1 = fmaxf(mx1, __shfl_xor_sync(0xffffffffu, mx1, 1));
            mx1 = fmaxf(mx1, __shfl_xor_sync(0xffffffffu, mx1, 2));
            float s0 = 0.f, s1 = 0.f;
#pragma unroll
            for (int nt = 0; nt < 8; ++nt) {
                acc[nt][0] = __expf(acc[nt][0] - mx0); s0 += acc[nt][0];
                acc[nt][1] = __expf(acc[nt][1] - mx0); s0 += acc[nt][1];
                acc[nt][2] = __expf(acc[nt][2] - mx1); s1 += acc[nt][2];
                acc[nt][3] = __expf(acc[nt][3] - mx1); s1 += acc[nt][3];
            }
            s0 += __shfl_xor_sync(0xffffffffu, s0, 1);
            s0 += __shfl_xor_sync(0xffffffffu, s0, 2);
            s1 += __shfl_xor_sync(0xffffffffu, s1, 1);
            s1 += __shfl_xor_sync(0xffffffffu, s1, 2);
            float inv0 = 1.f / s0, inv1 = 1.f / s1;
#pragma unroll
            for (int nt = 0; nt < 8; ++nt) {
                acc[nt][0] *= inv0; acc[nt][1] *= inv0;
                acc[nt][2] *= inv1; acc[nt][3] *= inv1;
            }
        }

        __syncthreads();   // all warps done reading q/k before alias write

        // ---- write P (fp16, stride 36) ----
#pragma unroll
        for (int nt = 0; nt < 8; ++nt) {
            P[r0 * 36 + nt * 4 + cq]       = h2u(acc[nt][0], acc[nt][1]);
            P[(r0 + 8) * 36 + nt * 4 + cq] = h2u(acc[nt][2], acc[nt][3]);
        }
        __syncwarp();

        // ---- O = P V ----
        {
            float oacc[4][4];
#pragma unroll
            for (int i = 0; i < 4; ++i)
#pragma unroll
                for (int j = 0; j < 4; ++j) oacc[i][j] = 0.f;
#pragma unroll
            for (int s = 0; s < 4; ++s) {
                uint32_t a[4];
                a[0] = P[r0 * 36 + s * 8 + cq];
                a[1] = P[(r0 + 8) * 36 + s * 8 + cq];
                a[2] = P[r0 * 36 + s * 8 + cq + 4];
                a[3] = P[(r0 + 8) * 36 + s * 8 + cq + 4];
#pragma unroll
                for (int nt = 0; nt < 4; ++nt) {
                    int bn = nt * 8 + (lane >> 2);
                    uint32_t bb[2];
                    bb[0] = sVt[bn * 36 + s * 8 + cq];
                    bb[1] = sVt[bn * 36 + s * 8 + cq + 4];
                    mma_f16(oacc[nt], a, bb);
                }
            }
#pragma unroll
            for (int nt = 0; nt < 4; ++nt) {
                int c = h * HDIM + nt * 8 + c0;
                if (r0 < SEQ)
                    g_att_t[a16_off(b * SEQ + r0, c)]     = h2u(oacc[nt][0], oacc[nt][1]);
                if (r0 + 8 < SEQ)
                    g_att_t[a16_off(b * SEQ + r0 + 8, c)] = h2u(oacc[nt][2], oacc[nt][3]);
            }
        }

        __syncthreads();   // cur buffer fully consumed
        if (h + 2 < HEADS) load_head(h + 2, cur);   // commits
        else               cp_async_commit();       // keep group accounting
    }
}

// ---------------------------------------------------------------------------
// Launch
// ---------------------------------------------------------------------------
extern "C" void kernel_launch(void* const* d_in, const int* in_sizes, int n_in,
                              void* d_out, int out_size) {
    const float* x      = (const float*)d_in[0];
    const float* mask   = (const float*)d_in[1];
    const float* qkv_w  = (const float*)d_in[2];
    const float* qkv_b  = (const float*)d_in[3];
    const float* proj_w = (const float*)d_in[4];
    const float* proj_b = (const float*)d_in[5];
    const float* rpb    = (const float*)d_in[6];
    const int*   rel    = (const int*)d_in[7];
    float*       out    = (float*)d_out;

    cudaFuncSetAttribute(gemm_f16<0>, cudaFuncAttributeMaxDynamicSharedMemorySize, GEMM_DSMEM);
    cudaFuncSetAttribute(gemm_f16<1>, cudaFuncAttributeMaxDynamicSharedMemorySize, GEMM_DSMEM);

    // 0) prep (fp16 mask/bias tables + tiled weights), x cvt
    prep_kernel<<<(NW * 2048 + 255) / 256, 256>>>(mask, rpb, rel, qkv_w, proj_w);
    cvt_x_kernel<<<(int)(((size_t)(MROWS / 16) * K16S * 32 + 255) / 256), 256>>>(x);
    // 1) QKV GEMM
    gemm_f16<0><<<dim3(QKV_N / 128, MROWS / 128), 128, GEMM_DSMEM>>>(qkv_b, nullptr);
    // 2) Attention (one block per window, 12 heads, double-buffered)
    attn_kernel<<<B_WIN, 128>>>();
    // 3) Proj GEMM
    gemm_f16<1><<<dim3(CDIM / 128, MROWS / 128), 128, GEMM_DSMEM>>>(proj_b, out);
}

// round 12
// speedup vs baseline: 4.1813x; 1.1056x over previous
#include <cuda_runtime.h>
#include <cuda_fp16.h>
#include <cstdint>

// Problem constants
#define B_WIN   4096
#define SEQ     49
#define NPAD    64
#define CDIM    384
#define HEADS   12
#define HDIM    32
#define NW      1024
#define MROWS   (B_WIN * SEQ)        // 200704
#define QKV_N   (3 * CDIM)           // 1152
#define QKV_U   (QKV_N / 2)          // 576 u32 per row
#define K16S    (CDIM / 16)          // 24 k16-subtiles
#define SCALE_F 0.17677669529663687f // 32^-0.5

// Scratch (static device globals)
__device__ uint32_t g_qkv[(size_t)MROWS * QKV_U];              // half2 rows (B_*N, 576)
__device__ uint32_t g_xa[(size_t)(MROWS / 16) * K16S * 128];   // x, A-tiled fp16
__device__ uint32_t g_att_t[(size_t)(MROWS / 16) * K16S * 128];// attn out, A-tiled fp16
__device__ uint32_t g_wqkv_t[(QKV_N / 8) * K16S * 64];         // B-tiled fp16
__device__ uint32_t g_wproj_t[(CDIM / 8) * K16S * 64];
__device__ uint32_t g_biasp_h[HEADS * 2048];                   // fp16 bias, permuted [h][i][w32]
__device__ uint32_t g_maskp_h[NW * 2048];                      // fp16 mask, permuted [w][i][w32]

// ---------------------------------------------------------------------------
// Helpers
// ---------------------------------------------------------------------------
__device__ __forceinline__ uint32_t h2u(float a, float b) {
    __half2 h = __floats2half2_rn(a, b);
    return *(uint32_t*)&h;
}

__device__ __forceinline__ void mma_f16(float* c, const uint32_t* a, const uint32_t* b) {
    asm volatile(
        "mma.sync.aligned.m16n8k16.row.col.f32.f16.f16.f32 "
        "{%0,%1,%2,%3}, {%4,%5,%6,%7}, {%8,%9}, {%0,%1,%2,%3};\n"
        : "+f"(c[0]), "+f"(c[1]), "+f"(c[2]), "+f"(c[3])
        : "r"(a[0]), "r"(a[1]), "r"(a[2]), "r"(a[3]), "r"(b[0]), "r"(b[1]));
}

__device__ __forceinline__ void ldsm_x4(uint32_t* r, uint32_t addr) {
    asm volatile("ldmatrix.sync.aligned.m8n8.x4.shared.b16 {%0,%1,%2,%3}, [%4];"
                 : "=r"(r[0]), "=r"(r[1]), "=r"(r[2]), "=r"(r[3]) : "r"(addr));
}
__device__ __forceinline__ void ldsm_x4_t(uint32_t* r, uint32_t addr) {
    asm volatile("ldmatrix.sync.aligned.m8n8.x4.trans.shared.b16 {%0,%1,%2,%3}, [%4];"
                 : "=r"(r[0]), "=r"(r[1]), "=r"(r[2]), "=r"(r[3]) : "r"(addr));
}
__device__ __forceinline__ uint32_t sm2u(const void* p) {
    return (uint32_t)__cvta_generic_to_shared(p);
}

__device__ __forceinline__ void cp_async16(void* smem_dst, const void* gmem_src) {
    uint32_t s = (uint32_t)__cvta_generic_to_shared(smem_dst);
    asm volatile("cp.async.cg.shared.global [%0], [%1], 16;\n" :: "r"(s), "l"(gmem_src));
}
__device__ __forceinline__ void cp_async16z(void* smem_dst, const void* gmem_src, uint32_t src_sz) {
    uint32_t s = (uint32_t)__cvta_generic_to_shared(smem_dst);
    asm volatile("cp.async.cg.shared.global [%0], [%1], 16, %2;\n" :: "r"(s), "l"(gmem_src), "r"(src_sz));
}
__device__ __forceinline__ void cp_async_commit() {
    asm volatile("cp.async.commit_group;\n" ::: "memory");
}
template <int N>
__device__ __forceinline__ void cp_async_wait() {
    asm volatile("cp.async.wait_group %0;\n" :: "n"(N) : "memory");
}

// A-tiled fp16 u32 index for element pair (m, c..c+1), c even, K=384
__device__ __forceinline__ size_t a16_off(int m, int c) {
    int m16 = m >> 4, rr = m & 15, k16 = c >> 4, kc = c & 15;
    int lane = ((rr & 7) << 2) | ((kc & 7) >> 1);
    int w = (rr >> 3) | ((kc >> 3) << 1);
    return (((size_t)m16 * K16S + k16) * 32 + lane) * 4 + w;
}

// ---------------------------------------------------------------------------
// Merged prep: permuted fp16 mask/bias tables, B-tiled weights
// Permutation: word w32 in [0,32) holds j-pair jp = (w32&7)*4 + (w32>>3),
// i.e. j0 = 8*(w32&7) + 2*(w32>>3)  -> per-thread contiguous 8 words.
// ---------------------------------------------------------------------------
__global__ void prep_kernel(const float* __restrict__ mask,
                            const float* __restrict__ rpb, const int* __restrict__ rel,
                            const float* __restrict__ qkv_w, const float* __restrict__ proj_w) {
    int t = blockIdx.x * 256 + threadIdx.x;
    if (t < NW * 2048) {
        int w = t >> 11, ij2 = t & 2047, i = ij2 >> 5, w32 = ij2 & 31;
        int j0 = 8 * (w32 & 7) + 2 * (w32 >> 3);
        float a = 0.f, b2 = 0.f;
        if (i < SEQ && j0 < SEQ)     a  = mask[(size_t)w * SEQ * SEQ + i * SEQ + j0];
        if (i < SEQ && j0 + 1 < SEQ) b2 = mask[(size_t)w * SEQ * SEQ + i * SEQ + j0 + 1];
        g_maskp_h[t] = h2u(a, b2);
    }
    if (t < HEADS * 2048) {
        int h = t >> 11, ij2 = t & 2047, i = ij2 >> 5, w32 = ij2 & 31;
        int j0 = 8 * (w32 & 7) + 2 * (w32 >> 3);
        float a = -60000.f, b2 = -60000.f;
        if (i < SEQ && j0 < SEQ)     a  = rpb[rel[i * SEQ + j0] * HEADS + h];
        if (i < SEQ && j0 + 1 < SEQ) b2 = rpb[rel[i * SEQ + j0 + 1] * HEADS + h];
        g_biasp_h[t] = h2u(a, b2);
    }
    if (t < (QKV_N / 8) * K16S * 32) {
        int lane = t & 31;
        int u = t >> 5;
        int k16 = u % K16S;
        int n8 = u / K16S;
        int kk = k16 * 16 + ((lane & 3) << 1);
        int nn = n8 * 8 + (lane >> 2);
        {
            uint2 o;
            o.x = h2u(qkv_w[(size_t)kk * QKV_N + nn],       qkv_w[(size_t)(kk + 1) * QKV_N + nn]);
            o.y = h2u(qkv_w[(size_t)(kk + 8) * QKV_N + nn], qkv_w[(size_t)(kk + 9) * QKV_N + nn]);
            *(uint2*)(g_wqkv_t + (size_t)t * 2) = o;
        }
        if (n8 < CDIM / 8) {
            uint2 o;
            o.x = h2u(proj_w[(size_t)kk * CDIM + nn],       proj_w[(size_t)(kk + 1) * CDIM + nn]);
            o.y = h2u(proj_w[(size_t)(kk + 8) * CDIM + nn], proj_w[(size_t)(kk + 9) * CDIM + nn]);
            *(uint2*)(g_wproj_t + (size_t)((n8 * K16S + k16) * 32 + lane) * 2) = o;
        }
    }
}

// x (row-major f32) -> g_xa (A-tiled fp16)
__global__ void cvt_x_kernel(const float* __restrict__ x) {
    size_t t = (size_t)blockIdx.x * 256 + threadIdx.x;
    const size_t total = (size_t)(MROWS / 16) * K16S * 32;
    if (t >= total) return;
    int lane = (int)(t & 31);
    size_t u = t >> 5;
    int k16 = (int)(u % K16S);
    int m16 = (int)(u / K16S);
    int r = lane >> 2, c = (lane & 3) << 1;
    const float* xp = x + (size_t)(m16 * 16) * CDIM + k16 * 16;
    float2 v00 = *(const float2*)(xp + (size_t)r * CDIM + c);
    float2 v10 = *(const float2*)(xp + (size_t)(r + 8) * CDIM + c);
    float2 v01 = *(const float2*)(xp + (size_t)r * CDIM + c + 8);
    float2 v11 = *(const float2*)(xp + (size_t)(r + 8) * CDIM + c + 8);
    uint4 o;
    o.x = h2u(v00.x, v00.y);
    o.y = h2u(v10.x, v10.y);
    o.z = h2u(v01.x, v01.y);
    o.w = h2u(v11.x, v11.y);
    *(uint4*)(g_xa + t * 4) = o;
}

// ---------------------------------------------------------------------------
// GEMM fp16 (unchanged): BM=128, BN=128, BK=32, 128 thr, 3-stage.
// ---------------------------------------------------------------------------
#define GSTAGE 16384
#define GSM_A(s) ((s) * GSTAGE)
#define GSM_B(s) ((s) * GSTAGE + 8192)
#define GEMM_DSMEM (3 * GSTAGE)

template <int MODE>
__global__ void __launch_bounds__(128)
gemm_f16(const float* __restrict__ bias, float* __restrict__ C_out) {
    const uint32_t* A = (MODE == 0) ? g_xa : g_att_t;
    const uint32_t* W = (MODE == 0) ? g_wqkv_t : g_wproj_t;
    const int    Ntot = (MODE == 0) ? QKV_N : CDIM;

    extern __shared__ __align__(16) uint8_t sm[];

    const int tid  = threadIdx.x;
    const int warp = tid >> 5;
    const int lane = tid & 31;
    const int wm   = warp >> 1;
    const int wn   = warp & 1;
    const int m16base = blockIdx.y * 8;
    const int n8base  = blockIdx.x * 16;
    const int n0 = n8base * 8;

    auto load_chunk = [&](int s, int ch) {
#pragma unroll
        for (int it = 0; it < 4; ++it) {
            int idx = tid + it * 128;
            int u = idx >> 5, i = idx & 31;
            cp_async16(sm + GSM_A(s) + idx * 16,
                       A + (((size_t)(m16base + (u >> 1)) * K16S + ch * 2 + (u & 1)) * 32 + i) * 4);
        }
#pragma unroll
        for (int it = 0; it < 4; ++it) {
            int idx = tid + it * 128;
            int u = idx >> 4, i16 = idx & 15;
            cp_async16(sm + GSM_B(s) + idx * 16,
                       W + ((size_t)(n8base + (u >> 1)) * K16S + ch * 2 + (u & 1)) * 64 + i16 * 4);
        }
        cp_async_commit();
    };

    float acc[4][8][4];
#pragma unroll
    for (int i = 0; i < 4; ++i)
#pragma unroll
        for (int j = 0; j < 8; ++j)
#pragma unroll
            for (int q = 0; q < 4; ++q) acc[i][j][q] = 0.f;

    load_chunk(0, 0);
    load_chunk(1, 1);

    const int NCH = K16S / 2;    // 12
    for (int ch = 0; ch < NCH; ++ch) {
        if (ch + 2 < NCH) load_chunk((ch + 2) % 3, ch + 2);
        else              cp_async_commit();
        cp_async_wait<2>();
        __syncthreads();

        const uint32_t* smA = (const uint32_t*)(sm + GSM_A(ch % 3));
        const uint32_t* smB = (const uint32_t*)(sm + GSM_B(ch % 3));
#pragma unroll
        for (int kl = 0; kl < 2; ++kl) {
            uint4 a[4];
#pragma unroll
            for (int mt = 0; mt < 4; ++mt)
                a[mt] = *(const uint4*)&smA[(((wm * 4 + mt) * 2 + kl) * 32 + lane) * 4];
            uint2 b[8];
#pragma unroll
            for (int nt = 0; nt < 8; ++nt)
                b[nt] = *(const uint2*)&smB[(((wn * 8 + nt) * 2 + kl) * 32 + lane) * 2];
#pragma unroll
            for (int mt = 0; mt < 4; ++mt)
#pragma unroll
                for (int nt = 0; nt < 8; ++nt)
                    mma_f16(acc[mt][nt], (const uint32_t*)&a[mt], (const uint32_t*)&b[nt]);
        }
        __syncthreads();
    }

    const float qs = (MODE == 0 && n0 < CDIM) ? SCALE_F : 1.f;
    const int rbase = m16base * 16 + wm * 64 + (lane >> 2);
    const int cbase = n0 + wn * 64 + ((lane & 3) << 1);
#pragma unroll
    for (int mt = 0; mt < 4; ++mt) {
        int r = rbase + mt * 16;
#pragma unroll
        for (int nt = 0; nt < 8; ++nt) {
            int cc = cbase + nt * 8;
            float b0 = bias[cc], b1 = bias[cc + 1];
            const float* a4 = acc[mt][nt];
            if (MODE == 0) {
                g_qkv[(size_t)r * QKV_U + (cc >> 1)]       = h2u((a4[0] + b0) * qs, (a4[1] + b1) * qs);
                g_qkv[(size_t)(r + 8) * QKV_U + (cc >> 1)] = h2u((a4[2] + b0) * qs, (a4[3] + b1) * qs);
            } else {
                *(float2*)(C_out + (size_t)r * Ntot + cc)       = make_float2(a4[0] + b0, a4[1] + b1);
                *(float2*)(C_out + (size_t)(r + 8) * Ntot + cc) = make_float2(a4[2] + b0, a4[3] + b1);
            }
        }
    }
}

// ---------------------------------------------------------------------------
// Window attention: one block per window, 12 heads, double-buffered cp.async.
// ldmatrix fragments, P kept in registers (C-frag == A-frag identity),
// ldmatrix.trans for V (no explicit transpose), vectorized mask/bias.
// ---------------------------------------------------------------------------
#define ATT_STAGE 3840   // q 1280 | k 1280 | v 1280 (u32), row stride 20 u32

__global__ void __launch_bounds__(128)
attn_kernel() {
    const int b = blockIdx.x;

    __shared__ uint32_t sS[2][ATT_STAGE];
    __shared__ uint32_t sMask[64 * 36];

    const int tid  = threadIdx.x;
    const int warp = tid >> 5;
    const int lane = tid & 31;

    const uint32_t* gq = g_qkv + (size_t)b * SEQ * QKV_U;

    auto load_head = [&](int h, int buf) {
#pragma unroll
        for (int i = 0; i < 6; ++i) {
            int idx = tid + i * 128;                 // 0..767
            int which = idx >> 8;                    // 0=q 1=k 2=v
            int n = (idx >> 2) & 63;
            int part = idx & 3;
            int nc = (n < SEQ) ? n : 0;
            const uint32_t* src = gq + (size_t)nc * QKV_U + h * 16 + which * 192 + part * 4;
            cp_async16z(&sS[buf][which * 1280 + n * 20 + part * 4], src, (n < SEQ) ? 16u : 0u);
        }
        cp_async_commit();
    };

    // mask (8KB fp16, permuted) — grouped with head 0's loads
    {
        const uint32_t* mp = g_maskp_h + (size_t)(b & (NW - 1)) * 2048;
#pragma unroll
        for (int i = 0; i < 4; ++i) {
            int idx = tid + i * 128;
            int row = idx >> 3, part = idx & 7;
            cp_async16(&sMask[row * 36 + part * 4], mp + row * 32 + part * 4);
        }
    }
    load_head(0, 0);
    load_head(1, 1);

    const int r0 = warp * 16 + (lane >> 2);
    const int cq = lane & 3;
    const int c0 = cq << 1;
    const int li = lane & 7;
    const int l3 = (lane >> 3) & 1;
    const int l4 = lane >> 4;

    for (int h = 0; h < HEADS; ++h) {
        const int cur = h & 1;
        cp_async_wait<1>();
        __syncthreads();

        const uint32_t qbase = sm2u(&sS[cur][0]);
        const uint32_t kbase = qbase + 1280 * 4;
        const uint32_t vbase = qbase + 2560 * 4;

        // ---- QK^T via ldmatrix ----
        float acc[8][4];
#pragma unroll
        for (int i = 0; i < 8; ++i)
#pragma unroll
            for (int j = 0; j < 4; ++j) acc[i][j] = 0.f;
#pragma unroll
        for (int s = 0; s < 2; ++s) {
            uint32_t a[4];
            ldsm_x4(a, qbase + (uint32_t)((warp * 16 + l3 * 8 + li) * 80 + (s * 16 + l4 * 8) * 2));
            uint32_t bf[4][4];
#pragma unroll
            for (int g = 0; g < 4; ++g)
                ldsm_x4(bf[g], kbase + (uint32_t)((g * 16 + l4 * 8 + li) * 80 + (s * 16 + l3 * 8) * 2));
#pragma unroll
            for (int g = 0; g < 4; ++g) {
                mma_f16(acc[2 * g],     a, &bf[g][0]);
                mma_f16(acc[2 * g + 1], a, &bf[g][2]);
            }
        }

        // ---- bias (LDG.128) + mask (LDS.128), permuted tables ----
        {
            const uint32_t* bp = g_biasp_h + h * 2048;
            uint4 b_lo0 = *(const uint4*)(bp + r0 * 32 + cq * 8);
            uint4 b_hi0 = *(const uint4*)(bp + r0 * 32 + cq * 8 + 4);
            uint4 b_lo1 = *(const uint4*)(bp + (r0 + 8) * 32 + cq * 8);
            uint4 b_hi1 = *(const uint4*)(bp + (r0 + 8) * 32 + cq * 8 + 4);
            uint4 m_lo0 = *(const uint4*)&sMask[r0 * 36 + cq * 8];
            uint4 m_hi0 = *(const uint4*)&sMask[r0 * 36 + cq * 8 + 4];
            uint4 m_lo1 = *(const uint4*)&sMask[(r0 + 8) * 36 + cq * 8];
            uint4 m_hi1 = *(const uint4*)&sMask[(r0 + 8) * 36 + cq * 8 + 4];
            const uint32_t* bw0 = (const uint32_t*)&b_lo0;   // [0..3]=nt0..3 via lo, hi
            const uint32_t* bw0h = (const uint32_t*)&b_hi0;
            const uint32_t* bw1 = (const uint32_t*)&b_lo1;
            const uint32_t* bw1h = (const uint32_t*)&b_hi1;
            const uint32_t* mw0 = (const uint32_t*)&m_lo0;
            const uint32_t* mw0h = (const uint32_t*)&m_hi0;
            const uint32_t* mw1 = (const uint32_t*)&m_lo1;
            const uint32_t* mw1h = (const uint32_t*)&m_hi1;
#pragma unroll
            for (int nt = 0; nt < 8; ++nt) {
                uint32_t bu0 = (nt < 4) ? bw0[nt] : bw0h[nt - 4];
                uint32_t bu1 = (nt < 4) ? bw1[nt] : bw1h[nt - 4];
                uint32_t mu0 = (nt < 4) ? mw0[nt] : mw0h[nt - 4];
                uint32_t mu1 = (nt < 4) ? mw1[nt] : mw1h[nt - 4];
                float2 fb0 = __half22float2(*(__half2*)&bu0);
                float2 fb1 = __half22float2(*(__half2*)&bu1);
                float2 fm0 = __half22float2(*(__half2*)&mu0);
                float2 fm1 = __half22float2(*(__half2*)&mu1);
                acc[nt][0] += fb0.x + fm0.x;
                acc[nt][1] += fb0.y + fm0.y;
                acc[nt][2] += fb1.x + fm1.x;
                acc[nt][3] += fb1.y + fm1.y;
            }
        }

        // ---- row softmax (quad shuffles) ----
        {
            float mx0 = -3e38f, mx1 = -3e38f;
#pragma unroll
            for (int nt = 0; nt < 8; ++nt) {
                mx0 = fmaxf(mx0, fmaxf(acc[nt][0], acc[nt][1]));
                mx1 = fmaxf(mx1, fmaxf(acc[nt][2], acc[nt][3]));
            }
            mx0 = fmaxf(mx0, __shfl_xor_sync(0xffffffffu, mx0, 1));
            mx0 = fmaxf(mx0, __shfl_xor_sync(0xffffffffu, mx0, 2));
            mx1 = fmaxf(mx1, __shfl_xor_sync(0xffffffffu, mx1, 1));
            mx1 = fmaxf(mx1, __shfl_xor_sync(0xffffffffu, mx1, 2));
            float s0 = 0.f, s1 = 0.f;
#pragma unroll
            for (int nt = 0; nt < 8; ++nt) {
                acc[nt][0] = __expf(acc[nt][0] - mx0); s0 += acc[nt][0];
                acc[nt][1] = __expf(acc[nt][1] - mx0); s0 += acc[nt][1];
                acc[nt][2] = __expf(acc[nt][2] - mx1); s1 += acc[nt][2];
                acc[nt][3] = __expf(acc[nt][3] - mx1); s1 += acc[nt][3];
            }
            s0 += __shfl_xor_sync(0xffffffffu, s0, 1);
            s0 += __shfl_xor_sync(0xffffffffu, s0, 2);
            s1 += __shfl_xor_sync(0xffffffffu, s1, 1);
            s1 += __shfl_xor_sync(0xffffffffu, s1, 2);
            float inv0 = 1.f / s0, inv1 = 1.f / s1;
#pragma unroll
            for (int nt = 0; nt < 8; ++nt) {
                acc[nt][0] *= inv0; acc[nt][1] *= inv0;
                acc[nt][2] *= inv1; acc[nt][3] *= inv1;
            }
        }

        // ---- O = P V : P from registers (C-frag == A-frag), V via ldmatrix.trans
        {
            float oacc[4][4];
#pragma unroll
            for (int i = 0; i < 4; ++i)
#pragma unroll
                for (int j = 0; j < 4; ++j) oacc[i][j] = 0.f;
#pragma unroll
            for (int s = 0; s < 4; ++s) {
                uint32_t a[4];
                a[0] = h2u(acc[2 * s][0],     acc[2 * s][1]);
                a[1] = h2u(acc[2 * s][2],     acc[2 * s][3]);
                a[2] = h2u(acc[2 * s + 1][0], acc[2 * s + 1][1]);
                a[3] = h2u(acc[2 * s + 1][2], acc[2 * s + 1][3]);
                uint32_t bf[2][4];
#pragma unroll
                for (int g = 0; g < 2; ++g)
                    ldsm_x4_t(bf[g], vbase + (uint32_t)((s * 16 + l3 * 8 + li) * 80 + (g * 16 + l4 * 8) * 2));
                mma_f16(oacc[0], a, &bf[0][0]);
                mma_f16(oacc[1], a, &bf[0][2]);
                mma_f16(oacc[2], a, &bf[1][0]);
                mma_f16(oacc[3], a, &bf[1][2]);
            }
#pragma unroll
            for (int nt = 0; nt < 4; ++nt) {
                int c = h * HDIM + nt * 8 + c0;
                if (r0 < SEQ)
                    g_att_t[a16_off(b * SEQ + r0, c)]     = h2u(oacc[nt][0], oacc[nt][1]);
                if (r0 + 8 < SEQ)
                    g_att_t[a16_off(b * SEQ + r0 + 8, c)] = h2u(oacc[nt][2], oacc[nt][3]);
            }
        }

        __syncthreads();   // all reads of cur buffer done before refill
        if (h + 2 < HEADS) load_head(h + 2, cur);
        else               cp_async_commit();
    }
}

// ---------------------------------------------------------------------------
// Launch
// ---------------------------------------------------------------------------
extern "C" void kernel_launch(void* const* d_in, const int* in_sizes, int n_in,
                              void* d_out, int out_size) {
    const float* x      = (const float*)d_in[0];
    const float* mask   = (const float*)d_in[1];
    const float* qkv_w  = (const float*)d_in[2];
    const float* qkv_b  = (const float*)d_in[3];
    const float* proj_w = (const float*)d_in[4];
    const float* proj_b = (const float*)d_in[5];
    const float* rpb    = (const float*)d_in[6];
    const int*   rel    = (const int*)d_in[7];
    float*       out    = (float*)d_out;

    cudaFuncSetAttribute(gemm_f16<0>, cudaFuncAttributeMaxDynamicSharedMemorySize, GEMM_DSMEM);
    cudaFuncSetAttribute(gemm_f16<1>, cudaFuncAttributeMaxDynamicSharedMemorySize, GEMM_DSMEM);

    // 0) prep (permuted fp16 mask/bias tables + tiled weights), x cvt
    prep_kernel<<<(NW * 2048 + 255) / 256, 256>>>(mask, rpb, rel, qkv_w, proj_w);
    cvt_x_kernel<<<(int)(((size_t)(MROWS / 16) * K16S * 32 + 255) / 256), 256>>>(x);
    // 1) QKV GEMM
    gemm_f16<0><<<dim3(QKV_N / 128, MROWS / 128), 128, GEMM_DSMEM>>>(qkv_b, nullptr);
    // 2) Attention (one block per window, 12 heads, double-buffered)
    attn_kernel<<<B_WIN, 128>>>();
    // 3) Proj GEMM
    gemm_f16<1><<<dim3(CDIM / 128, MROWS / 128), 128, GEMM_DSMEM>>>(proj_b, out);
}

// round 13
// speedup vs baseline: 4.2864x; 1.0251x over previous
#include <cuda_runtime.h>
#include <cuda_fp16.h>
#include <cstdint>

// Problem constants
#define B_WIN   4096
#define SEQ     49
#define NPAD    64
#define CDIM    384
#define HEADS   12
#define HDIM    32
#define NW      1024
#define MROWS   (B_WIN * SEQ)        // 200704
#define QKV_N   (3 * CDIM)           // 1152
#define QKV_U   (QKV_N / 2)          // 576 u32 per row
#define K16S    (CDIM / 16)          // 24 k16-subtiles
#define SCALE_F 0.17677669529663687f // 32^-0.5
#define LOG2E   1.4426950408889634f

// Scratch (static device globals)
__device__ uint32_t g_qkv[(size_t)MROWS * QKV_U];              // half2 rows (B_*N, 576)
__device__ uint32_t g_xa[(size_t)(MROWS / 16) * K16S * 128];   // x, A-tiled fp16
__device__ uint32_t g_att_t[(size_t)(MROWS / 16) * K16S * 128];// attn out, A-tiled fp16
__device__ uint32_t g_wqkv_t[(QKV_N / 8) * K16S * 64];         // B-tiled fp16
__device__ uint32_t g_wproj_t[(CDIM / 8) * K16S * 64];
__device__ uint32_t g_biasp_h[HEADS * 2048];                   // fp16 bias*log2e, permuted, pad=-30000
__device__ uint32_t g_maskp_h[NW * 2048];                      // fp16 mask*log2e, permuted, pad=0

// ---------------------------------------------------------------------------
// Helpers
// ---------------------------------------------------------------------------
__device__ __forceinline__ uint32_t h2u(float a, float b) {
    __half2 h = __floats2half2_rn(a, b);
    return *(uint32_t*)&h;
}
__device__ __forceinline__ float ex2(float x) {
    float y;
    asm("ex2.approx.f32 %0, %1;" : "=f"(y) : "f"(x));
    return y;
}

__device__ __forceinline__ void mma_f16(float* c, const uint32_t* a, const uint32_t* b) {
    asm volatile(
        "mma.sync.aligned.m16n8k16.row.col.f32.f16.f16.f32 "
        "{%0,%1,%2,%3}, {%4,%5,%6,%7}, {%8,%9}, {%0,%1,%2,%3};\n"
        : "+f"(c[0]), "+f"(c[1]), "+f"(c[2]), "+f"(c[3])
        : "r"(a[0]), "r"(a[1]), "r"(a[2]), "r"(a[3]), "r"(b[0]), "r"(b[1]));
}

__device__ __forceinline__ void ldsm_x4(uint32_t* r, uint32_t addr) {
    asm volatile("ldmatrix.sync.aligned.m8n8.x4.shared.b16 {%0,%1,%2,%3}, [%4];"
                 : "=r"(r[0]), "=r"(r[1]), "=r"(r[2]), "=r"(r[3]) : "r"(addr));
}
__device__ __forceinline__ void ldsm_x4_t(uint32_t* r, uint32_t addr) {
    asm volatile("ldmatrix.sync.aligned.m8n8.x4.trans.shared.b16 {%0,%1,%2,%3}, [%4];"
                 : "=r"(r[0]), "=r"(r[1]), "=r"(r[2]), "=r"(r[3]) : "r"(addr));
}
__device__ __forceinline__ uint32_t sm2u(const void* p) {
    return (uint32_t)__cvta_generic_to_shared(p);
}

__device__ __forceinline__ void cp_async16(void* smem_dst, const void* gmem_src) {
    uint32_t s = (uint32_t)__cvta_generic_to_shared(smem_dst);
    asm volatile("cp.async.cg.shared.global [%0], [%1], 16;\n" :: "r"(s), "l"(gmem_src));
}
__device__ __forceinline__ void cp_async16z(void* smem_dst, const void* gmem_src, uint32_t src_sz) {
    uint32_t s = (uint32_t)__cvta_generic_to_shared(smem_dst);
    asm volatile("cp.async.cg.shared.global [%0], [%1], 16, %2;\n" :: "r"(s), "l"(gmem_src), "r"(src_sz));
}
__device__ __forceinline__ void cp_async_commit() {
    asm volatile("cp.async.commit_group;\n" ::: "memory");
}
template <int N>
__device__ __forceinline__ void cp_async_wait() {
    asm volatile("cp.async.wait_group %0;\n" :: "n"(N) : "memory");
}

// A-tiled fp16 u32 index for element pair (m, c..c+1), c even, K=384
__device__ __forceinline__ size_t a16_off(int m, int c) {
    int m16 = m >> 4, rr = m & 15, k16 = c >> 4, kc = c & 15;
    int lane = ((rr & 7) << 2) | ((kc & 7) >> 1);
    int w = (rr >> 3) | ((kc >> 3) << 1);
    return (((size_t)m16 * K16S + k16) * 32 + lane) * 4 + w;
}

// ---------------------------------------------------------------------------
// Merged cvt_x + prep (block-range partitioned)
// Permutation for mask/bias: word w32 holds j0 = 8*(w32&7) + 2*(w32>>3).
// Both tables pre-scaled by LOG2E; bias pad = -30000 (ex2 -> 0).
// ---------------------------------------------------------------------------
#define CVT_BLKS 37632    // (MROWS/16)*K16S*32 / 256
#define PREP_BLKS 8192    // NW*2048 / 256

__global__ void prep_cvt_kernel(const float* __restrict__ x,
                                const float* __restrict__ mask,
                                const float* __restrict__ rpb, const int* __restrict__ rel,
                                const float* __restrict__ qkv_w, const float* __restrict__ proj_w) {
    if (blockIdx.x < CVT_BLKS) {
        size_t t = (size_t)blockIdx.x * 256 + threadIdx.x;
        int lane = (int)(t & 31);
        size_t u = t >> 5;
        int k16 = (int)(u % K16S);
        int m16 = (int)(u / K16S);
        int r = lane >> 2, c = (lane & 3) << 1;
        const float* xp = x + (size_t)(m16 * 16) * CDIM + k16 * 16;
        float2 v00 = *(const float2*)(xp + (size_t)r * CDIM + c);
        float2 v10 = *(const float2*)(xp + (size_t)(r + 8) * CDIM + c);
        float2 v01 = *(const float2*)(xp + (size_t)r * CDIM + c + 8);
        float2 v11 = *(const float2*)(xp + (size_t)(r + 8) * CDIM + c + 8);
        uint4 o;
        o.x = h2u(v00.x, v00.y);
        o.y = h2u(v10.x, v10.y);
        o.z = h2u(v01.x, v01.y);
        o.w = h2u(v11.x, v11.y);
        *(uint4*)(g_xa + t * 4) = o;
        return;
    }
    int t = (blockIdx.x - CVT_BLKS) * 256 + threadIdx.x;
    // mask * LOG2E, permuted
    if (t < NW * 2048) {
        int w = t >> 11, ij2 = t & 2047, i = ij2 >> 5, w32 = ij2 & 31;
        int j0 = 8 * (w32 & 7) + 2 * (w32 >> 3);
        float a = 0.f, b2 = 0.f;
        if (i < SEQ && j0 < SEQ)     a  = mask[(size_t)w * SEQ * SEQ + i * SEQ + j0] * LOG2E;
        if (i < SEQ && j0 + 1 < SEQ) b2 = mask[(size_t)w * SEQ * SEQ + i * SEQ + j0 + 1] * LOG2E;
        g_maskp_h[t] = h2u(a, b2);
    }
    // bias * LOG2E, permuted, pad=-30000
    if (t < HEADS * 2048) {
        int h = t >> 11, ij2 = t & 2047, i = ij2 >> 5, w32 = ij2 & 31;
        int j0 = 8 * (w32 & 7) + 2 * (w32 >> 3);
        float a = -30000.f, b2 = -30000.f;
        if (i < SEQ && j0 < SEQ)     a  = rpb[rel[i * SEQ + j0] * HEADS + h] * LOG2E;
        if (i < SEQ && j0 + 1 < SEQ) b2 = rpb[rel[i * SEQ + j0 + 1] * HEADS + h] * LOG2E;
        g_biasp_h[t] = h2u(a, b2);
    }
    // weights B-tiled fp16
    if (t < (QKV_N / 8) * K16S * 32) {
        int lane = t & 31;
        int u = t >> 5;
        int k16 = u % K16S;
        int n8 = u / K16S;
        int kk = k16 * 16 + ((lane & 3) << 1);
        int nn = n8 * 8 + (lane >> 2);
        {
            uint2 o;
            o.x = h2u(qkv_w[(size_t)kk * QKV_N + nn],       qkv_w[(size_t)(kk + 1) * QKV_N + nn]);
            o.y = h2u(qkv_w[(size_t)(kk + 8) * QKV_N + nn], qkv_w[(size_t)(kk + 9) * QKV_N + nn]);
            *(uint2*)(g_wqkv_t + (size_t)t * 2) = o;
        }
        if (n8 < CDIM / 8) {
            uint2 o;
            o.x = h2u(proj_w[(size_t)kk * CDIM + nn],       proj_w[(size_t)(kk + 1) * CDIM + nn]);
            o.y = h2u(proj_w[(size_t)(kk + 8) * CDIM + nn], proj_w[(size_t)(kk + 9) * CDIM + nn]);
            *(uint2*)(g_wproj_t + (size_t)((n8 * K16S + k16) * 32 + lane) * 2) = o;
        }
    }
}

// ---------------------------------------------------------------------------
// GEMM fp16 (structure unchanged): BM=128, BN=128, BK=32, 128 thr, 3-stage.
// MODE 0 q-cols scaled by SCALE_F * LOG2E (base-2 softmax folding).
// ---------------------------------------------------------------------------
#define GSTAGE 16384
#define GSM_A(s) ((s) * GSTAGE)
#define GSM_B(s) ((s) * GSTAGE + 8192)
#define GEMM_DSMEM (3 * GSTAGE)

template <int MODE>
__global__ void __launch_bounds__(128)
gemm_f16(const float* __restrict__ bias, float* __restrict__ C_out) {
    const uint32_t* A = (MODE == 0) ? g_xa : g_att_t;
    const uint32_t* W = (MODE == 0) ? g_wqkv_t : g_wproj_t;
    const int    Ntot = (MODE == 0) ? QKV_N : CDIM;

    extern __shared__ __align__(16) uint8_t sm[];

    const int tid  = threadIdx.x;
    const int warp = tid >> 5;
    const int lane = tid & 31;
    const int wm   = warp >> 1;
    const int wn   = warp & 1;
    const int m16base = blockIdx.y * 8;
    const int n8base  = blockIdx.x * 16;
    const int n0 = n8base * 8;

    auto load_chunk = [&](int s, int ch) {
#pragma unroll
        for (int it = 0; it < 4; ++it) {
            int idx = tid + it * 128;
            int u = idx >> 5, i = idx & 31;
            cp_async16(sm + GSM_A(s) + idx * 16,
                       A + (((size_t)(m16base + (u >> 1)) * K16S + ch * 2 + (u & 1)) * 32 + i) * 4);
        }
#pragma unroll
        for (int it = 0; it < 4; ++it) {
            int idx = tid + it * 128;
            int u = idx >> 4, i16 = idx & 15;
            cp_async16(sm + GSM_B(s) + idx * 16,
                       W + ((size_t)(n8base + (u >> 1)) * K16S + ch * 2 + (u & 1)) * 64 + i16 * 4);
        }
        cp_async_commit();
    };

    float acc[4][8][4];
#pragma unroll
    for (int i = 0; i < 4; ++i)
#pragma unroll
        for (int j = 0; j < 8; ++j)
#pragma unroll
            for (int q = 0; q < 4; ++q) acc[i][j][q] = 0.f;

    load_chunk(0, 0);
    load_chunk(1, 1);

    const int NCH = K16S / 2;    // 12
    for (int ch = 0; ch < NCH; ++ch) {
        if (ch + 2 < NCH) load_chunk((ch + 2) % 3, ch + 2);
        else              cp_async_commit();
        cp_async_wait<2>();
        __syncthreads();

        const uint32_t* smA = (const uint32_t*)(sm + GSM_A(ch % 3));
        const uint32_t* smB = (const uint32_t*)(sm + GSM_B(ch % 3));
#pragma unroll
        for (int kl = 0; kl < 2; ++kl) {
            uint4 a[4];
#pragma unroll
            for (int mt = 0; mt < 4; ++mt)
                a[mt] = *(const uint4*)&smA[(((wm * 4 + mt) * 2 + kl) * 32 + lane) * 4];
            uint2 b[8];
#pragma unroll
            for (int nt = 0; nt < 8; ++nt)
                b[nt] = *(const uint2*)&smB[(((wn * 8 + nt) * 2 + kl) * 32 + lane) * 2];
#pragma unroll
            for (int mt = 0; mt < 4; ++mt)
#pragma unroll
                for (int nt = 0; nt < 8; ++nt)
                    mma_f16(acc[mt][nt], (const uint32_t*)&a[mt], (const uint32_t*)&b[nt]);
        }
        __syncthreads();
    }

    const float qs = (MODE == 0 && n0 < CDIM) ? SCALE_F * LOG2E : 1.f;
    const int rbase = m16base * 16 + wm * 64 + (lane >> 2);
    const int cbase = n0 + wn * 64 + ((lane & 3) << 1);
#pragma unroll
    for (int mt = 0; mt < 4; ++mt) {
        int r = rbase + mt * 16;
#pragma unroll
        for (int nt = 0; nt < 8; ++nt) {
            int cc = cbase + nt * 8;
            float b0 = bias[cc], b1 = bias[cc + 1];
            const float* a4 = acc[mt][nt];
            if (MODE == 0) {
                g_qkv[(size_t)r * QKV_U + (cc >> 1)]       = h2u((a4[0] + b0) * qs, (a4[1] + b1) * qs);
                g_qkv[(size_t)(r + 8) * QKV_U + (cc >> 1)] = h2u((a4[2] + b0) * qs, (a4[3] + b1) * qs);
            } else {
                *(float2*)(C_out + (size_t)r * Ntot + cc)       = make_float2(a4[0] + b0, a4[1] + b1);
                *(float2*)(C_out + (size_t)(r + 8) * Ntot + cc) = make_float2(a4[2] + b0, a4[3] + b1);
            }
        }
    }
}

// ---------------------------------------------------------------------------
// Window attention: one block per window, 12 heads, double-buffered cp.async.
// Base-2 softmax, no max-subtraction, normalize-after-PV, mask+bias via LDG.
// ---------------------------------------------------------------------------
#define ATT_STAGE 3840   // q 1280 | k 1280 | v 1280 (u32), row stride 20 u32

__global__ void __launch_bounds__(128, 6)
attn_kernel() {
    const int b = blockIdx.x;

    __shared__ uint32_t sS[2][ATT_STAGE];

    const int tid  = threadIdx.x;
    const int warp = tid >> 5;
    const int lane = tid & 31;

    const uint32_t* gq = g_qkv + (size_t)b * SEQ * QKV_U;

    auto load_head = [&](int h, int buf) {
#pragma unroll
        for (int i = 0; i < 6; ++i) {
            int idx = tid + i * 128;                 // 0..767
            int which = idx >> 8;                    // 0=q 1=k 2=v
            int n = (idx >> 2) & 63;
            int part = idx & 3;
            int nc = (n < SEQ) ? n : 0;
            const uint32_t* src = gq + (size_t)nc * QKV_U + h * 16 + which * 192 + part * 4;
            cp_async16z(&sS[buf][which * 1280 + n * 20 + part * 4], src, (n < SEQ) ? 16u : 0u);
        }
        cp_async_commit();
    };

    load_head(0, 0);
    load_head(1, 1);

    const int r0 = warp * 16 + (lane >> 2);
    const int cq = lane & 3;
    const int c0 = cq << 1;
    const int li = lane & 7;
    const int l3 = (lane >> 3) & 1;
    const int l4 = lane >> 4;

    const uint32_t* mp = g_maskp_h + (size_t)(b & (NW - 1)) * 2048;

    for (int h = 0; h < HEADS; ++h) {
        const int cur = h & 1;
        cp_async_wait<1>();
        __syncthreads();

        const uint32_t qbase = sm2u(&sS[cur][0]);
        const uint32_t kbase = qbase + 1280 * 4;
        const uint32_t vbase = qbase + 2560 * 4;

        // ---- QK^T via ldmatrix ----
        float acc[8][4];
#pragma unroll
        for (int i = 0; i < 8; ++i)
#pragma unroll
            for (int j = 0; j < 4; ++j) acc[i][j] = 0.f;
#pragma unroll
        for (int s = 0; s < 2; ++s) {
            uint32_t a[4];
            ldsm_x4(a, qbase + (uint32_t)((warp * 16 + l3 * 8 + li) * 80 + (s * 16 + l4 * 8) * 2));
            uint32_t bf[4][4];
#pragma unroll
            for (int g = 0; g < 4; ++g)
                ldsm_x4(bf[g], kbase + (uint32_t)((g * 16 + l4 * 8 + li) * 80 + (s * 16 + l3 * 8) * 2));
#pragma unroll
            for (int g = 0; g < 4; ++g) {
                mma_f16(acc[2 * g],     a, &bf[g][0]);
                mma_f16(acc[2 * g + 1], a, &bf[g][2]);
            }
        }

        // ---- bias + mask (both LDG.128 from permuted fp16 tables) ----
        {
            const uint32_t* bp = g_biasp_h + h * 2048;
            uint4 b_lo0 = *(const uint4*)(bp + r0 * 32 + cq * 8);
            uint4 b_hi0 = *(const uint4*)(bp + r0 * 32 + cq * 8 + 4);
            uint4 b_lo1 = *(const uint4*)(bp + (r0 + 8) * 32 + cq * 8);
            uint4 b_hi1 = *(const uint4*)(bp + (r0 + 8) * 32 + cq * 8 + 4);
            uint4 m_lo0 = *(const uint4*)(mp + r0 * 32 + cq * 8);
            uint4 m_hi0 = *(const uint4*)(mp + r0 * 32 + cq * 8 + 4);
            uint4 m_lo1 = *(const uint4*)(mp + (r0 + 8) * 32 + cq * 8);
            uint4 m_hi1 = *(const uint4*)(mp + (r0 + 8) * 32 + cq * 8 + 4);
            const uint32_t* bw0 = (const uint32_t*)&b_lo0;
            const uint32_t* bw0h = (const uint32_t*)&b_hi0;
            const uint32_t* bw1 = (const uint32_t*)&b_lo1;
            const uint32_t* bw1h = (const uint32_t*)&b_hi1;
            const uint32_t* mw0 = (const uint32_t*)&m_lo0;
            const uint32_t* mw0h = (const uint32_t*)&m_hi0;
            const uint32_t* mw1 = (const uint32_t*)&m_lo1;
            const uint32_t* mw1h = (const uint32_t*)&m_hi1;
#pragma unroll
            for (int nt = 0; nt < 8; ++nt) {
                uint32_t bu0 = (nt < 4) ? bw0[nt] : bw0h[nt - 4];
                uint32_t bu1 = (nt < 4) ? bw1[nt] : bw1h[nt - 4];
                uint32_t mu0 = (nt < 4) ? mw0[nt] : mw0h[nt - 4];
                uint32_t mu1 = (nt < 4) ? mw1[nt] : mw1h[nt - 4];
                float2 fb0 = __half22float2(*(__half2*)&bu0);
                float2 fb1 = __half22float2(*(__half2*)&bu1);
                float2 fm0 = __half22float2(*(__half2*)&mu0);
                float2 fm1 = __half22float2(*(__half2*)&mu1);
                acc[nt][0] += fb0.x + fm0.x;
                acc[nt][1] += fb0.y + fm0.y;
                acc[nt][2] += fb1.x + fm1.x;
                acc[nt][3] += fb1.y + fm1.y;
            }
        }

        // ---- base-2 softmax, no max-subtraction; nt=7 is always padding ----
        float inv0, inv1;
        {
            float s0 = 0.f, s1 = 0.f;
#pragma unroll
            for (int nt = 0; nt < 7; ++nt) {
                acc[nt][0] = ex2(acc[nt][0]); s0 += acc[nt][0];
                acc[nt][1] = ex2(acc[nt][1]); s0 += acc[nt][1];
                acc[nt][2] = ex2(acc[nt][2]); s1 += acc[nt][2];
                acc[nt][3] = ex2(acc[nt][3]); s1 += acc[nt][3];
            }
            acc[7][0] = acc[7][1] = acc[7][2] = acc[7][3] = 0.f;
            s0 += __shfl_xor_sync(0xffffffffu, s0, 1);
            s0 += __shfl_xor_sync(0xffffffffu, s0, 2);
            s1 += __shfl_xor_sync(0xffffffffu, s1, 1);
            s1 += __shfl_xor_sync(0xffffffffu, s1, 2);
            inv0 = 1.f / s0;
            inv1 = 1.f / s1;
        }

        // ---- O = P V (P unnormalized, from registers); normalize after ----
        {
            float oacc[4][4];
#pragma unroll
            for (int i = 0; i < 4; ++i)
#pragma unroll
                for (int j = 0; j < 4; ++j) oacc[i][j] = 0.f;
#pragma unroll
            for (int s = 0; s < 4; ++s) {
                uint32_t a[4];
                a[0] = h2u(acc[2 * s][0],     acc[2 * s][1]);
                a[1] = h2u(acc[2 * s][2],     acc[2 * s][3]);
                a[2] = h2u(acc[2 * s + 1][0], acc[2 * s + 1][1]);
                a[3] = h2u(acc[2 * s + 1][2], acc[2 * s + 1][3]);
                uint32_t bf[2][4];
#pragma unroll
                for (int g = 0; g < 2; ++g)
                    ldsm_x4_t(bf[g], vbase + (uint32_t)((s * 16 + l3 * 8 + li) * 80 + (g * 16 + l4 * 8) * 2));
                mma_f16(oacc[0], a, &bf[0][0]);
                mma_f16(oacc[1], a, &bf[0][2]);
                mma_f16(oacc[2], a, &bf[1][0]);
                mma_f16(oacc[3], a, &bf[1][2]);
            }
#pragma unroll
            for (int nt = 0; nt < 4; ++nt) {
                int c = h * HDIM + nt * 8 + c0;
                if (r0 < SEQ)
                    g_att_t[a16_off(b * SEQ + r0, c)]     = h2u(oacc[nt][0] * inv0, oacc[nt][1] * inv0);
                if (r0 + 8 < SEQ)
                    g_att_t[a16_off(b * SEQ + r0 + 8, c)] = h2u(oacc[nt][2] * inv1, oacc[nt][3] * inv1);
            }
        }

        __syncthreads();   // all reads of cur buffer done before refill
        if (h + 2 < HEADS) load_head(h + 2, cur);
        else               cp_async_commit();
    }
}

// ---------------------------------------------------------------------------
// Launch
// ---------------------------------------------------------------------------
extern "C" void kernel_launch(void* const* d_in, const int* in_sizes, int n_in,
                              void* d_out, int out_size) {
    const float* x      = (const float*)d_in[0];
    const float* mask   = (const float*)d_in[1];
    const float* qkv_w  = (const float*)d_in[2];
    const float* qkv_b  = (const float*)d_in[3];
    const float* proj_w = (const float*)d_in[4];
    const float* proj_b = (const float*)d_in[5];
    const float* rpb    = (const float*)d_in[6];
    const int*   rel    = (const int*)d_in[7];
    float*       out    = (float*)d_out;

    cudaFuncSetAttribute(gemm_f16<0>, cudaFuncAttributeMaxDynamicSharedMemorySize, GEMM_DSMEM);
    cudaFuncSetAttribute(gemm_f16<1>, cudaFuncAttributeMaxDynamicSharedMemorySize, GEMM_DSMEM);

    // 0) merged prep (log2e-scaled fp16 tables + tiled weights) + x cvt
    prep_cvt_kernel<<<CVT_BLKS + PREP_BLKS, 256>>>(x, mask, rpb, rel, qkv_w, proj_w);
    // 1) QKV GEMM (q-cols scaled by SCALE_F*LOG2E)
    gemm_f16<0><<<dim3(QKV_N / 128, MROWS / 128), 128, GEMM_DSMEM>>>(qkv_b, nullptr);
    // 2) Attention (one block per window, 12 heads, double-buffered)
    attn_kernel<<<B_WIN, 128>>>();
    // 3) Proj GEMM
    gemm_f16<1><<<dim3(CDIM / 128, MROWS / 128), 128, GEMM_DSMEM>>>(proj_b, out);
}

// round 14
// speedup vs baseline: 4.2917x; 1.0012x over previous
#include <cuda_runtime.h>
#include <cuda_fp16.h>
#include <cstdint>

// Problem constants
#define B_WIN   4096
#define SEQ     49
#define NPAD    64
#define CDIM    384
#define HEADS   12
#define HDIM    32
#define NW      1024
#define MROWS   (B_WIN * SEQ)        // 200704
#define QKV_N   (3 * CDIM)           // 1152
#define QKV_U   (QKV_N / 2)          // 576 u32 per row
#define K16S    (CDIM / 16)          // 24 k16-subtiles
#define SCALE_F 0.17677669529663687f // 32^-0.5
#define LOG2E   1.4426950408889634f

// Scratch (static device globals)
__device__ uint32_t g_qkv[(size_t)MROWS * QKV_U];              // half2 rows (B_*N, 576)
__device__ uint32_t g_xa[(size_t)(MROWS / 16) * K16S * 128];   // x, A-tiled fp16
__device__ uint32_t g_att_t[(size_t)(MROWS / 16) * K16S * 128];// attn out, A-tiled fp16
__device__ uint32_t g_wqkv_t[(QKV_N / 8) * K16S * 64];         // B-tiled fp16
__device__ uint32_t g_wproj_t[(CDIM / 8) * K16S * 64];
__device__ uint32_t g_biasp_h[HEADS * 2048];                   // fp16 bias*log2e, permuted, pad=-30000
__device__ uint32_t g_maskp_h[NW * 2048];                      // fp16 mask*log2e, permuted, pad=0

// ---------------------------------------------------------------------------
// Helpers
// ---------------------------------------------------------------------------
__device__ __forceinline__ uint32_t h2u(float a, float b) {
    __half2 h = __floats2half2_rn(a, b);
    return *(uint32_t*)&h;
}
__device__ __forceinline__ float ex2(float x) {
    float y;
    asm("ex2.approx.f32 %0, %1;" : "=f"(y) : "f"(x));
    return y;
}

__device__ __forceinline__ void mma_f16(float* c, const uint32_t* a, const uint32_t* b) {
    asm volatile(
        "mma.sync.aligned.m16n8k16.row.col.f32.f16.f16.f32 "
        "{%0,%1,%2,%3}, {%4,%5,%6,%7}, {%8,%9}, {%0,%1,%2,%3};\n"
        : "+f"(c[0]), "+f"(c[1]), "+f"(c[2]), "+f"(c[3])
        : "r"(a[0]), "r"(a[1]), "r"(a[2]), "r"(a[3]), "r"(b[0]), "r"(b[1]));
}

__device__ __forceinline__ void ldsm_x4(uint32_t* r, uint32_t addr) {
    asm volatile("ldmatrix.sync.aligned.m8n8.x4.shared.b16 {%0,%1,%2,%3}, [%4];"
                 : "=r"(r[0]), "=r"(r[1]), "=r"(r[2]), "=r"(r[3]) : "r"(addr));
}
__device__ __forceinline__ void ldsm_x4_t(uint32_t* r, uint32_t addr) {
    asm volatile("ldmatrix.sync.aligned.m8n8.x4.trans.shared.b16 {%0,%1,%2,%3}, [%4];"
                 : "=r"(r[0]), "=r"(r[1]), "=r"(r[2]), "=r"(r[3]) : "r"(addr));
}
__device__ __forceinline__ uint32_t sm2u(const void* p) {
    return (uint32_t)__cvta_generic_to_shared(p);
}

__device__ __forceinline__ void cp_async16(void* smem_dst, const void* gmem_src) {
    uint32_t s = (uint32_t)__cvta_generic_to_shared(smem_dst);
    asm volatile("cp.async.cg.shared.global [%0], [%1], 16;\n" :: "r"(s), "l"(gmem_src));
}
__device__ __forceinline__ void cp_async16z(void* smem_dst, const void* gmem_src, uint32_t src_sz) {
    uint32_t s = (uint32_t)__cvta_generic_to_shared(smem_dst);
    asm volatile("cp.async.cg.shared.global [%0], [%1], 16, %2;\n" :: "r"(s), "l"(gmem_src), "r"(src_sz));
}
__device__ __forceinline__ void cp_async_commit() {
    asm volatile("cp.async.commit_group;\n" ::: "memory");
}
template <int N>
__device__ __forceinline__ void cp_async_wait() {
    asm volatile("cp.async.wait_group %0;\n" :: "n"(N) : "memory");
}

// A-tiled fp16 u32 index for element pair (m, c..c+1), c even, K=384
__device__ __forceinline__ size_t a16_off(int m, int c) {
    int m16 = m >> 4, rr = m & 15, k16 = c >> 4, kc = c & 15;
    int lane = ((rr & 7) << 2) | ((kc & 7) >> 1);
    int w = (rr >> 3) | ((kc >> 3) << 1);
    return (((size_t)m16 * K16S + k16) * 32 + lane) * 4 + w;
}

// ---------------------------------------------------------------------------
// Merged cvt_x + prep (block-range partitioned)
// ---------------------------------------------------------------------------
#define CVT_BLKS 37632    // (MROWS/16)*K16S*32 / 256
#define PREP_BLKS 8192    // NW*2048 / 256

__global__ void prep_cvt_kernel(const float* __restrict__ x,
                                const float* __restrict__ mask,
                                const float* __restrict__ rpb, const int* __restrict__ rel,
                                const float* __restrict__ qkv_w, const float* __restrict__ proj_w) {
    if (blockIdx.x < CVT_BLKS) {
        size_t t = (size_t)blockIdx.x * 256 + threadIdx.x;
        int lane = (int)(t & 31);
        size_t u = t >> 5;
        int k16 = (int)(u % K16S);
        int m16 = (int)(u / K16S);
        int r = lane >> 2, c = (lane & 3) << 1;
        const float* xp = x + (size_t)(m16 * 16) * CDIM + k16 * 16;
        float2 v00 = *(const float2*)(xp + (size_t)r * CDIM + c);
        float2 v10 = *(const float2*)(xp + (size_t)(r + 8) * CDIM + c);
        float2 v01 = *(const float2*)(xp + (size_t)r * CDIM + c + 8);
        float2 v11 = *(const float2*)(xp + (size_t)(r + 8) * CDIM + c + 8);
        uint4 o;
        o.x = h2u(v00.x, v00.y);
        o.y = h2u(v10.x, v10.y);
        o.z = h2u(v01.x, v01.y);
        o.w = h2u(v11.x, v11.y);
        *(uint4*)(g_xa + t * 4) = o;
        return;
    }
    int t = (blockIdx.x - CVT_BLKS) * 256 + threadIdx.x;
    if (t < NW * 2048) {
        int w = t >> 11, ij2 = t & 2047, i = ij2 >> 5, w32 = ij2 & 31;
        int j0 = 8 * (w32 & 7) + 2 * (w32 >> 3);
        float a = 0.f, b2 = 0.f;
        if (i < SEQ && j0 < SEQ)     a  = mask[(size_t)w * SEQ * SEQ + i * SEQ + j0] * LOG2E;
        if (i < SEQ && j0 + 1 < SEQ) b2 = mask[(size_t)w * SEQ * SEQ + i * SEQ + j0 + 1] * LOG2E;
        g_maskp_h[t] = h2u(a, b2);
    }
    if (t < HEADS * 2048) {
        int h = t >> 11, ij2 = t & 2047, i = ij2 >> 5, w32 = ij2 & 31;
        int j0 = 8 * (w32 & 7) + 2 * (w32 >> 3);
        float a = -30000.f, b2 = -30000.f;
        if (i < SEQ && j0 < SEQ)     a  = rpb[rel[i * SEQ + j0] * HEADS + h] * LOG2E;
        if (i < SEQ && j0 + 1 < SEQ) b2 = rpb[rel[i * SEQ + j0 + 1] * HEADS + h] * LOG2E;
        g_biasp_h[t] = h2u(a, b2);
    }
    if (t < (QKV_N / 8) * K16S * 32) {
        int lane = t & 31;
        int u = t >> 5;
        int k16 = u % K16S;
        int n8 = u / K16S;
        int kk = k16 * 16 + ((lane & 3) << 1);
        int nn = n8 * 8 + (lane >> 2);
        {
            uint2 o;
            o.x = h2u(qkv_w[(size_t)kk * QKV_N + nn],       qkv_w[(size_t)(kk + 1) * QKV_N + nn]);
            o.y = h2u(qkv_w[(size_t)(kk + 8) * QKV_N + nn], qkv_w[(size_t)(kk + 9) * QKV_N + nn]);
            *(uint2*)(g_wqkv_t + (size_t)t * 2) = o;
        }
        if (n8 < CDIM / 8) {
            uint2 o;
            o.x = h2u(proj_w[(size_t)kk * CDIM + nn],       proj_w[(size_t)(kk + 1) * CDIM + nn]);
            o.y = h2u(proj_w[(size_t)(kk + 8) * CDIM + nn], proj_w[(size_t)(kk + 9) * CDIM + nn]);
            *(uint2*)(g_wproj_t + (size_t)((n8 * K16S + k16) * 32 + lane) * 2) = o;
        }
    }
}

// ---------------------------------------------------------------------------
// GEMM fp16: BM=128, BN=128, BK=32, 256 threads (8 warps, 2m x 4n, warp 64x32),
// 3-stage cp.async. Lower reg pressure -> 2 CTAs/SM (16 warps).
// MODE 0 q-cols scaled by SCALE_F * LOG2E.
// ---------------------------------------------------------------------------
#define GSTAGE 16384
#define GSM_A(s) ((s) * GSTAGE)
#define GSM_B(s) ((s) * GSTAGE + 8192)
#define GEMM_DSMEM (3 * GSTAGE)

template <int MODE>
__global__ void __launch_bounds__(256, 2)
gemm_f16(const float* __restrict__ bias, float* __restrict__ C_out) {
    const uint32_t* A = (MODE == 0) ? g_xa : g_att_t;
    const uint32_t* W = (MODE == 0) ? g_wqkv_t : g_wproj_t;
    const int    Ntot = (MODE == 0) ? QKV_N : CDIM;

    extern __shared__ __align__(16) uint8_t sm[];

    const int tid  = threadIdx.x;
    const int warp = tid >> 5;
    const int lane = tid & 31;
    const int wm   = warp >> 2;          // 0..1 (64-row halves)
    const int wn   = warp & 3;           // 0..3 (32-col quarters)
    const int m16base = blockIdx.y * 8;
    const int n8base  = blockIdx.x * 16;
    const int n0 = n8base * 8;

    auto load_chunk = [&](int s, int ch) {
#pragma unroll
        for (int it = 0; it < 2; ++it) {
            int idx = tid + it * 256;            // 0..511
            int u = idx >> 5, i = idx & 31;      // A unit 128 u32
            cp_async16(sm + GSM_A(s) + idx * 16,
                       A + (((size_t)(m16base + (u >> 1)) * K16S + ch * 2 + (u & 1)) * 32 + i) * 4);
        }
#pragma unroll
        for (int it = 0; it < 2; ++it) {
            int idx = tid + it * 256;
            int u = idx >> 4, i16 = idx & 15;    // B unit 64 u32
            cp_async16(sm + GSM_B(s) + idx * 16,
                       W + ((size_t)(n8base + (u >> 1)) * K16S + ch * 2 + (u & 1)) * 64 + i16 * 4);
        }
        cp_async_commit();
    };

    float acc[4][4][4];
#pragma unroll
    for (int i = 0; i < 4; ++i)
#pragma unroll
        for (int j = 0; j < 4; ++j)
#pragma unroll
            for (int q = 0; q < 4; ++q) acc[i][j][q] = 0.f;

    load_chunk(0, 0);
    load_chunk(1, 1);

    const int NCH = K16S / 2;    // 12
    for (int ch = 0; ch < NCH; ++ch) {
        if (ch + 2 < NCH) load_chunk((ch + 2) % 3, ch + 2);
        else              cp_async_commit();
        cp_async_wait<2>();
        __syncthreads();

        const uint32_t* smA = (const uint32_t*)(sm + GSM_A(ch % 3));
        const uint32_t* smB = (const uint32_t*)(sm + GSM_B(ch % 3));
#pragma unroll
        for (int kl = 0; kl < 2; ++kl) {
            uint4 a[4];
#pragma unroll
            for (int mt = 0; mt < 4; ++mt)
                a[mt] = *(const uint4*)&smA[(((wm * 4 + mt) * 2 + kl) * 32 + lane) * 4];
            uint2 b[4];
#pragma unroll
            for (int nt = 0; nt < 4; ++nt)
                b[nt] = *(const uint2*)&smB[(((wn * 4 + nt) * 2 + kl) * 32 + lane) * 2];
#pragma unroll
            for (int mt = 0; mt < 4; ++mt)
#pragma unroll
                for (int nt = 0; nt < 4; ++nt)
                    mma_f16(acc[mt][nt], (const uint32_t*)&a[mt], (const uint32_t*)&b[nt]);
        }
        __syncthreads();
    }

    const float qs = (MODE == 0 && n0 < CDIM) ? SCALE_F * LOG2E : 1.f;
    const int rbase = m16base * 16 + wm * 64 + (lane >> 2);
    const int cbase = n0 + wn * 32 + ((lane & 3) << 1);
#pragma unroll
    for (int mt = 0; mt < 4; ++mt) {
        int r = rbase + mt * 16;
#pragma unroll
        for (int nt = 0; nt < 4; ++nt) {
            int cc = cbase + nt * 8;
            float b0 = bias[cc], b1 = bias[cc + 1];
            const float* a4 = acc[mt][nt];
            if (MODE == 0) {
                g_qkv[(size_t)r * QKV_U + (cc >> 1)]       = h2u((a4[0] + b0) * qs, (a4[1] + b1) * qs);
                g_qkv[(size_t)(r + 8) * QKV_U + (cc >> 1)] = h2u((a4[2] + b0) * qs, (a4[3] + b1) * qs);
            } else {
                *(float2*)(C_out + (size_t)r * Ntot + cc)       = make_float2(a4[0] + b0, a4[1] + b1);
                *(float2*)(C_out + (size_t)(r + 8) * Ntot + cc) = make_float2(a4[2] + b0, a4[3] + b1);
            }
        }
    }
}

// ---------------------------------------------------------------------------
// Window attention (unchanged from R13): one block per window, 12 heads,
// double-buffered cp.async, base-2 softmax, normalize-after-PV.
// ---------------------------------------------------------------------------
#define ATT_STAGE 3840   // q 1280 | k 1280 | v 1280 (u32), row stride 20 u32

__global__ void __launch_bounds__(128, 6)
attn_kernel() {
    const int b = blockIdx.x;

    __shared__ uint32_t sS[2][ATT_STAGE];

    const int tid  = threadIdx.x;
    const int warp = tid >> 5;
    const int lane = tid & 31;

    const uint32_t* gq = g_qkv + (size_t)b * SEQ * QKV_U;

    auto load_head = [&](int h, int buf) {
#pragma unroll
        for (int i = 0; i < 6; ++i) {
            int idx = tid + i * 128;                 // 0..767
            int which = idx >> 8;                    // 0=q 1=k 2=v
            int n = (idx >> 2) & 63;
            int part = idx & 3;
            int nc = (n < SEQ) ? n : 0;
            const uint32_t* src = gq + (size_t)nc * QKV_U + h * 16 + which * 192 + part * 4;
            cp_async16z(&sS[buf][which * 1280 + n * 20 + part * 4], src, (n < SEQ) ? 16u : 0u);
        }
        cp_async_commit();
    };

    load_head(0, 0);
    load_head(1, 1);

    const int r0 = warp * 16 + (lane >> 2);
    const int cq = lane & 3;
    const int c0 = cq << 1;
    const int li = lane & 7;
    const int l3 = (lane >> 3) & 1;
    const int l4 = lane >> 4;

    const uint32_t* mp = g_maskp_h + (size_t)(b & (NW - 1)) * 2048;

    for (int h = 0; h < HEADS; ++h) {
        const int cur = h & 1;
        cp_async_wait<1>();
        __syncthreads();

        const uint32_t qbase = sm2u(&sS[cur][0]);
        const uint32_t kbase = qbase + 1280 * 4;
        const uint32_t vbase = qbase + 2560 * 4;

        // ---- QK^T via ldmatrix ----
        float acc[8][4];
#pragma unroll
        for (int i = 0; i < 8; ++i)
#pragma unroll
            for (int j = 0; j < 4; ++j) acc[i][j] = 0.f;
#pragma unroll
        for (int s = 0; s < 2; ++s) {
            uint32_t a[4];
            ldsm_x4(a, qbase + (uint32_t)((warp * 16 + l3 * 8 + li) * 80 + (s * 16 + l4 * 8) * 2));
            uint32_t bf[4][4];
#pragma unroll
            for (int g = 0; g < 4; ++g)
                ldsm_x4(bf[g], kbase + (uint32_t)((g * 16 + l4 * 8 + li) * 80 + (s * 16 + l3 * 8) * 2));
#pragma unroll
            for (int g = 0; g < 4; ++g) {
                mma_f16(acc[2 * g],     a, &bf[g][0]);
                mma_f16(acc[2 * g + 1], a, &bf[g][2]);
            }
        }

        // ---- bias + mask (both LDG.128 from permuted fp16 tables) ----
        {
            const uint32_t* bp = g_biasp_h + h * 2048;
            uint4 b_lo0 = *(const uint4*)(bp + r0 * 32 + cq * 8);
            uint4 b_hi0 = *(const uint4*)(bp + r0 * 32 + cq * 8 + 4);
            uint4 b_lo1 = *(const uint4*)(bp + (r0 + 8) * 32 + cq * 8);
            uint4 b_hi1 = *(const uint4*)(bp + (r0 + 8) * 32 + cq * 8 + 4);
            uint4 m_lo0 = *(const uint4*)(mp + r0 * 32 + cq * 8);
            uint4 m_hi0 = *(const uint4*)(mp + r0 * 32 + cq * 8 + 4);
            uint4 m_lo1 = *(const uint4*)(mp + (r0 + 8) * 32 + cq * 8);
            uint4 m_hi1 = *(const uint4*)(mp + (r0 + 8) * 32 + cq * 8 + 4);
            const uint32_t* bw0 = (const uint32_t*)&b_lo0;
            const uint32_t* bw0h = (const uint32_t*)&b_hi0;
            const uint32_t* bw1 = (const uint32_t*)&b_lo1;
            const uint32_t* bw1h = (const uint32_t*)&b_hi1;
            const uint32_t* mw0 = (const uint32_t*)&m_lo0;
            const uint32_t* mw0h = (const uint32_t*)&m_hi0;
            const uint32_t* mw1 = (const uint32_t*)&m_lo1;
            const uint32_t* mw1h = (const uint32_t*)&m_hi1;
#pragma unroll
            for (int nt = 0; nt < 8; ++nt) {
                uint32_t bu0 = (nt < 4) ? bw0[nt] : bw0h[nt - 4];
                uint32_t bu1 = (nt < 4) ? bw1[nt] : bw1h[nt - 4];
                uint32_t mu0 = (nt < 4) ? mw0[nt] : mw0h[nt - 4];
                uint32_t mu1 = (nt < 4) ? mw1[nt] : mw1h[nt - 4];
                float2 fb0 = __half22float2(*(__half2*)&bu0);
                float2 fb1 = __half22float2(*(__half2*)&bu1);
                float2 fm0 = __half22float2(*(__half2*)&mu0);
                float2 fm1 = __half22float2(*(__half2*)&mu1);
                acc[nt][0] += fb0.x + fm0.x;
                acc[nt][1] += fb0.y + fm0.y;
                acc[nt][2] += fb1.x + fm1.x;
                acc[nt][3] += fb1.y + fm1.y;
            }
        }

        // ---- base-2 softmax, no max-subtraction; nt=7 is always padding ----
        float inv0, inv1;
        {
            float s0 = 0.f, s1 = 0.f;
#pragma unroll
            for (int nt = 0; nt < 7; ++nt) {
                acc[nt][0] = ex2(acc[nt][0]); s0 += acc[nt][0];
                acc[nt][1] = ex2(acc[nt][1]); s0 += acc[nt][1];
                acc[nt][2] = ex2(acc[nt][2]); s1 += acc[nt][2];
                acc[nt][3] = ex2(acc[nt][3]); s1 += acc[nt][3];
            }
            acc[7][0] = acc[7][1] = acc[7][2] = acc[7][3] = 0.f;
            s0 += __shfl_xor_sync(0xffffffffu, s0, 1);
            s0 += __shfl_xor_sync(0xffffffffu, s0, 2);
            s1 += __shfl_xor_sync(0xffffffffu, s1, 1);
            s1 += __shfl_xor_sync(0xffffffffu, s1, 2);
            inv0 = 1.f / s0;
            inv1 = 1.f / s1;
        }

        // ---- O = P V (P unnormalized, from registers); normalize after ----
        {
            float oacc[4][4];
#pragma unroll
            for (int i = 0; i < 4; ++i)
#pragma unroll
                for (int j = 0; j < 4; ++j) oacc[i][j] = 0.f;
#pragma unroll
            for (int s = 0; s < 4; ++s) {
                uint32_t a[4];
                a[0] = h2u(acc[2 * s][0],     acc[2 * s][1]);
                a[1] = h2u(acc[2 * s][2],     acc[2 * s][3]);
                a[2] = h2u(acc[2 * s + 1][0], acc[2 * s + 1][1]);
                a[3] = h2u(acc[2 * s + 1][2], acc[2 * s + 1][3]);
                uint32_t bf[2][4];
#pragma unroll
                for (int g = 0; g < 2; ++g)
                    ldsm_x4_t(bf[g], vbase + (uint32_t)((s * 16 + l3 * 8 + li) * 80 + (g * 16 + l4 * 8) * 2));
                mma_f16(oacc[0], a, &bf[0][0]);
                mma_f16(oacc[1], a, &bf[0][2]);
                mma_f16(oacc[2], a, &bf[1][0]);
                mma_f16(oacc[3], a, &bf[1][2]);
            }
#pragma unroll
            for (int nt = 0; nt < 4; ++nt) {
                int c = h * HDIM + nt * 8 + c0;
                if (r0 < SEQ)
                    g_att_t[a16_off(b * SEQ + r0, c)]     = h2u(oacc[nt][0] * inv0, oacc[nt][1] * inv0);
                if (r0 + 8 < SEQ)
                    g_att_t[a16_off(b * SEQ + r0 + 8, c)] = h2u(oacc[nt][2] * inv1, oacc[nt][3] * inv1);
            }
        }

        __syncthreads();   // all reads of cur buffer done before refill
        if (h + 2 < HEADS) load_head(h + 2, cur);
        else               cp_async_commit();
    }
}

// ---------------------------------------------------------------------------
// Launch
// ---------------------------------------------------------------------------
extern "C" void kernel_launch(void* const* d_in, const int* in_sizes, int n_in,
                              void* d_out, int out_size) {
    const float* x      = (const float*)d_in[0];
    const float* mask   = (const float*)d_in[1];
    const float* qkv_w  = (const float*)d_in[2];
    const float* qkv_b  = (const float*)d_in[3];
    const float* proj_w = (const float*)d_in[4];
    const float* proj_b = (const float*)d_in[5];
    const float* rpb    = (const float*)d_in[6];
    const int*   rel    = (const int*)d_in[7];
    float*       out    = (float*)d_out;

    cudaFuncSetAttribute(gemm_f16<0>, cudaFuncAttributeMaxDynamicSharedMemorySize, GEMM_DSMEM);
    cudaFuncSetAttribute(gemm_f16<1>, cudaFuncAttributeMaxDynamicSharedMemorySize, GEMM_DSMEM);

    // 0) merged prep (log2e-scaled fp16 tables + tiled weights) + x cvt
    prep_cvt_kernel<<<CVT_BLKS + PREP_BLKS, 256>>>(x, mask, rpb, rel, qkv_w, proj_w);
    // 1) QKV GEMM (q-cols scaled by SCALE_F*LOG2E)
    gemm_f16<0><<<dim3(QKV_N / 128, MROWS / 128), 256, GEMM_DSMEM>>>(qkv_b, nullptr);
    // 2) Attention (one block per window, 12 heads, double-buffered)
    attn_kernel<<<B_WIN, 128>>>();
    // 3) Proj GEMM
    gemm_f16<1><<<dim3(CDIM / 128, MROWS / 128), 256, GEMM_DSMEM>>>(proj_b, out);
}